// round 10
// baseline (speedup 1.0000x reference)
#include <cuda_runtime.h>
#include <cuda_fp16.h>
#include <math.h>
#include <stdint.h>

// ---------------- problem constants ----------------
#define SEQ        2048
#define DIM        2048
#define DIM_INNER  4096
#define D_STATE    64
#define D_CONV     4
#define HEADDIM    128
#define NHEADS     32
#define CHUNK      256
#define NCHUNK     (SEQ / CHUNK)          // 8
#define CONV_DIM   (DIM_INNER + 2 * D_STATE)      // 4224
#define D_IN_PROJ  (2 * DIM_INNER + 2 * D_STATE + NHEADS)  // 8352

// ---------------- scratch (device globals; no allocation allowed) -------------
__device__ __align__(128) float g_zxbcdt[SEQ * D_IN_PROJ];
__device__ float g_dt   [SEQ * NHEADS];
__device__ float g_dA   [SEQ * NHEADS];
__device__ float g_xs   [SEQ * DIM_INNER];
__device__ __align__(128) float g_xdt  [SEQ * DIM_INNER];
__device__ float g_B    [SEQ * D_STATE];
__device__ float g_C    [SEQ * D_STATE];
__device__ float g_Acs  [NCHUNK * NHEADS * CHUNK];
__device__ float g_Alast[NCHUNK * NHEADS];
__device__ float g_states[NCHUNK * NHEADS * HEADDIM * D_STATE];
__device__ float g_sprev [NCHUNK * NHEADS * HEADDIM * D_STATE];
__device__ __align__(128) float g_y    [SEQ * DIM_INNER];
// fp16 GEMM operands
__device__ __align__(128) __half g_wA [D_IN_PROJ * DIM];
__device__ __align__(128) __half g_wB [DIM * DIM_INNER];
__device__ __align__(128) __half g_xh [SEQ * DIM];
__device__ __align__(128) __half g_yh [SEQ * DIM_INNER];

__device__ __forceinline__ float siluf(float v) { return v / (1.0f + expf(-v)); }
__device__ __forceinline__ float softplusf(float v) { return (v > 20.0f) ? v : log1pf(expf(v)); }

// ---------------- fp32 -> fp16 conversion pass ----------------
__global__ void tohalf_kernel(const float* __restrict__ in, __half* __restrict__ out, int n) {
    int i = (blockIdx.x * blockDim.x + threadIdx.x) * 8;
    if (i >= n) return;
    float4 a = *(const float4*)(in + i);
    float4 b = *(const float4*)(in + i + 4);
    __half2 h0 = __floats2half2_rn(a.x, a.y);
    __half2 h1 = __floats2half2_rn(a.z, a.w);
    __half2 h2 = __floats2half2_rn(b.x, b.y);
    __half2 h3 = __floats2half2_rn(b.z, b.w);
    uint4 o;
    o.x = *(uint32_t*)&h0; o.y = *(uint32_t*)&h1;
    o.z = *(uint32_t*)&h2; o.w = *(uint32_t*)&h3;
    *(uint4*)(out + i) = o;
}

#define MMA_F16(acc, a, b) \
    asm volatile( \
        "mma.sync.aligned.m16n8k16.row.col.f32.f16.f16.f32 " \
        "{%0,%1,%2,%3}, {%4,%5,%6,%7}, {%8,%9}, {%0,%1,%2,%3};" \
        : "+f"((acc)[0]), "+f"((acc)[1]), "+f"((acc)[2]), "+f"((acc)[3]) \
        : "r"((a)[0]), "r"((a)[1]), "r"((a)[2]), "r"((a)[3]), \
          "r"((b)[0]), "r"((b)[1]))

#define LDSM_X4(r0, r1, r2, r3, addr) \
    asm volatile("ldmatrix.sync.aligned.m8n8.x4.shared.b16 {%0,%1,%2,%3}, [%4];" \
        : "=r"(r0), "=r"(r1), "=r"(r2), "=r"(r3) : "r"(addr))

// ==== fp16 mma.sync GEMM, 128x256 CTA tile, cp.async 4-stage + ldmatrix ====
#define TBM   128
#define TBN   256
#define TBK   32
#define NSTG  4
#define ROWPH 40
#define STGA  (TBM * ROWPH)              // 5120 halves per A stage
#define STGB  (TBN * ROWPH)              // 10240 halves per B stage
#define GEMM_SMEM (NSTG * (STGA + STGB) * 2)   // 122880 bytes

__global__ void __launch_bounds__(256, 1)
h16_gemm(const __half* __restrict__ A, const __half* __restrict__ B,
         float* __restrict__ C, int M, int N, int K) {
    extern __shared__ __half sm[];

    const int tid  = threadIdx.x;
    const int lane = tid & 31;
    const int warp = tid >> 5;
    const int m0   = blockIdx.y * TBM;
    const int n0   = blockIdx.x * TBN;
    const int wm   = (warp >> 2) * 64;      // 0 or 64
    const int wn   = (warp & 3) * 64;       // 0,64,128,192
    const int lr   = lane >> 2;
    const int lc   = lane & 3;
    const int ktiles = K / TBK;

    const int lrow = tid >> 2;              // 0..63
    const int lch  = (tid & 3) * 8;         // half offset 0,8,16,24

    const int rowin  = lane & 7;
    const int a_row  = ((lane >> 3) & 1) * 8 + rowin;
    const int a_koff = ((lane >> 4) & 1) * 8;
    const int b_row  = ((lane >> 4) & 1) * 8 + rowin;
    const int b_koff = ((lane >> 3) & 1) * 8;

    uint32_t a_s0, b_s0;
    {
        uint32_t base;
        asm("{ .reg .u64 t; cvta.to.shared.u64 t, %1; cvt.u32.u64 %0, t; }"
            : "=r"(base) : "l"(sm));
        a_s0 = base;
        b_s0 = base + NSTG * STGA * 2;
    }

    auto issue = [&](int kt, int st) {
        const __half* Ag = A + (long)m0 * K + kt * TBK;
        const __half* Bg = B + (long)n0 * K + kt * TBK;
        uint32_t abase = a_s0 + st * STGA * 2;
        uint32_t bbase = b_s0 + st * STGB * 2;
#pragma unroll
        for (int i = 0; i < 2; i++) {
            int r = lrow + i * 64;
            uint32_t doff = r * ROWPH * 2 + lch * 2;
            asm volatile("cp.async.cg.shared.global [%0], [%1], 16;"
                         :: "r"(abase + doff), "l"(Ag + (long)r * K + lch) : "memory");
        }
#pragma unroll
        for (int i = 0; i < 4; i++) {
            int r = lrow + i * 64;
            uint32_t doff = r * ROWPH * 2 + lch * 2;
            int sz = (n0 + r < N) ? 16 : 0;
            asm volatile("cp.async.cg.shared.global [%0], [%1], 16, %2;"
                         :: "r"(bbase + doff), "l"(Bg + (long)r * K + lch), "r"(sz) : "memory");
        }
        asm volatile("cp.async.commit_group;" ::: "memory");
    };

#pragma unroll
    for (int st = 0; st < NSTG - 1; st++) issue(st, st);

    float acc[4][8][4];
#pragma unroll
    for (int i = 0; i < 4; i++)
#pragma unroll
        for (int j = 0; j < 8; j++)
#pragma unroll
            for (int r = 0; r < 4; r++) acc[i][j][r] = 0.0f;

    for (int kt = 0; kt < ktiles; kt++) {
        int s = kt % NSTG;
        asm volatile("cp.async.wait_group %0;" :: "n"(NSTG - 2));
        __syncthreads();
        int nt = kt + NSTG - 1;
        if (nt < ktiles) issue(nt, nt % NSTG);
        else asm volatile("cp.async.commit_group;" ::: "memory");

        uint32_t abase = a_s0 + s * STGA * 2;
        uint32_t bbase = b_s0 + s * STGB * 2;
#pragma unroll
        for (int kk = 0; kk < 2; kk++) {
            int kb = kk * 16;
            uint32_t afr[4][4], bfr[8][2];
#pragma unroll
            for (int mi = 0; mi < 4; mi++) {
                uint32_t addr = abase + (((wm + mi * 16 + a_row) * ROWPH) + kb + a_koff) * 2;
                LDSM_X4(afr[mi][0], afr[mi][1], afr[mi][2], afr[mi][3], addr);
            }
#pragma unroll
            for (int nj = 0; nj < 4; nj++) {
                uint32_t addr = bbase + (((wn + nj * 16 + b_row) * ROWPH) + kb + b_koff) * 2;
                LDSM_X4(bfr[nj * 2][0], bfr[nj * 2][1],
                        bfr[nj * 2 + 1][0], bfr[nj * 2 + 1][1], addr);
            }
#pragma unroll
            for (int mi = 0; mi < 4; mi++)
#pragma unroll
                for (int ni = 0; ni < 8; ni++)
                    MMA_F16(acc[mi][ni], afr[mi], bfr[ni]);
        }
    }

#pragma unroll
    for (int mi = 0; mi < 4; mi++) {
        int r0 = m0 + wm + mi * 16 + lr;
#pragma unroll
        for (int ni = 0; ni < 8; ni++) {
            int ccol = n0 + wn + ni * 8 + lc * 2;
            if (ccol < N) {
                float* p0 = C + (long)r0 * N + ccol;
                float* p1 = C + (long)(r0 + 8) * N + ccol;
                p0[0] = acc[mi][ni][0];
                p0[1] = acc[mi][ni][1];
                p1[0] = acc[mi][ni][2];
                p1[1] = acc[mi][ni][3];
            }
        }
    }
}

// ---------------- dt / dA ----------------
__global__ void dt_kernel(const float* __restrict__ dt_bias,
                          const float* __restrict__ A_log) {
    int idx = blockIdx.x * blockDim.x + threadIdx.x;
    if (idx >= SEQ * NHEADS) return;
    int l = idx / NHEADS, h = idx % NHEADS;
    float v = g_zxbcdt[l * D_IN_PROJ + (D_IN_PROJ - NHEADS) + h] + dt_bias[h];
    float sp = softplusf(v);
    g_dt[idx] = sp;
    g_dA[idx] = -expf(A_log[h]) * sp;
}

// ---------------- causal depthwise conv + SiLU + split ----------------
__global__ void conv_kernel(const float* __restrict__ conv_w,
                            const float* __restrict__ conv_b) {
    int idx = blockIdx.x * blockDim.x + threadIdx.x;
    if (idx >= SEQ * CONV_DIM) return;
    int l = idx / CONV_DIM, ch = idx % CONV_DIM;
    float acc = conv_b[ch];
#pragma unroll
    for (int k = 0; k < D_CONV; k++) {
        int ls = l - (D_CONV - 1) + k;
        if (ls >= 0)
            acc += g_zxbcdt[ls * D_IN_PROJ + DIM_INNER + ch] * conv_w[ch * D_CONV + k];
    }
    float v = siluf(acc);
    if (ch < DIM_INNER) {
        int h = ch >> 7;
        g_xs [l * DIM_INNER + ch] = v;
        g_xdt[l * DIM_INNER + ch] = v * g_dt[l * NHEADS + h];
    } else if (ch < DIM_INNER + D_STATE) {
        g_B[l * D_STATE + (ch - DIM_INNER)] = v;
    } else {
        g_C[l * D_STATE + (ch - DIM_INNER - D_STATE)] = v;
    }
}

// ---------------- per-(chunk,head) inclusive cumsum of dA ----------------
__global__ void cumsum_kernel() {
    int ch = blockIdx.x;
    int c = ch / NHEADS, h = ch % NHEADS;
    int t = threadIdx.x;
    __shared__ float s[CHUNK];
    s[t] = g_dA[(c * CHUNK + t) * NHEADS + h];
    __syncthreads();
    for (int off = 1; off < CHUNK; off <<= 1) {
        float add = (t >= off) ? s[t - off] : 0.0f;
        __syncthreads();
        s[t] += add;
        __syncthreads();
    }
    g_Acs[ch * CHUNK + t] = s[t];
    if (t == CHUNK - 1) g_Alast[ch] = s[t];
}

// ---------------- chunk states ----------------
__global__ void __launch_bounds__(256)
states_kernel() {
    int ch = blockIdx.x;
    int c = ch / NHEADS, h = ch % NHEADS;
    int t = threadIdx.x;
    int tp = t & 15;
    int tn = t >> 4;

    __shared__ float xw[32][HEADDIM];
    __shared__ float Bs2[32][D_STATE];
    __shared__ float dec[32];

    float acc[8][4];
#pragma unroll
    for (int i = 0; i < 8; i++)
#pragma unroll
        for (int j = 0; j < 4; j++) acc[i][j] = 0.0f;

    float Al = g_Alast[ch];

    for (int lt = 0; lt < CHUNK; lt += 32) {
        if (t < 32) dec[t] = expf(Al - g_Acs[ch * CHUNK + lt + t]);
        __syncthreads();
#pragma unroll
        for (int r = 0; r < 16; r++) {
            int lin = t + r * 256;
            int l = lin >> 7, p = lin & 127;
            xw[l][p] = g_xdt[(c * CHUNK + lt + l) * DIM_INNER + h * HEADDIM + p] * dec[l];
        }
#pragma unroll
        for (int r = 0; r < 8; r++) {
            int lin = t + r * 256;
            int l = lin >> 6, n = lin & 63;
            Bs2[l][n] = g_B[(c * CHUNK + lt + l) * D_STATE + n];
        }
        __syncthreads();
#pragma unroll 4
        for (int l = 0; l < 32; l++) {
            float a[8], b[4];
#pragma unroll
            for (int i = 0; i < 8; i++) a[i] = xw[l][tp * 8 + i];
#pragma unroll
            for (int j = 0; j < 4; j++) b[j] = Bs2[l][tn * 4 + j];
#pragma unroll
            for (int i = 0; i < 8; i++)
#pragma unroll
                for (int j = 0; j < 4; j++)
                    acc[i][j] = fmaf(a[i], b[j], acc[i][j]);
        }
        __syncthreads();
    }
#pragma unroll
    for (int i = 0; i < 8; i++)
#pragma unroll
        for (int j = 0; j < 4; j++)
            g_states[ch * (HEADDIM * D_STATE) + (tp * 8 + i) * D_STATE + tn * 4 + j] = acc[i][j];
}

// ---------------- inter-chunk recurrence ----------------
__global__ void sprev_kernel() {
    int idx = blockIdx.x * blockDim.x + threadIdx.x;
    if (idx >= NHEADS * HEADDIM * D_STATE) return;
    int h = idx / (HEADDIM * D_STATE);
    int r = idx % (HEADDIM * D_STATE);
    float S = 0.0f;
    for (int c = 0; c < NCHUNK; c++) {
        int ch = c * NHEADS + h;
        g_sprev[ch * (HEADDIM * D_STATE) + r] = S;
        S = expf(g_Alast[ch]) * S + g_states[ch * (HEADDIM * D_STATE) + r];
    }
}

// ================ fused SSD Y kernel (fp16 mma) ================
#define YROW 72
#define O_CH   0
#define O_BS   (O_CH + 128 * YROW)
#define O_GS   (O_BS + 64 * YROW)
#define O_XH   (O_GS + 128 * YROW)
#define O_XL   (O_XH + 128 * YROW)
#define O_SS   (O_XL + 128 * YROW)
#define O_END  (O_SS + 128 * YROW)
#define Y_SMEM_BYTES (O_END * 2 + (128 + 128 + 64) * 4)

__global__ void __launch_bounds__(256, 1)
y_mma_kernel(const float* __restrict__ Dparam) {
    extern __shared__ __half ysm[];
    __half* Ch  = ysm + O_CH;
    __half* Bsm = ysm + O_BS;
    __half* Gsm = ysm + O_GS;
    __half* Xh  = ysm + O_XH;
    __half* Xl  = ysm + O_XL;
    __half* Ssm = ysm + O_SS;
    float* acsl  = (float*)(ysm + O_END);
    float* expAl = acsl + 128;
    float* acss  = expAl + 128;

    const int hh = blockIdx.y, c = blockIdx.z;
    const int lh = blockIdx.x;
    const int l0 = lh * 128;
    const int ch = c * NHEADS + hh;
    const int tid  = threadIdx.x;
    const int lane = tid & 31;
    const int warp = tid >> 5;
    const int lr   = lane >> 2;
    const int lc   = lane & 3;
    const int wmY = (warp >> 1) * 32;
    const int wnY = (warp & 1) * 64;
    const int wmG = (warp >> 1) * 32;
    const int wnG = (warp & 1) * 32;

    {
        int n = tid & 63, r4 = tid >> 6;
#pragma unroll
        for (int i = 0; i < 32; i++) {
            int l = r4 + i * 4;
            Ch[l * YROW + n]  = __float2half_rn(g_C[(c * CHUNK + l0 + l) * D_STATE + n]);
            Ssm[l * YROW + n] = __float2half_rn(g_sprev[ch * (HEADDIM * D_STATE) + l * D_STATE + n]);
        }
        if (tid < 128) {
            float a = g_Acs[ch * CHUNK + l0 + tid];
            acsl[tid] = a;
            expAl[tid] = expf(a);
        }
    }
    __syncthreads();

    float acc[2][8][4];
#pragma unroll
    for (int i = 0; i < 2; i++)
#pragma unroll
        for (int j = 0; j < 8; j++)
#pragma unroll
            for (int r = 0; r < 4; r++) acc[i][j][r] = 0.0f;

    // ---- Y_off: C @ Sprev^T (K = 64) ----
#pragma unroll
    for (int kk = 0; kk < 4; kk++) {
        int kb = kk * 16;
        uint32_t afr[2][4], bfr[8][2];
#pragma unroll
        for (int mi = 0; mi < 2; mi++) {
            int mb = wmY + mi * 16 + lr;
            afr[mi][0] = *(const uint32_t*)&Ch[(mb    ) * YROW + kb + lc * 2];
            afr[mi][1] = *(const uint32_t*)&Ch[(mb + 8) * YROW + kb + lc * 2];
            afr[mi][2] = *(const uint32_t*)&Ch[(mb    ) * YROW + kb + 8 + lc * 2];
            afr[mi][3] = *(const uint32_t*)&Ch[(mb + 8) * YROW + kb + 8 + lc * 2];
        }
#pragma unroll
        for (int ni = 0; ni < 8; ni++) {
            int nb = wnY + ni * 8 + lr;
            bfr[ni][0] = *(const uint32_t*)&Ssm[nb * YROW + kb + lc * 2];
            bfr[ni][1] = *(const uint32_t*)&Ssm[nb * YROW + kb + 8 + lc * 2];
        }
#pragma unroll
        for (int mi = 0; mi < 2; mi++)
#pragma unroll
            for (int ni = 0; ni < 8; ni++)
                MMA_F16(acc[mi][ni], afr[mi], bfr[ni]);
    }
#pragma unroll
    for (int mi = 0; mi < 2; mi++) {
        int r0 = wmY + mi * 16 + lr;
        float e0 = expAl[r0], e1 = expAl[r0 + 8];
#pragma unroll
        for (int ni = 0; ni < 8; ni++) {
            acc[mi][ni][0] *= e0; acc[mi][ni][1] *= e0;
            acc[mi][ni][2] *= e1; acc[mi][ni][3] *= e1;
        }
    }

    // ---- Y_diag: s-tiles of 64 ----
    const int nst = 2 * (lh + 1);
    for (int st = 0; st < nst; st++) {
        {
            int n = tid & 63, s4 = tid >> 6;
#pragma unroll
            for (int i = 0; i < 16; i++) {
                int s = s4 + i * 4;
                Bsm[s * YROW + n] = __float2half_rn(g_B[(c * CHUNK + st * 64 + s) * D_STATE + n]);
            }
            if (tid < 64) acss[tid] = g_Acs[ch * CHUNK + st * 64 + tid];
            int p = tid & 127, s2 = tid >> 7;
#pragma unroll
            for (int i = 0; i < 32; i++) {
                int s = s2 + i * 2;
                float v = g_xdt[(c * CHUNK + st * 64 + s) * DIM_INNER + hh * HEADDIM + p];
                __half hi = __float2half_rn(v);
                Xh[p * YROW + s] = hi;
                Xl[p * YROW + s] = __float2half_rn(v - __half2float(hi));
            }
        }
        __syncthreads();

        float gacc[2][4][4];
#pragma unroll
        for (int i = 0; i < 2; i++)
#pragma unroll
            for (int j = 0; j < 4; j++)
#pragma unroll
                for (int r = 0; r < 4; r++) gacc[i][j][r] = 0.0f;
#pragma unroll
        for (int kk = 0; kk < 4; kk++) {
            int kb = kk * 16;
            uint32_t afr[2][4], bfr[4][2];
#pragma unroll
            for (int mi = 0; mi < 2; mi++) {
                int mb = wmG + mi * 16 + lr;
                afr[mi][0] = *(const uint32_t*)&Ch[(mb    ) * YROW + kb + lc * 2];
                afr[mi][1] = *(const uint32_t*)&Ch[(mb + 8) * YROW + kb + lc * 2];
                afr[mi][2] = *(const uint32_t*)&Ch[(mb    ) * YROW + kb + 8 + lc * 2];
                afr[mi][3] = *(const uint32_t*)&Ch[(mb + 8) * YROW + kb + 8 + lc * 2];
            }
#pragma unroll
            for (int ni = 0; ni < 4; ni++) {
                int nb = wnG + ni * 8 + lr;
                bfr[ni][0] = *(const uint32_t*)&Bsm[nb * YROW + kb + lc * 2];
                bfr[ni][1] = *(const uint32_t*)&Bsm[nb * YROW + kb + 8 + lc * 2];
            }
#pragma unroll
            for (int mi = 0; mi < 2; mi++)
#pragma unroll
                for (int ni = 0; ni < 4; ni++)
                    MMA_F16(gacc[mi][ni], afr[mi], bfr[ni]);
        }

        const int sbase = st * 64;
#pragma unroll
        for (int mi = 0; mi < 2; mi++) {
            int r0 = wmG + mi * 16 + lr;
            float a0 = acsl[r0], a1 = acsl[r0 + 8];
            int lg0 = l0 + r0, lg1 = lg0 + 8;
#pragma unroll
            for (int ni = 0; ni < 4; ni++) {
                int cl = wnG + ni * 8 + lc * 2;
                float as0 = acss[cl], as1 = acss[cl + 1];
                int sg0 = sbase + cl, sg1 = sg0 + 1;
                float g00 = (sg0 <= lg0) ? gacc[mi][ni][0] * expf(a0 - as0) : 0.0f;
                float g01 = (sg1 <= lg0) ? gacc[mi][ni][1] * expf(a0 - as1) : 0.0f;
                float g10 = (sg0 <= lg1) ? gacc[mi][ni][2] * expf(a1 - as0) : 0.0f;
                float g11 = (sg1 <= lg1) ? gacc[mi][ni][3] * expf(a1 - as1) : 0.0f;
                Gsm[(r0    ) * YROW + cl    ] = __float2half_rn(g00);
                Gsm[(r0    ) * YROW + cl + 1] = __float2half_rn(g01);
                Gsm[(r0 + 8) * YROW + cl    ] = __float2half_rn(g10);
                Gsm[(r0 + 8) * YROW + cl + 1] = __float2half_rn(g11);
            }
        }
        __syncthreads();

#pragma unroll
        for (int kk = 0; kk < 4; kk++) {
            int kb = kk * 16;
            uint32_t afr[2][4], bh[8][2], bl[8][2];
#pragma unroll
            for (int mi = 0; mi < 2; mi++) {
                int mb = wmY + mi * 16 + lr;
                afr[mi][0] = *(const uint32_t*)&Gsm[(mb    ) * YROW + kb + lc * 2];
                afr[mi][1] = *(const uint32_t*)&Gsm[(mb + 8) * YROW + kb + lc * 2];
                afr[mi][2] = *(const uint32_t*)&Gsm[(mb    ) * YROW + kb + 8 + lc * 2];
                afr[mi][3] = *(const uint32_t*)&Gsm[(mb + 8) * YROW + kb + 8 + lc * 2];
            }
#pragma unroll
            for (int ni = 0; ni < 8; ni++) {
                int nb = wnY + ni * 8 + lr;
                bh[ni][0] = *(const uint32_t*)&Xh[nb * YROW + kb + lc * 2];
                bh[ni][1] = *(const uint32_t*)&Xh[nb * YROW + kb + 8 + lc * 2];
                bl[ni][0] = *(const uint32_t*)&Xl[nb * YROW + kb + lc * 2];
                bl[ni][1] = *(const uint32_t*)&Xl[nb * YROW + kb + 8 + lc * 2];
            }
#pragma unroll
            for (int mi = 0; mi < 2; mi++)
#pragma unroll
                for (int ni = 0; ni < 8; ni++) {
                    MMA_F16(acc[mi][ni], afr[mi], bh[ni]);
                    MMA_F16(acc[mi][ni], afr[mi], bl[ni]);
                }
        }
        __syncthreads();
    }

    float Dh = Dparam[hh];
#pragma unroll
    for (int mi = 0; mi < 2; mi++) {
        int r0 = wmY + mi * 16 + lr;
#pragma unroll
        for (int ni = 0; ni < 8; ni++) {
            int col = wnY + ni * 8 + lc * 2;
            long o0 = (long)(c * CHUNK + l0 + r0) * DIM_INNER + hh * HEADDIM + col;
            long o1 = o0 + 8L * DIM_INNER;
            g_y[o0]     = acc[mi][ni][0] + g_xs[o0] * Dh;
            g_y[o0 + 1] = acc[mi][ni][1] + g_xs[o0 + 1] * Dh;
            g_y[o1]     = acc[mi][ni][2] + g_xs[o1] * Dh;
            g_y[o1 + 1] = acc[mi][ni][3] + g_xs[o1 + 1] * Dh;
        }
    }
}

// ---------------- gated RMSNorm (writes fp16 for out_proj) ----------------
__global__ void __launch_bounds__(256)
norm_kernel(const float* __restrict__ norm_w) {
    int l = blockIdx.x;
    int t = threadIdx.x;
    float vals[16];
    float ss = 0.0f;
#pragma unroll
    for (int r = 0; r < 16; r++) {
        int j = t + r * 256;
        float yv = g_y[l * DIM_INNER + j];
        float zv = g_zxbcdt[l * D_IN_PROJ + j];
        float gv = yv * siluf(zv);
        vals[r] = gv;
        ss += gv * gv;
    }
    __shared__ float red[8];
#pragma unroll
    for (int off = 16; off > 0; off >>= 1)
        ss += __shfl_down_sync(0xffffffffu, ss, off);
    if ((t & 31) == 0) red[t >> 5] = ss;
    __syncthreads();
    float total;
    {
        float v = (t < 8) ? red[t] : 0.0f;
#pragma unroll
        for (int off = 4; off > 0; off >>= 1)
            v += __shfl_down_sync(0xffffffffu, v, off);
        if (t == 0) red[0] = v;
    }
    __syncthreads();
    total = red[0];
    float scale = rsqrtf(total / (float)DIM_INNER + 1e-5f);
#pragma unroll
    for (int r = 0; r < 16; r++) {
        int j = t + r * 256;
        g_yh[l * DIM_INNER + j] = __float2half_rn(vals[r] * scale * norm_w[j]);
    }
}

// ---------------- host launcher ----------------
extern "C" void kernel_launch(void* const* d_in, const int* in_sizes, int n_in,
                              void* d_out, int out_size) {
    const float* x        = (const float*)d_in[0];
    const float* in_w     = (const float*)d_in[1];
    const float* conv_w   = (const float*)d_in[2];
    const float* conv_b   = (const float*)d_in[3];
    const float* dt_bias  = (const float*)d_in[4];
    const float* A_log    = (const float*)d_in[5];
    const float* Dparam   = (const float*)d_in[6];
    const float* norm_w   = (const float*)d_in[7];
    const float* out_w    = (const float*)d_in[8];
    float* out            = (float*)d_out;

    float*  zx;  cudaGetSymbolAddress((void**)&zx,  g_zxbcdt);
    __half* wA;  cudaGetSymbolAddress((void**)&wA,  g_wA);
    __half* wB;  cudaGetSymbolAddress((void**)&wB,  g_wB);
    __half* xh;  cudaGetSymbolAddress((void**)&xh,  g_xh);
    __half* yh;  cudaGetSymbolAddress((void**)&yh,  g_yh);

    cudaFuncSetAttribute(h16_gemm, cudaFuncAttributeMaxDynamicSharedMemorySize, GEMM_SMEM);
    cudaFuncSetAttribute(y_mma_kernel, cudaFuncAttributeMaxDynamicSharedMemorySize, Y_SMEM_BYTES);

    // 0. convert GEMM operands to fp16
    tohalf_kernel<<<(D_IN_PROJ * DIM / 8 + 255) / 256, 256>>>(in_w, wA, D_IN_PROJ * DIM);
    tohalf_kernel<<<(SEQ * DIM / 8 + 255) / 256, 256>>>(x, xh, SEQ * DIM);
    tohalf_kernel<<<(DIM * DIM_INNER / 8 + 255) / 256, 256>>>(out_w, wB, DIM * DIM_INNER);

    // 1. in_proj (fp16 mma, 128x256 tile)
    {
        dim3 grid((D_IN_PROJ + TBN - 1) / TBN, SEQ / TBM);
        h16_gemm<<<grid, 256, GEMM_SMEM>>>(xh, wA, zx, SEQ, D_IN_PROJ, DIM);
    }
    // 2. dt / dA
    dt_kernel<<<(SEQ * NHEADS + 255) / 256, 256>>>(dt_bias, A_log);
    // 3. conv + silu + split
    conv_kernel<<<(SEQ * CONV_DIM + 255) / 256, 256>>>(conv_w, conv_b);
    // 4. cumsum per (chunk, head)
    cumsum_kernel<<<NCHUNK * NHEADS, CHUNK>>>();
    // 5. chunk states
    states_kernel<<<NCHUNK * NHEADS, 256>>>();
    // 6. inter-chunk recurrence
    sprev_kernel<<<(NHEADS * HEADDIM * D_STATE + 255) / 256, 256>>>();
    // 7. Y via fp16 mma
    {
        dim3 grid(2, NHEADS, NCHUNK);
        y_mma_kernel<<<grid, 256, Y_SMEM_BYTES>>>(Dparam);
    }
    // 8. gated RMSNorm
    norm_kernel<<<SEQ, 256>>>(norm_w);
    // 9. out_proj
    {
        dim3 grid(DIM / TBN, SEQ / TBM);
        h16_gemm<<<grid, 256, GEMM_SMEM>>>(yh, wB, out, SEQ, DIM, DIM_INNER);
    }
}

// round 11
// speedup vs baseline: 1.1476x; 1.1476x over previous
#include <cuda_runtime.h>
#include <cuda_fp16.h>
#include <math.h>
#include <stdint.h>

// ---------------- problem constants ----------------
#define SEQ        2048
#define DIM        2048
#define DIM_INNER  4096
#define D_STATE    64
#define D_CONV     4
#define HEADDIM    128
#define NHEADS     32
#define CHUNK      256
#define NCHUNK     (SEQ / CHUNK)          // 8
#define CONV_DIM   (DIM_INNER + 2 * D_STATE)      // 4224
#define D_IN_PROJ  (2 * DIM_INNER + 2 * D_STATE + NHEADS)  // 8352

// ---------------- scratch (device globals; no allocation allowed) -------------
__device__ __align__(128) float g_zxbcdt[SEQ * D_IN_PROJ];
__device__ float g_dt   [SEQ * NHEADS];
__device__ float g_dA   [SEQ * NHEADS];
__device__ float g_xs   [SEQ * DIM_INNER];
__device__ __align__(128) float g_xdt  [SEQ * DIM_INNER];
__device__ float g_B    [SEQ * D_STATE];
__device__ float g_C    [SEQ * D_STATE];
__device__ float g_Acs  [NCHUNK * NHEADS * CHUNK];
__device__ float g_Alast[NCHUNK * NHEADS];
__device__ float g_states[NCHUNK * NHEADS * HEADDIM * D_STATE];
__device__ float g_sprev [NCHUNK * NHEADS * HEADDIM * D_STATE];
__device__ __align__(128) float g_y    [SEQ * DIM_INNER];
// fp16 GEMM operands
__device__ __align__(128) __half g_wA [D_IN_PROJ * DIM];
__device__ __align__(128) __half g_wB [DIM * DIM_INNER];
__device__ __align__(128) __half g_xh [SEQ * DIM];
__device__ __align__(128) __half g_yh [SEQ * DIM_INNER];

__device__ __forceinline__ float siluf(float v) { return v / (1.0f + expf(-v)); }
__device__ __forceinline__ float softplusf(float v) { return (v > 20.0f) ? v : log1pf(expf(v)); }

// ---------------- fp32 -> fp16 conversion pass ----------------
__global__ void tohalf_kernel(const float* __restrict__ in, __half* __restrict__ out, int n) {
    int i = (blockIdx.x * blockDim.x + threadIdx.x) * 8;
    if (i >= n) return;
    float4 a = *(const float4*)(in + i);
    float4 b = *(const float4*)(in + i + 4);
    __half2 h0 = __floats2half2_rn(a.x, a.y);
    __half2 h1 = __floats2half2_rn(a.z, a.w);
    __half2 h2 = __floats2half2_rn(b.x, b.y);
    __half2 h3 = __floats2half2_rn(b.z, b.w);
    uint4 o;
    o.x = *(uint32_t*)&h0; o.y = *(uint32_t*)&h1;
    o.z = *(uint32_t*)&h2; o.w = *(uint32_t*)&h3;
    *(uint4*)(out + i) = o;
}

#define MMA_F16(acc, a, b) \
    asm volatile( \
        "mma.sync.aligned.m16n8k16.row.col.f32.f16.f16.f32 " \
        "{%0,%1,%2,%3}, {%4,%5,%6,%7}, {%8,%9}, {%0,%1,%2,%3};" \
        : "+f"((acc)[0]), "+f"((acc)[1]), "+f"((acc)[2]), "+f"((acc)[3]) \
        : "r"((a)[0]), "r"((a)[1]), "r"((a)[2]), "r"((a)[3]), \
          "r"((b)[0]), "r"((b)[1]))

#define LDSM_X4(r0, r1, r2, r3, addr) \
    asm volatile("ldmatrix.sync.aligned.m8n8.x4.shared.b16 {%0,%1,%2,%3}, [%4];" \
        : "=r"(r0), "=r"(r1), "=r"(r2), "=r"(r3) : "r"(addr))

// ==== fp16 mma.sync GEMM: 128x128 CTA, 128 thr (4 warps, 64x64 warp tile),
// ==== cp.async 4-stage + ldmatrix, 2 CTAs/SM for cross-CTA latency hiding ====
#define TBM   128
#define TBN   128
#define TBK   32
#define NSTG  4
#define ROWPH 40
#define STGH  (TBM * ROWPH)              // 5120 halves per operand per stage
#define GEMM_SMEM (2 * NSTG * STGH * 2)  // 81920 bytes

__global__ void __launch_bounds__(128, 2)
h16_gemm(const __half* __restrict__ A, const __half* __restrict__ B,
         float* __restrict__ C, int M, int N, int K) {
    extern __shared__ __half sm[];

    const int tid  = threadIdx.x;
    const int lane = tid & 31;
    const int warp = tid >> 5;
    const int m0   = blockIdx.y * TBM;
    const int n0   = blockIdx.x * TBN;
    const int wm   = (warp >> 1) * 64;      // 0 or 64
    const int wn   = (warp & 1) * 64;       // 0 or 64
    const int lr   = lane >> 2;
    const int lc   = lane & 3;
    const int ktiles = K / TBK;

    const int lrow = tid >> 2;              // 0..31
    const int lch  = (tid & 3) * 8;         // half offset 0,8,16,24

    const int rowin  = lane & 7;
    const int a_row  = ((lane >> 3) & 1) * 8 + rowin;
    const int a_koff = ((lane >> 4) & 1) * 8;
    const int b_row  = ((lane >> 4) & 1) * 8 + rowin;
    const int b_koff = ((lane >> 3) & 1) * 8;

    uint32_t a_s0, b_s0;
    {
        uint32_t base;
        asm("{ .reg .u64 t; cvta.to.shared.u64 t, %1; cvt.u32.u64 %0, t; }"
            : "=r"(base) : "l"(sm));
        a_s0 = base;
        b_s0 = base + NSTG * STGH * 2;
    }

    auto issue = [&](int kt, int st) {
        const __half* Ag = A + (long)m0 * K + kt * TBK;
        const __half* Bg = B + (long)n0 * K + kt * TBK;
        uint32_t abase = a_s0 + st * STGH * 2;
        uint32_t bbase = b_s0 + st * STGH * 2;
#pragma unroll
        for (int i = 0; i < 4; i++) {
            int r = lrow + i * 32;
            uint32_t doff = r * ROWPH * 2 + lch * 2;
            asm volatile("cp.async.cg.shared.global [%0], [%1], 16;"
                         :: "r"(abase + doff), "l"(Ag + (long)r * K + lch) : "memory");
            int sz = (n0 + r < N) ? 16 : 0;
            asm volatile("cp.async.cg.shared.global [%0], [%1], 16, %2;"
                         :: "r"(bbase + doff), "l"(Bg + (long)r * K + lch), "r"(sz) : "memory");
        }
        asm volatile("cp.async.commit_group;" ::: "memory");
    };

#pragma unroll
    for (int st = 0; st < NSTG - 1; st++) issue(st, st);

    float acc[4][8][4];
#pragma unroll
    for (int i = 0; i < 4; i++)
#pragma unroll
        for (int j = 0; j < 8; j++)
#pragma unroll
            for (int r = 0; r < 4; r++) acc[i][j][r] = 0.0f;

    for (int kt = 0; kt < ktiles; kt++) {
        int s = kt % NSTG;
        asm volatile("cp.async.wait_group %0;" :: "n"(NSTG - 2));
        __syncthreads();
        int nt = kt + NSTG - 1;
        if (nt < ktiles) issue(nt, nt % NSTG);
        else asm volatile("cp.async.commit_group;" ::: "memory");

        uint32_t abase = a_s0 + s * STGH * 2;
        uint32_t bbase = b_s0 + s * STGH * 2;
#pragma unroll
        for (int kk = 0; kk < 2; kk++) {
            int kb = kk * 16;
            uint32_t afr[4][4], bfr[8][2];
#pragma unroll
            for (int mi = 0; mi < 4; mi++) {
                uint32_t addr = abase + (((wm + mi * 16 + a_row) * ROWPH) + kb + a_koff) * 2;
                LDSM_X4(afr[mi][0], afr[mi][1], afr[mi][2], afr[mi][3], addr);
            }
#pragma unroll
            for (int nj = 0; nj < 4; nj++) {
                uint32_t addr = bbase + (((wn + nj * 16 + b_row) * ROWPH) + kb + b_koff) * 2;
                LDSM_X4(bfr[nj * 2][0], bfr[nj * 2][1],
                        bfr[nj * 2 + 1][0], bfr[nj * 2 + 1][1], addr);
            }
#pragma unroll
            for (int mi = 0; mi < 4; mi++)
#pragma unroll
                for (int ni = 0; ni < 8; ni++)
                    MMA_F16(acc[mi][ni], afr[mi], bfr[ni]);
        }
    }

#pragma unroll
    for (int mi = 0; mi < 4; mi++) {
        int r0 = m0 + wm + mi * 16 + lr;
#pragma unroll
        for (int ni = 0; ni < 8; ni++) {
            int ccol = n0 + wn + ni * 8 + lc * 2;
            if (ccol < N) {
                float* p0 = C + (long)r0 * N + ccol;
                float* p1 = C + (long)(r0 + 8) * N + ccol;
                p0[0] = acc[mi][ni][0];
                p0[1] = acc[mi][ni][1];
                p1[0] = acc[mi][ni][2];
                p1[1] = acc[mi][ni][3];
            }
        }
    }
}

// ---------------- dt / dA ----------------
__global__ void dt_kernel(const float* __restrict__ dt_bias,
                          const float* __restrict__ A_log) {
    int idx = blockIdx.x * blockDim.x + threadIdx.x;
    if (idx >= SEQ * NHEADS) return;
    int l = idx / NHEADS, h = idx % NHEADS;
    float v = g_zxbcdt[l * D_IN_PROJ + (D_IN_PROJ - NHEADS) + h] + dt_bias[h];
    float sp = softplusf(v);
    g_dt[idx] = sp;
    g_dA[idx] = -expf(A_log[h]) * sp;
}

// ---------------- causal depthwise conv + SiLU + split ----------------
__global__ void conv_kernel(const float* __restrict__ conv_w,
                            const float* __restrict__ conv_b) {
    int idx = blockIdx.x * blockDim.x + threadIdx.x;
    if (idx >= SEQ * CONV_DIM) return;
    int l = idx / CONV_DIM, ch = idx % CONV_DIM;
    float acc = conv_b[ch];
#pragma unroll
    for (int k = 0; k < D_CONV; k++) {
        int ls = l - (D_CONV - 1) + k;
        if (ls >= 0)
            acc += g_zxbcdt[ls * D_IN_PROJ + DIM_INNER + ch] * conv_w[ch * D_CONV + k];
    }
    float v = siluf(acc);
    if (ch < DIM_INNER) {
        int h = ch >> 7;
        g_xs [l * DIM_INNER + ch] = v;
        g_xdt[l * DIM_INNER + ch] = v * g_dt[l * NHEADS + h];
    } else if (ch < DIM_INNER + D_STATE) {
        g_B[l * D_STATE + (ch - DIM_INNER)] = v;
    } else {
        g_C[l * D_STATE + (ch - DIM_INNER - D_STATE)] = v;
    }
}

// ---------------- per-(chunk,head) inclusive cumsum of dA ----------------
__global__ void cumsum_kernel() {
    int ch = blockIdx.x;
    int c = ch / NHEADS, h = ch % NHEADS;
    int t = threadIdx.x;
    __shared__ float s[CHUNK];
    s[t] = g_dA[(c * CHUNK + t) * NHEADS + h];
    __syncthreads();
    for (int off = 1; off < CHUNK; off <<= 1) {
        float add = (t >= off) ? s[t - off] : 0.0f;
        __syncthreads();
        s[t] += add;
        __syncthreads();
    }
    g_Acs[ch * CHUNK + t] = s[t];
    if (t == CHUNK - 1) g_Alast[ch] = s[t];
}

// ---------------- chunk states ----------------
__global__ void __launch_bounds__(256)
states_kernel() {
    int ch = blockIdx.x;
    int c = ch / NHEADS, h = ch % NHEADS;
    int t = threadIdx.x;
    int tp = t & 15;
    int tn = t >> 4;

    __shared__ float xw[32][HEADDIM];
    __shared__ float Bs2[32][D_STATE];
    __shared__ float dec[32];

    float acc[8][4];
#pragma unroll
    for (int i = 0; i < 8; i++)
#pragma unroll
        for (int j = 0; j < 4; j++) acc[i][j] = 0.0f;

    float Al = g_Alast[ch];

    for (int lt = 0; lt < CHUNK; lt += 32) {
        if (t < 32) dec[t] = expf(Al - g_Acs[ch * CHUNK + lt + t]);
        __syncthreads();
#pragma unroll
        for (int r = 0; r < 16; r++) {
            int lin = t + r * 256;
            int l = lin >> 7, p = lin & 127;
            xw[l][p] = g_xdt[(c * CHUNK + lt + l) * DIM_INNER + h * HEADDIM + p] * dec[l];
        }
#pragma unroll
        for (int r = 0; r < 8; r++) {
            int lin = t + r * 256;
            int l = lin >> 6, n = lin & 63;
            Bs2[l][n] = g_B[(c * CHUNK + lt + l) * D_STATE + n];
        }
        __syncthreads();
#pragma unroll 4
        for (int l = 0; l < 32; l++) {
            float a[8], b[4];
#pragma unroll
            for (int i = 0; i < 8; i++) a[i] = xw[l][tp * 8 + i];
#pragma unroll
            for (int j = 0; j < 4; j++) b[j] = Bs2[l][tn * 4 + j];
#pragma unroll
            for (int i = 0; i < 8; i++)
#pragma unroll
                for (int j = 0; j < 4; j++)
                    acc[i][j] = fmaf(a[i], b[j], acc[i][j]);
        }
        __syncthreads();
    }
#pragma unroll
    for (int i = 0; i < 8; i++)
#pragma unroll
        for (int j = 0; j < 4; j++)
            g_states[ch * (HEADDIM * D_STATE) + (tp * 8 + i) * D_STATE + tn * 4 + j] = acc[i][j];
}

// ---------------- inter-chunk recurrence ----------------
__global__ void sprev_kernel() {
    int idx = blockIdx.x * blockDim.x + threadIdx.x;
    if (idx >= NHEADS * HEADDIM * D_STATE) return;
    int h = idx / (HEADDIM * D_STATE);
    int r = idx % (HEADDIM * D_STATE);
    float S = 0.0f;
    for (int c = 0; c < NCHUNK; c++) {
        int ch = c * NHEADS + h;
        g_sprev[ch * (HEADDIM * D_STATE) + r] = S;
        S = expf(g_Alast[ch]) * S + g_states[ch * (HEADDIM * D_STATE) + r];
    }
}

// ================ fused SSD Y kernel (fp16 mma) ================
#define YROW 72
#define O_CH   0
#define O_BS   (O_CH + 128 * YROW)
#define O_GS   (O_BS + 64 * YROW)
#define O_XH   (O_GS + 128 * YROW)
#define O_XL   (O_XH + 128 * YROW)
#define O_SS   (O_XL + 128 * YROW)
#define O_END  (O_SS + 128 * YROW)
#define Y_SMEM_BYTES (O_END * 2 + (128 + 128 + 64) * 4)

__global__ void __launch_bounds__(256, 1)
y_mma_kernel(const float* __restrict__ Dparam) {
    extern __shared__ __half ysm[];
    __half* Ch  = ysm + O_CH;
    __half* Bsm = ysm + O_BS;
    __half* Gsm = ysm + O_GS;
    __half* Xh  = ysm + O_XH;
    __half* Xl  = ysm + O_XL;
    __half* Ssm = ysm + O_SS;
    float* acsl  = (float*)(ysm + O_END);
    float* expAl = acsl + 128;
    float* acss  = expAl + 128;

    const int hh = blockIdx.y, c = blockIdx.z;
    const int lh = blockIdx.x;
    const int l0 = lh * 128;
    const int ch = c * NHEADS + hh;
    const int tid  = threadIdx.x;
    const int lane = tid & 31;
    const int warp = tid >> 5;
    const int lr   = lane >> 2;
    const int lc   = lane & 3;
    const int wmY = (warp >> 1) * 32;
    const int wnY = (warp & 1) * 64;
    const int wmG = (warp >> 1) * 32;
    const int wnG = (warp & 1) * 32;

    {
        int n = tid & 63, r4 = tid >> 6;
#pragma unroll
        for (int i = 0; i < 32; i++) {
            int l = r4 + i * 4;
            Ch[l * YROW + n]  = __float2half_rn(g_C[(c * CHUNK + l0 + l) * D_STATE + n]);
            Ssm[l * YROW + n] = __float2half_rn(g_sprev[ch * (HEADDIM * D_STATE) + l * D_STATE + n]);
        }
        if (tid < 128) {
            float a = g_Acs[ch * CHUNK + l0 + tid];
            acsl[tid] = a;
            expAl[tid] = expf(a);
        }
    }
    __syncthreads();

    float acc[2][8][4];
#pragma unroll
    for (int i = 0; i < 2; i++)
#pragma unroll
        for (int j = 0; j < 8; j++)
#pragma unroll
            for (int r = 0; r < 4; r++) acc[i][j][r] = 0.0f;

    // ---- Y_off: C @ Sprev^T (K = 64) ----
#pragma unroll
    for (int kk = 0; kk < 4; kk++) {
        int kb = kk * 16;
        uint32_t afr[2][4], bfr[8][2];
#pragma unroll
        for (int mi = 0; mi < 2; mi++) {
            int mb = wmY + mi * 16 + lr;
            afr[mi][0] = *(const uint32_t*)&Ch[(mb    ) * YROW + kb + lc * 2];
            afr[mi][1] = *(const uint32_t*)&Ch[(mb + 8) * YROW + kb + lc * 2];
            afr[mi][2] = *(const uint32_t*)&Ch[(mb    ) * YROW + kb + 8 + lc * 2];
            afr[mi][3] = *(const uint32_t*)&Ch[(mb + 8) * YROW + kb + 8 + lc * 2];
        }
#pragma unroll
        for (int ni = 0; ni < 8; ni++) {
            int nb = wnY + ni * 8 + lr;
            bfr[ni][0] = *(const uint32_t*)&Ssm[nb * YROW + kb + lc * 2];
            bfr[ni][1] = *(const uint32_t*)&Ssm[nb * YROW + kb + 8 + lc * 2];
        }
#pragma unroll
        for (int mi = 0; mi < 2; mi++)
#pragma unroll
            for (int ni = 0; ni < 8; ni++)
                MMA_F16(acc[mi][ni], afr[mi], bfr[ni]);
    }
#pragma unroll
    for (int mi = 0; mi < 2; mi++) {
        int r0 = wmY + mi * 16 + lr;
        float e0 = expAl[r0], e1 = expAl[r0 + 8];
#pragma unroll
        for (int ni = 0; ni < 8; ni++) {
            acc[mi][ni][0] *= e0; acc[mi][ni][1] *= e0;
            acc[mi][ni][2] *= e1; acc[mi][ni][3] *= e1;
        }
    }

    // ---- Y_diag: s-tiles of 64 ----
    const int nst = 2 * (lh + 1);
    for (int st = 0; st < nst; st++) {
        {
            int n = tid & 63, s4 = tid >> 6;
#pragma unroll
            for (int i = 0; i < 16; i++) {
                int s = s4 + i * 4;
                Bsm[s * YROW + n] = __float2half_rn(g_B[(c * CHUNK + st * 64 + s) * D_STATE + n]);
            }
            if (tid < 64) acss[tid] = g_Acs[ch * CHUNK + st * 64 + tid];
            int p = tid & 127, s2 = tid >> 7;
#pragma unroll
            for (int i = 0; i < 32; i++) {
                int s = s2 + i * 2;
                float v = g_xdt[(c * CHUNK + st * 64 + s) * DIM_INNER + hh * HEADDIM + p];
                __half hi = __float2half_rn(v);
                Xh[p * YROW + s] = hi;
                Xl[p * YROW + s] = __float2half_rn(v - __half2float(hi));
            }
        }
        __syncthreads();

        float gacc[2][4][4];
#pragma unroll
        for (int i = 0; i < 2; i++)
#pragma unroll
            for (int j = 0; j < 4; j++)
#pragma unroll
                for (int r = 0; r < 4; r++) gacc[i][j][r] = 0.0f;
#pragma unroll
        for (int kk = 0; kk < 4; kk++) {
            int kb = kk * 16;
            uint32_t afr[2][4], bfr[4][2];
#pragma unroll
            for (int mi = 0; mi < 2; mi++) {
                int mb = wmG + mi * 16 + lr;
                afr[mi][0] = *(const uint32_t*)&Ch[(mb    ) * YROW + kb + lc * 2];
                afr[mi][1] = *(const uint32_t*)&Ch[(mb + 8) * YROW + kb + lc * 2];
                afr[mi][2] = *(const uint32_t*)&Ch[(mb    ) * YROW + kb + 8 + lc * 2];
                afr[mi][3] = *(const uint32_t*)&Ch[(mb + 8) * YROW + kb + 8 + lc * 2];
            }
#pragma unroll
            for (int ni = 0; ni < 4; ni++) {
                int nb = wnG + ni * 8 + lr;
                bfr[ni][0] = *(const uint32_t*)&Bsm[nb * YROW + kb + lc * 2];
                bfr[ni][1] = *(const uint32_t*)&Bsm[nb * YROW + kb + 8 + lc * 2];
            }
#pragma unroll
            for (int mi = 0; mi < 2; mi++)
#pragma unroll
                for (int ni = 0; ni < 4; ni++)
                    MMA_F16(gacc[mi][ni], afr[mi], bfr[ni]);
        }

        const int sbase = st * 64;
#pragma unroll
        for (int mi = 0; mi < 2; mi++) {
            int r0 = wmG + mi * 16 + lr;
            float a0 = acsl[r0], a1 = acsl[r0 + 8];
            int lg0 = l0 + r0, lg1 = lg0 + 8;
#pragma unroll
            for (int ni = 0; ni < 4; ni++) {
                int cl = wnG + ni * 8 + lc * 2;
                float as0 = acss[cl], as1 = acss[cl + 1];
                int sg0 = sbase + cl, sg1 = sg0 + 1;
                float g00 = (sg0 <= lg0) ? gacc[mi][ni][0] * expf(a0 - as0) : 0.0f;
                float g01 = (sg1 <= lg0) ? gacc[mi][ni][1] * expf(a0 - as1) : 0.0f;
                float g10 = (sg0 <= lg1) ? gacc[mi][ni][2] * expf(a1 - as0) : 0.0f;
                float g11 = (sg1 <= lg1) ? gacc[mi][ni][3] * expf(a1 - as1) : 0.0f;
                Gsm[(r0    ) * YROW + cl    ] = __float2half_rn(g00);
                Gsm[(r0    ) * YROW + cl + 1] = __float2half_rn(g01);
                Gsm[(r0 + 8) * YROW + cl    ] = __float2half_rn(g10);
                Gsm[(r0 + 8) * YROW + cl + 1] = __float2half_rn(g11);
            }
        }
        __syncthreads();

#pragma unroll
        for (int kk = 0; kk < 4; kk++) {
            int kb = kk * 16;
            uint32_t afr[2][4], bh[8][2], bl[8][2];
#pragma unroll
            for (int mi = 0; mi < 2; mi++) {
                int mb = wmY + mi * 16 + lr;
                afr[mi][0] = *(const uint32_t*)&Gsm[(mb    ) * YROW + kb + lc * 2];
                afr[mi][1] = *(const uint32_t*)&Gsm[(mb + 8) * YROW + kb + lc * 2];
                afr[mi][2] = *(const uint32_t*)&Gsm[(mb    ) * YROW + kb + 8 + lc * 2];
                afr[mi][3] = *(const uint32_t*)&Gsm[(mb + 8) * YROW + kb + 8 + lc * 2];
            }
#pragma unroll
            for (int ni = 0; ni < 8; ni++) {
                int nb = wnY + ni * 8 + lr;
                bh[ni][0] = *(const uint32_t*)&Xh[nb * YROW + kb + lc * 2];
                bh[ni][1] = *(const uint32_t*)&Xh[nb * YROW + kb + 8 + lc * 2];
                bl[ni][0] = *(const uint32_t*)&Xl[nb * YROW + kb + lc * 2];
                bl[ni][1] = *(const uint32_t*)&Xl[nb * YROW + kb + 8 + lc * 2];
            }
#pragma unroll
            for (int mi = 0; mi < 2; mi++)
#pragma unroll
                for (int ni = 0; ni < 8; ni++) {
                    MMA_F16(acc[mi][ni], afr[mi], bh[ni]);
                    MMA_F16(acc[mi][ni], afr[mi], bl[ni]);
                }
        }
        __syncthreads();
    }

    float Dh = Dparam[hh];
#pragma unroll
    for (int mi = 0; mi < 2; mi++) {
        int r0 = wmY + mi * 16 + lr;
#pragma unroll
        for (int ni = 0; ni < 8; ni++) {
            int col = wnY + ni * 8 + lc * 2;
            long o0 = (long)(c * CHUNK + l0 + r0) * DIM_INNER + hh * HEADDIM + col;
            long o1 = o0 + 8L * DIM_INNER;
            g_y[o0]     = acc[mi][ni][0] + g_xs[o0] * Dh;
            g_y[o0 + 1] = acc[mi][ni][1] + g_xs[o0 + 1] * Dh;
            g_y[o1]     = acc[mi][ni][2] + g_xs[o1] * Dh;
            g_y[o1 + 1] = acc[mi][ni][3] + g_xs[o1 + 1] * Dh;
        }
    }
}

// ---------------- gated RMSNorm (writes fp16 for out_proj) ----------------
__global__ void __launch_bounds__(256)
norm_kernel(const float* __restrict__ norm_w) {
    int l = blockIdx.x;
    int t = threadIdx.x;
    float vals[16];
    float ss = 0.0f;
#pragma unroll
    for (int r = 0; r < 16; r++) {
        int j = t + r * 256;
        float yv = g_y[l * DIM_INNER + j];
        float zv = g_zxbcdt[l * D_IN_PROJ + j];
        float gv = yv * siluf(zv);
        vals[r] = gv;
        ss += gv * gv;
    }
    __shared__ float red[8];
#pragma unroll
    for (int off = 16; off > 0; off >>= 1)
        ss += __shfl_down_sync(0xffffffffu, ss, off);
    if ((t & 31) == 0) red[t >> 5] = ss;
    __syncthreads();
    float total;
    {
        float v = (t < 8) ? red[t] : 0.0f;
#pragma unroll
        for (int off = 4; off > 0; off >>= 1)
            v += __shfl_down_sync(0xffffffffu, v, off);
        if (t == 0) red[0] = v;
    }
    __syncthreads();
    total = red[0];
    float scale = rsqrtf(total / (float)DIM_INNER + 1e-5f);
#pragma unroll
    for (int r = 0; r < 16; r++) {
        int j = t + r * 256;
        g_yh[l * DIM_INNER + j] = __float2half_rn(vals[r] * scale * norm_w[j]);
    }
}

// ---------------- host launcher ----------------
extern "C" void kernel_launch(void* const* d_in, const int* in_sizes, int n_in,
                              void* d_out, int out_size) {
    const float* x        = (const float*)d_in[0];
    const float* in_w     = (const float*)d_in[1];
    const float* conv_w   = (const float*)d_in[2];
    const float* conv_b   = (const float*)d_in[3];
    const float* dt_bias  = (const float*)d_in[4];
    const float* A_log    = (const float*)d_in[5];
    const float* Dparam   = (const float*)d_in[6];
    const float* norm_w   = (const float*)d_in[7];
    const float* out_w    = (const float*)d_in[8];
    float* out            = (float*)d_out;

    float*  zx;  cudaGetSymbolAddress((void**)&zx,  g_zxbcdt);
    __half* wA;  cudaGetSymbolAddress((void**)&wA,  g_wA);
    __half* wB;  cudaGetSymbolAddress((void**)&wB,  g_wB);
    __half* xh;  cudaGetSymbolAddress((void**)&xh,  g_xh);
    __half* yh;  cudaGetSymbolAddress((void**)&yh,  g_yh);

    cudaFuncSetAttribute(h16_gemm, cudaFuncAttributeMaxDynamicSharedMemorySize, GEMM_SMEM);
    cudaFuncSetAttribute(y_mma_kernel, cudaFuncAttributeMaxDynamicSharedMemorySize, Y_SMEM_BYTES);

    // 0. convert GEMM operands to fp16
    tohalf_kernel<<<(D_IN_PROJ * DIM / 8 + 255) / 256, 256>>>(in_w, wA, D_IN_PROJ * DIM);
    tohalf_kernel<<<(SEQ * DIM / 8 + 255) / 256, 256>>>(x, xh, SEQ * DIM);
    tohalf_kernel<<<(DIM * DIM_INNER / 8 + 255) / 256, 256>>>(out_w, wB, DIM * DIM_INNER);

    // 1. in_proj (fp16 mma, 128x128 tile, 64x64 warp tiles, 2 CTAs/SM)
    {
        dim3 grid((D_IN_PROJ + TBN - 1) / TBN, SEQ / TBM);
        h16_gemm<<<grid, 128, GEMM_SMEM>>>(xh, wA, zx, SEQ, D_IN_PROJ, DIM);
    }
    // 2. dt / dA
    dt_kernel<<<(SEQ * NHEADS + 255) / 256, 256>>>(dt_bias, A_log);
    // 3. conv + silu + split
    conv_kernel<<<(SEQ * CONV_DIM + 255) / 256, 256>>>(conv_w, conv_b);
    // 4. cumsum per (chunk, head)
    cumsum_kernel<<<NCHUNK * NHEADS, CHUNK>>>();
    // 5. chunk states
    states_kernel<<<NCHUNK * NHEADS, 256>>>();
    // 6. inter-chunk recurrence
    sprev_kernel<<<(NHEADS * HEADDIM * D_STATE + 255) / 256, 256>>>();
    // 7. Y via fp16 mma
    {
        dim3 grid(2, NHEADS, NCHUNK);
        y_mma_kernel<<<grid, 256, Y_SMEM_BYTES>>>(Dparam);
    }
    // 8. gated RMSNorm
    norm_kernel<<<SEQ, 256>>>(norm_w);
    // 9. out_proj
    {
        dim3 grid(DIM / TBN, SEQ / TBM);
        h16_gemm<<<grid, 128, GEMM_SMEM>>>(yh, wB, out, SEQ, DIM, DIM_INNER);
    }
}

// round 12
// speedup vs baseline: 1.1533x; 1.0049x over previous
#include <cuda_runtime.h>
#include <cuda_fp16.h>
#include <math.h>
#include <stdint.h>

// ---------------- problem constants ----------------
#define SEQ        2048
#define DIM        2048
#define DIM_INNER  4096
#define D_STATE    64
#define D_CONV     4
#define HEADDIM    128
#define NHEADS     32
#define CHUNK      256
#define NCHUNK     (SEQ / CHUNK)          // 8
#define CONV_DIM   (DIM_INNER + 2 * D_STATE)      // 4224
#define D_IN_PROJ  (2 * DIM_INNER + 2 * D_STATE + NHEADS)  // 8352

// ---------------- scratch (device globals; no allocation allowed) -------------
__device__ __align__(128) float g_zxbcdt[SEQ * D_IN_PROJ];
__device__ float g_dt   [SEQ * NHEADS];
__device__ float g_dA   [SEQ * NHEADS];
__device__ __align__(128) __half g_xsh [SEQ * DIM_INNER];
__device__ __align__(128) float g_xdt  [SEQ * DIM_INNER];
__device__ float g_B    [SEQ * D_STATE];
__device__ float g_C    [SEQ * D_STATE];
__device__ float g_Acs  [NCHUNK * NHEADS * CHUNK];
__device__ float g_Alast[NCHUNK * NHEADS];
__device__ float g_states[NCHUNK * NHEADS * HEADDIM * D_STATE];
__device__ float g_sprev [NCHUNK * NHEADS * HEADDIM * D_STATE];
__device__ __align__(128) float g_y    [SEQ * DIM_INNER];
// fp16 GEMM operands
__device__ __align__(128) __half g_wA [D_IN_PROJ * DIM];
__device__ __align__(128) __half g_wB [DIM * DIM_INNER];
__device__ __align__(128) __half g_xh [SEQ * DIM];
__device__ __align__(128) __half g_yh [SEQ * DIM_INNER];

__device__ __forceinline__ float siluf(float v) { return v / (1.0f + expf(-v)); }
__device__ __forceinline__ float softplusf(float v) { return (v > 20.0f) ? v : log1pf(expf(v)); }

// ---------------- fp32 -> fp16 conversion pass ----------------
__global__ void tohalf_kernel(const float* __restrict__ in, __half* __restrict__ out, int n) {
    int i = (blockIdx.x * blockDim.x + threadIdx.x) * 8;
    if (i >= n) return;
    float4 a = *(const float4*)(in + i);
    float4 b = *(const float4*)(in + i + 4);
    __half2 h0 = __floats2half2_rn(a.x, a.y);
    __half2 h1 = __floats2half2_rn(a.z, a.w);
    __half2 h2 = __floats2half2_rn(b.x, b.y);
    __half2 h3 = __floats2half2_rn(b.z, b.w);
    uint4 o;
    o.x = *(uint32_t*)&h0; o.y = *(uint32_t*)&h1;
    o.z = *(uint32_t*)&h2; o.w = *(uint32_t*)&h3;
    *(uint4*)(out + i) = o;
}

#define MMA_F16(acc, a, b) \
    asm volatile( \
        "mma.sync.aligned.m16n8k16.row.col.f32.f16.f16.f32 " \
        "{%0,%1,%2,%3}, {%4,%5,%6,%7}, {%8,%9}, {%0,%1,%2,%3};" \
        : "+f"((acc)[0]), "+f"((acc)[1]), "+f"((acc)[2]), "+f"((acc)[3]) \
        : "r"((a)[0]), "r"((a)[1]), "r"((a)[2]), "r"((a)[3]), \
          "r"((b)[0]), "r"((b)[1]))

#define LDSM_X4(r0, r1, r2, r3, addr) \
    asm volatile("ldmatrix.sync.aligned.m8n8.x4.shared.b16 {%0,%1,%2,%3}, [%4];" \
        : "=r"(r0), "=r"(r1), "=r"(r2), "=r"(r3) : "r"(addr))

// ==== fp16 mma.sync GEMM: 128x128 CTA, 128 thr (4 warps, 64x64 warp tile),
// ==== TBK=64, cp.async 3-stage + ldmatrix, 2 CTAs/SM ====
#define TBM   128
#define TBN   128
#define TBK   64
#define NSTG  3
#define ROWPH 72                          // row stride in halves (144B)
#define STGH  (TBM * ROWPH)               // 9216 halves per operand per stage
#define GEMM_SMEM (2 * NSTG * STGH * 2)   // 110592 bytes

__global__ void __launch_bounds__(128, 2)
h16_gemm(const __half* __restrict__ A, const __half* __restrict__ B,
         float* __restrict__ C, int M, int N, int K) {
    extern __shared__ __half sm[];

    const int tid  = threadIdx.x;
    const int lane = tid & 31;
    const int warp = tid >> 5;
    const int m0   = blockIdx.y * TBM;
    const int n0   = blockIdx.x * TBN;
    const int wm   = (warp >> 1) * 64;      // 0 or 64
    const int wn   = (warp & 1) * 64;       // 0 or 64
    const int lr   = lane >> 2;
    const int lc   = lane & 3;
    const int ktiles = K / TBK;

    const int lr8 = tid >> 3;               // 0..15 (row group)
    const int lg8 = tid & 7;                // 16B chunk 0..7

    const int rowin  = lane & 7;
    const int a_row  = ((lane >> 3) & 1) * 8 + rowin;
    const int a_koff = ((lane >> 4) & 1) * 8;
    const int b_row  = ((lane >> 4) & 1) * 8 + rowin;
    const int b_koff = ((lane >> 3) & 1) * 8;

    uint32_t a_s0, b_s0;
    {
        uint32_t base;
        asm("{ .reg .u64 t; cvta.to.shared.u64 t, %1; cvt.u32.u64 %0, t; }"
            : "=r"(base) : "l"(sm));
        a_s0 = base;
        b_s0 = base + NSTG * STGH * 2;
    }

    auto issue = [&](int kt, int st) {
        const __half* Ag = A + (long)m0 * K + kt * TBK;
        const __half* Bg = B + (long)n0 * K + kt * TBK;
        uint32_t abase = a_s0 + st * STGH * 2;
        uint32_t bbase = b_s0 + st * STGH * 2;
#pragma unroll
        for (int i = 0; i < 8; i++) {
            int r = lr8 + 16 * i;
            uint32_t doff = r * (ROWPH * 2) + lg8 * 16;
            asm volatile("cp.async.cg.shared.global [%0], [%1], 16;"
                         :: "r"(abase + doff), "l"(Ag + (long)r * K + lg8 * 8) : "memory");
            int sz = (n0 + r < N) ? 16 : 0;
            asm volatile("cp.async.cg.shared.global [%0], [%1], 16, %2;"
                         :: "r"(bbase + doff), "l"(Bg + (long)r * K + lg8 * 8), "r"(sz) : "memory");
        }
        asm volatile("cp.async.commit_group;" ::: "memory");
    };

#pragma unroll
    for (int st = 0; st < NSTG - 1; st++) issue(st, st);

    float acc[4][8][4];
#pragma unroll
    for (int i = 0; i < 4; i++)
#pragma unroll
        for (int j = 0; j < 8; j++)
#pragma unroll
            for (int r = 0; r < 4; r++) acc[i][j][r] = 0.0f;

    for (int kt = 0; kt < ktiles; kt++) {
        int s = kt % NSTG;
        asm volatile("cp.async.wait_group %0;" :: "n"(NSTG - 2));
        __syncthreads();
        int nt = kt + NSTG - 1;
        if (nt < ktiles) issue(nt, nt % NSTG);
        else asm volatile("cp.async.commit_group;" ::: "memory");

        uint32_t abase = a_s0 + s * STGH * 2;
        uint32_t bbase = b_s0 + s * STGH * 2;
#pragma unroll
        for (int kk = 0; kk < 4; kk++) {
            int kb = kk * 16;
            uint32_t afr[4][4], bfr[8][2];
#pragma unroll
            for (int mi = 0; mi < 4; mi++) {
                uint32_t addr = abase + (((wm + mi * 16 + a_row) * ROWPH) + kb + a_koff) * 2;
                LDSM_X4(afr[mi][0], afr[mi][1], afr[mi][2], afr[mi][3], addr);
            }
#pragma unroll
            for (int nj = 0; nj < 4; nj++) {
                uint32_t addr = bbase + (((wn + nj * 16 + b_row) * ROWPH) + kb + b_koff) * 2;
                LDSM_X4(bfr[nj * 2][0], bfr[nj * 2][1],
                        bfr[nj * 2 + 1][0], bfr[nj * 2 + 1][1], addr);
            }
#pragma unroll
            for (int mi = 0; mi < 4; mi++)
#pragma unroll
                for (int ni = 0; ni < 8; ni++)
                    MMA_F16(acc[mi][ni], afr[mi], bfr[ni]);
        }
    }

#pragma unroll
    for (int mi = 0; mi < 4; mi++) {
        int r0 = m0 + wm + mi * 16 + lr;
#pragma unroll
        for (int ni = 0; ni < 8; ni++) {
            int ccol = n0 + wn + ni * 8 + lc * 2;
            if (ccol < N) {
                float* p0 = C + (long)r0 * N + ccol;
                float* p1 = C + (long)(r0 + 8) * N + ccol;
                p0[0] = acc[mi][ni][0];
                p0[1] = acc[mi][ni][1];
                p1[0] = acc[mi][ni][2];
                p1[1] = acc[mi][ni][3];
            }
        }
    }
}

// ---------------- dt / dA ----------------
__global__ void dt_kernel(const float* __restrict__ dt_bias,
                          const float* __restrict__ A_log) {
    int idx = blockIdx.x * blockDim.x + threadIdx.x;
    if (idx >= SEQ * NHEADS) return;
    int l = idx / NHEADS, h = idx % NHEADS;
    float v = g_zxbcdt[l * D_IN_PROJ + (D_IN_PROJ - NHEADS) + h] + dt_bias[h];
    float sp = softplusf(v);
    g_dt[idx] = sp;
    g_dA[idx] = -expf(A_log[h]) * sp;
}

// ---------------- causal depthwise conv + SiLU + split (4-wide) ----------------
__global__ void conv_kernel(const float* __restrict__ conv_w,
                            const float* __restrict__ conv_b) {
    int idx = (blockIdx.x * blockDim.x + threadIdx.x) * 4;
    if (idx >= SEQ * CONV_DIM) return;
    int l = idx / CONV_DIM, ch = idx % CONV_DIM;   // 4 consecutive channels, same l

    float4 wv[4];
#pragma unroll
    for (int j = 0; j < 4; j++)
        wv[j] = *(const float4*)&conv_w[(ch + j) * D_CONV];

    float4 acc = *(const float4*)&conv_b[ch];
#pragma unroll
    for (int k = 0; k < D_CONV; k++) {
        int ls = l - (D_CONV - 1) + k;
        if (ls >= 0) {
            float4 v = *(const float4*)&g_zxbcdt[ls * D_IN_PROJ + DIM_INNER + ch];
            acc.x += v.x * ((const float*)&wv[0])[k];
            acc.y += v.y * ((const float*)&wv[1])[k];
            acc.z += v.z * ((const float*)&wv[2])[k];
            acc.w += v.w * ((const float*)&wv[3])[k];
        }
    }
    acc.x = siluf(acc.x); acc.y = siluf(acc.y);
    acc.z = siluf(acc.z); acc.w = siluf(acc.w);

    if (ch < DIM_INNER) {
        int h = ch >> 7;
        float dtv = g_dt[l * NHEADS + h];
        __half2 h0 = __floats2half2_rn(acc.x, acc.y);
        __half2 h1 = __floats2half2_rn(acc.z, acc.w);
        *(uint32_t*)&g_xsh[l * DIM_INNER + ch]     = *(uint32_t*)&h0;
        *(uint32_t*)&g_xsh[l * DIM_INNER + ch + 2] = *(uint32_t*)&h1;
        float4 xd = make_float4(acc.x * dtv, acc.y * dtv, acc.z * dtv, acc.w * dtv);
        *(float4*)&g_xdt[l * DIM_INNER + ch] = xd;
    } else if (ch < DIM_INNER + D_STATE) {
        *(float4*)&g_B[l * D_STATE + (ch - DIM_INNER)] = acc;
    } else {
        *(float4*)&g_C[l * D_STATE + (ch - DIM_INNER - D_STATE)] = acc;
    }
}

// ---------------- per-(chunk,head) inclusive cumsum of dA ----------------
__global__ void cumsum_kernel() {
    int ch = blockIdx.x;
    int c = ch / NHEADS, h = ch % NHEADS;
    int t = threadIdx.x;
    __shared__ float s[CHUNK];
    s[t] = g_dA[(c * CHUNK + t) * NHEADS + h];
    __syncthreads();
    for (int off = 1; off < CHUNK; off <<= 1) {
        float add = (t >= off) ? s[t - off] : 0.0f;
        __syncthreads();
        s[t] += add;
        __syncthreads();
    }
    g_Acs[ch * CHUNK + t] = s[t];
    if (t == CHUNK - 1) g_Alast[ch] = s[t];
}

// ---------------- chunk states ----------------
__global__ void __launch_bounds__(256)
states_kernel() {
    int ch = blockIdx.x;
    int c = ch / NHEADS, h = ch % NHEADS;
    int t = threadIdx.x;
    int tp = t & 15;
    int tn = t >> 4;

    __shared__ float xw[32][HEADDIM];
    __shared__ float Bs2[32][D_STATE];
    __shared__ float dec[32];

    float acc[8][4];
#pragma unroll
    for (int i = 0; i < 8; i++)
#pragma unroll
        for (int j = 0; j < 4; j++) acc[i][j] = 0.0f;

    float Al = g_Alast[ch];

    for (int lt = 0; lt < CHUNK; lt += 32) {
        if (t < 32) dec[t] = expf(Al - g_Acs[ch * CHUNK + lt + t]);
        __syncthreads();
#pragma unroll
        for (int r = 0; r < 16; r++) {
            int lin = t + r * 256;
            int l = lin >> 7, p = lin & 127;
            xw[l][p] = g_xdt[(c * CHUNK + lt + l) * DIM_INNER + h * HEADDIM + p] * dec[l];
        }
#pragma unroll
        for (int r = 0; r < 8; r++) {
            int lin = t + r * 256;
            int l = lin >> 6, n = lin & 63;
            Bs2[l][n] = g_B[(c * CHUNK + lt + l) * D_STATE + n];
        }
        __syncthreads();
#pragma unroll 4
        for (int l = 0; l < 32; l++) {
            float a[8], b[4];
#pragma unroll
            for (int i = 0; i < 8; i++) a[i] = xw[l][tp * 8 + i];
#pragma unroll
            for (int j = 0; j < 4; j++) b[j] = Bs2[l][tn * 4 + j];
#pragma unroll
            for (int i = 0; i < 8; i++)
#pragma unroll
                for (int j = 0; j < 4; j++)
                    acc[i][j] = fmaf(a[i], b[j], acc[i][j]);
        }
        __syncthreads();
    }
#pragma unroll
    for (int i = 0; i < 8; i++)
#pragma unroll
        for (int j = 0; j < 4; j++)
            g_states[ch * (HEADDIM * D_STATE) + (tp * 8 + i) * D_STATE + tn * 4 + j] = acc[i][j];
}

// ---------------- inter-chunk recurrence ----------------
__global__ void sprev_kernel() {
    int idx = blockIdx.x * blockDim.x + threadIdx.x;
    if (idx >= NHEADS * HEADDIM * D_STATE) return;
    int h = idx / (HEADDIM * D_STATE);
    int r = idx % (HEADDIM * D_STATE);
    float S = 0.0f;
    for (int c = 0; c < NCHUNK; c++) {
        int ch = c * NHEADS + h;
        g_sprev[ch * (HEADDIM * D_STATE) + r] = S;
        S = expf(g_Alast[ch]) * S + g_states[ch * (HEADDIM * D_STATE) + r];
    }
}

// ================ fused SSD Y kernel (fp16 mma) ================
#define YROW 72
#define O_CH   0
#define O_BS   (O_CH + 128 * YROW)
#define O_GS   (O_BS + 64 * YROW)
#define O_XH   (O_GS + 128 * YROW)
#define O_XL   (O_XH + 128 * YROW)
#define O_SS   (O_XL + 128 * YROW)
#define O_END  (O_SS + 128 * YROW)
#define Y_SMEM_BYTES (O_END * 2 + (128 + 128 + 64) * 4)

__global__ void __launch_bounds__(256, 1)
y_mma_kernel(const float* __restrict__ Dparam) {
    extern __shared__ __half ysm[];
    __half* Ch  = ysm + O_CH;
    __half* Bsm = ysm + O_BS;
    __half* Gsm = ysm + O_GS;
    __half* Xh  = ysm + O_XH;
    __half* Xl  = ysm + O_XL;
    __half* Ssm = ysm + O_SS;
    float* acsl  = (float*)(ysm + O_END);
    float* expAl = acsl + 128;
    float* acss  = expAl + 128;

    const int hh = blockIdx.y, c = blockIdx.z;
    const int lh = blockIdx.x;
    const int l0 = lh * 128;
    const int ch = c * NHEADS + hh;
    const int tid  = threadIdx.x;
    const int lane = tid & 31;
    const int warp = tid >> 5;
    const int lr   = lane >> 2;
    const int lc   = lane & 3;
    const int wmY = (warp >> 1) * 32;
    const int wnY = (warp & 1) * 64;
    const int wmG = (warp >> 1) * 32;
    const int wnG = (warp & 1) * 32;

    {
        int n = tid & 63, r4 = tid >> 6;
#pragma unroll
        for (int i = 0; i < 32; i++) {
            int l = r4 + i * 4;
            Ch[l * YROW + n]  = __float2half_rn(g_C[(c * CHUNK + l0 + l) * D_STATE + n]);
            Ssm[l * YROW + n] = __float2half_rn(g_sprev[ch * (HEADDIM * D_STATE) + l * D_STATE + n]);
        }
        if (tid < 128) {
            float a = g_Acs[ch * CHUNK + l0 + tid];
            acsl[tid] = a;
            expAl[tid] = expf(a);
        }
    }
    __syncthreads();

    float acc[2][8][4];
#pragma unroll
    for (int i = 0; i < 2; i++)
#pragma unroll
        for (int j = 0; j < 8; j++)
#pragma unroll
            for (int r = 0; r < 4; r++) acc[i][j][r] = 0.0f;

    // ---- Y_off: C @ Sprev^T (K = 64) ----
#pragma unroll
    for (int kk = 0; kk < 4; kk++) {
        int kb = kk * 16;
        uint32_t afr[2][4], bfr[8][2];
#pragma unroll
        for (int mi = 0; mi < 2; mi++) {
            int mb = wmY + mi * 16 + lr;
            afr[mi][0] = *(const uint32_t*)&Ch[(mb    ) * YROW + kb + lc * 2];
            afr[mi][1] = *(const uint32_t*)&Ch[(mb + 8) * YROW + kb + lc * 2];
            afr[mi][2] = *(const uint32_t*)&Ch[(mb    ) * YROW + kb + 8 + lc * 2];
            afr[mi][3] = *(const uint32_t*)&Ch[(mb + 8) * YROW + kb + 8 + lc * 2];
        }
#pragma unroll
        for (int ni = 0; ni < 8; ni++) {
            int nb = wnY + ni * 8 + lr;
            bfr[ni][0] = *(const uint32_t*)&Ssm[nb * YROW + kb + lc * 2];
            bfr[ni][1] = *(const uint32_t*)&Ssm[nb * YROW + kb + 8 + lc * 2];
        }
#pragma unroll
        for (int mi = 0; mi < 2; mi++)
#pragma unroll
            for (int ni = 0; ni < 8; ni++)
                MMA_F16(acc[mi][ni], afr[mi], bfr[ni]);
    }
#pragma unroll
    for (int mi = 0; mi < 2; mi++) {
        int r0 = wmY + mi * 16 + lr;
        float e0 = expAl[r0], e1 = expAl[r0 + 8];
#pragma unroll
        for (int ni = 0; ni < 8; ni++) {
            acc[mi][ni][0] *= e0; acc[mi][ni][1] *= e0;
            acc[mi][ni][2] *= e1; acc[mi][ni][3] *= e1;
        }
    }

    // ---- Y_diag: s-tiles of 64 ----
    const int nst = 2 * (lh + 1);
    for (int st = 0; st < nst; st++) {
        {
            int n = tid & 63, s4 = tid >> 6;
#pragma unroll
            for (int i = 0; i < 16; i++) {
                int s = s4 + i * 4;
                Bsm[s * YROW + n] = __float2half_rn(g_B[(c * CHUNK + st * 64 + s) * D_STATE + n]);
            }
            if (tid < 64) acss[tid] = g_Acs[ch * CHUNK + st * 64 + tid];
            int p = tid & 127, s2 = tid >> 7;
#pragma unroll
            for (int i = 0; i < 32; i++) {
                int s = s2 + i * 2;
                float v = g_xdt[(c * CHUNK + st * 64 + s) * DIM_INNER + hh * HEADDIM + p];
                __half hi = __float2half_rn(v);
                Xh[p * YROW + s] = hi;
                Xl[p * YROW + s] = __float2half_rn(v - __half2float(hi));
            }
        }
        __syncthreads();

        float gacc[2][4][4];
#pragma unroll
        for (int i = 0; i < 2; i++)
#pragma unroll
            for (int j = 0; j < 4; j++)
#pragma unroll
                for (int r = 0; r < 4; r++) gacc[i][j][r] = 0.0f;
#pragma unroll
        for (int kk = 0; kk < 4; kk++) {
            int kb = kk * 16;
            uint32_t afr[2][4], bfr[4][2];
#pragma unroll
            for (int mi = 0; mi < 2; mi++) {
                int mb = wmG + mi * 16 + lr;
                afr[mi][0] = *(const uint32_t*)&Ch[(mb    ) * YROW + kb + lc * 2];
                afr[mi][1] = *(const uint32_t*)&Ch[(mb + 8) * YROW + kb + lc * 2];
                afr[mi][2] = *(const uint32_t*)&Ch[(mb    ) * YROW + kb + 8 + lc * 2];
                afr[mi][3] = *(const uint32_t*)&Ch[(mb + 8) * YROW + kb + 8 + lc * 2];
            }
#pragma unroll
            for (int ni = 0; ni < 4; ni++) {
                int nb = wnG + ni * 8 + lr;
                bfr[ni][0] = *(const uint32_t*)&Bsm[nb * YROW + kb + lc * 2];
                bfr[ni][1] = *(const uint32_t*)&Bsm[nb * YROW + kb + 8 + lc * 2];
            }
#pragma unroll
            for (int mi = 0; mi < 2; mi++)
#pragma unroll
                for (int ni = 0; ni < 4; ni++)
                    MMA_F16(gacc[mi][ni], afr[mi], bfr[ni]);
        }

        const int sbase = st * 64;
#pragma unroll
        for (int mi = 0; mi < 2; mi++) {
            int r0 = wmG + mi * 16 + lr;
            float a0 = acsl[r0], a1 = acsl[r0 + 8];
            int lg0 = l0 + r0, lg1 = lg0 + 8;
#pragma unroll
            for (int ni = 0; ni < 4; ni++) {
                int cl = wnG + ni * 8 + lc * 2;
                float as0 = acss[cl], as1 = acss[cl + 1];
                int sg0 = sbase + cl, sg1 = sg0 + 1;
                float g00 = (sg0 <= lg0) ? gacc[mi][ni][0] * expf(a0 - as0) : 0.0f;
                float g01 = (sg1 <= lg0) ? gacc[mi][ni][1] * expf(a0 - as1) : 0.0f;
                float g10 = (sg0 <= lg1) ? gacc[mi][ni][2] * expf(a1 - as0) : 0.0f;
                float g11 = (sg1 <= lg1) ? gacc[mi][ni][3] * expf(a1 - as1) : 0.0f;
                Gsm[(r0    ) * YROW + cl    ] = __float2half_rn(g00);
                Gsm[(r0    ) * YROW + cl + 1] = __float2half_rn(g01);
                Gsm[(r0 + 8) * YROW + cl    ] = __float2half_rn(g10);
                Gsm[(r0 + 8) * YROW + cl + 1] = __float2half_rn(g11);
            }
        }
        __syncthreads();

#pragma unroll
        for (int kk = 0; kk < 4; kk++) {
            int kb = kk * 16;
            uint32_t afr[2][4], bh[8][2], bl[8][2];
#pragma unroll
            for (int mi = 0; mi < 2; mi++) {
                int mb = wmY + mi * 16 + lr;
                afr[mi][0] = *(const uint32_t*)&Gsm[(mb    ) * YROW + kb + lc * 2];
                afr[mi][1] = *(const uint32_t*)&Gsm[(mb + 8) * YROW + kb + lc * 2];
                afr[mi][2] = *(const uint32_t*)&Gsm[(mb    ) * YROW + kb + 8 + lc * 2];
                afr[mi][3] = *(const uint32_t*)&Gsm[(mb + 8) * YROW + kb + 8 + lc * 2];
            }
#pragma unroll
            for (int ni = 0; ni < 8; ni++) {
                int nb = wnY + ni * 8 + lr;
                bh[ni][0] = *(const uint32_t*)&Xh[nb * YROW + kb + lc * 2];
                bh[ni][1] = *(const uint32_t*)&Xh[nb * YROW + kb + 8 + lc * 2];
                bl[ni][0] = *(const uint32_t*)&Xl[nb * YROW + kb + lc * 2];
                bl[ni][1] = *(const uint32_t*)&Xl[nb * YROW + kb + 8 + lc * 2];
            }
#pragma unroll
            for (int mi = 0; mi < 2; mi++)
#pragma unroll
                for (int ni = 0; ni < 8; ni++) {
                    MMA_F16(acc[mi][ni], afr[mi], bh[ni]);
                    MMA_F16(acc[mi][ni], afr[mi], bl[ni]);
                }
        }
        __syncthreads();
    }

    float Dh = Dparam[hh];
#pragma unroll
    for (int mi = 0; mi < 2; mi++) {
        int r0 = wmY + mi * 16 + lr;
#pragma unroll
        for (int ni = 0; ni < 8; ni++) {
            int col = wnY + ni * 8 + lc * 2;
            long o0 = (long)(c * CHUNK + l0 + r0) * DIM_INNER + hh * HEADDIM + col;
            long o1 = o0 + 8L * DIM_INNER;
            g_y[o0]     = acc[mi][ni][0] + __half2float(g_xsh[o0]) * Dh;
            g_y[o0 + 1] = acc[mi][ni][1] + __half2float(g_xsh[o0 + 1]) * Dh;
            g_y[o1]     = acc[mi][ni][2] + __half2float(g_xsh[o1]) * Dh;
            g_y[o1 + 1] = acc[mi][ni][3] + __half2float(g_xsh[o1 + 1]) * Dh;
        }
    }
}

// ---------------- gated RMSNorm (writes fp16 for out_proj) ----------------
__global__ void __launch_bounds__(256)
norm_kernel(const float* __restrict__ norm_w) {
    int l = blockIdx.x;
    int t = threadIdx.x;
    float vals[16];
    float ss = 0.0f;
#pragma unroll
    for (int r = 0; r < 16; r++) {
        int j = t + r * 256;
        float yv = g_y[l * DIM_INNER + j];
        float zv = g_zxbcdt[l * D_IN_PROJ + j];
        float gv = yv * siluf(zv);
        vals[r] = gv;
        ss += gv * gv;
    }
    __shared__ float red[8];
#pragma unroll
    for (int off = 16; off > 0; off >>= 1)
        ss += __shfl_down_sync(0xffffffffu, ss, off);
    if ((t & 31) == 0) red[t >> 5] = ss;
    __syncthreads();
    float total;
    {
        float v = (t < 8) ? red[t] : 0.0f;
#pragma unroll
        for (int off = 4; off > 0; off >>= 1)
            v += __shfl_down_sync(0xffffffffu, v, off);
        if (t == 0) red[0] = v;
    }
    __syncthreads();
    total = red[0];
    float scale = rsqrtf(total / (float)DIM_INNER + 1e-5f);
#pragma unroll
    for (int r = 0; r < 16; r++) {
        int j = t + r * 256;
        g_yh[l * DIM_INNER + j] = __float2half_rn(vals[r] * scale * norm_w[j]);
    }
}

// ---------------- host launcher ----------------
extern "C" void kernel_launch(void* const* d_in, const int* in_sizes, int n_in,
                              void* d_out, int out_size) {
    const float* x        = (const float*)d_in[0];
    const float* in_w     = (const float*)d_in[1];
    const float* conv_w   = (const float*)d_in[2];
    const float* conv_b   = (const float*)d_in[3];
    const float* dt_bias  = (const float*)d_in[4];
    const float* A_log    = (const float*)d_in[5];
    const float* Dparam   = (const float*)d_in[6];
    const float* norm_w   = (const float*)d_in[7];
    const float* out_w    = (const float*)d_in[8];
    float* out            = (float*)d_out;

    float*  zx;  cudaGetSymbolAddress((void**)&zx,  g_zxbcdt);
    __half* wA;  cudaGetSymbolAddress((void**)&wA,  g_wA);
    __half* wB;  cudaGetSymbolAddress((void**)&wB,  g_wB);
    __half* xh;  cudaGetSymbolAddress((void**)&xh,  g_xh);
    __half* yh;  cudaGetSymbolAddress((void**)&yh,  g_yh);

    cudaFuncSetAttribute(h16_gemm, cudaFuncAttributeMaxDynamicSharedMemorySize, GEMM_SMEM);
    cudaFuncSetAttribute(y_mma_kernel, cudaFuncAttributeMaxDynamicSharedMemorySize, Y_SMEM_BYTES);

    // 0. convert GEMM operands to fp16
    tohalf_kernel<<<(D_IN_PROJ * DIM / 8 + 255) / 256, 256>>>(in_w, wA, D_IN_PROJ * DIM);
    tohalf_kernel<<<(SEQ * DIM / 8 + 255) / 256, 256>>>(x, xh, SEQ * DIM);
    tohalf_kernel<<<(DIM * DIM_INNER / 8 + 255) / 256, 256>>>(out_w, wB, DIM * DIM_INNER);

    // 1. in_proj (fp16 mma, TBK=64, 3-stage, 2 CTAs/SM)
    {
        dim3 grid((D_IN_PROJ + TBN - 1) / TBN, SEQ / TBM);
        h16_gemm<<<grid, 128, GEMM_SMEM>>>(xh, wA, zx, SEQ, D_IN_PROJ, DIM);
    }
    // 2. dt / dA
    dt_kernel<<<(SEQ * NHEADS + 255) / 256, 256>>>(dt_bias, A_log);
    // 3. conv + silu + split (4 channels/thread)
    conv_kernel<<<(SEQ * CONV_DIM / 4 + 255) / 256, 256>>>(conv_w, conv_b);
    // 4. cumsum per (chunk, head)
    cumsum_kernel<<<NCHUNK * NHEADS, CHUNK>>>();
    // 5. chunk states
    states_kernel<<<NCHUNK * NHEADS, 256>>>();
    // 6. inter-chunk recurrence
    sprev_kernel<<<(NHEADS * HEADDIM * D_STATE + 255) / 256, 256>>>();
    // 7. Y via fp16 mma
    {
        dim3 grid(2, NHEADS, NCHUNK);
        y_mma_kernel<<<grid, 256, Y_SMEM_BYTES>>>(Dparam);
    }
    // 8. gated RMSNorm
    norm_kernel<<<SEQ, 256>>>(norm_w);
    // 9. out_proj
    {
        dim3 grid(DIM / TBN, SEQ / TBM);
        h16_gemm<<<grid, 128, GEMM_SMEM>>>(yh, wB, out, SEQ, DIM, DIM_INNER);
    }
}

// round 13
// speedup vs baseline: 1.3341x; 1.1568x over previous
#include <cuda_runtime.h>
#include <cuda_fp16.h>
#include <math.h>
#include <stdint.h>

// ---------------- problem constants ----------------
#define SEQ        2048
#define DIM        2048
#define DIM_INNER  4096
#define D_STATE    64
#define D_CONV     4
#define HEADDIM    128
#define NHEADS     32
#define CHUNK      256
#define NCHUNK     (SEQ / CHUNK)          // 8
#define CONV_DIM   (DIM_INNER + 2 * D_STATE)      // 4224
#define D_IN_PROJ  (2 * DIM_INNER + 2 * D_STATE + NHEADS)  // 8352

// ---------------- scratch (device globals; no allocation allowed) -------------
__device__ __align__(128) float g_zxbcdt[SEQ * D_IN_PROJ];
__device__ float g_dt   [SEQ * NHEADS];
__device__ float g_dA   [SEQ * NHEADS];
__device__ __align__(128) __half g_xsh [SEQ * DIM_INNER];
__device__ __align__(128) float g_xdt  [SEQ * DIM_INNER];
__device__ float g_B    [SEQ * D_STATE];
__device__ float g_C    [SEQ * D_STATE];
__device__ float g_Acs  [NCHUNK * NHEADS * CHUNK];
__device__ float g_Alast[NCHUNK * NHEADS];
__device__ float g_states[NCHUNK * NHEADS * HEADDIM * D_STATE];
__device__ float g_sprev [NCHUNK * NHEADS * HEADDIM * D_STATE];
__device__ __align__(128) float g_y    [SEQ * DIM_INNER];
// fp16 GEMM operands
__device__ __align__(128) __half g_wA [D_IN_PROJ * DIM];
__device__ __align__(128) __half g_wB [DIM * DIM_INNER];
__device__ __align__(128) __half g_xh [SEQ * DIM];
__device__ __align__(128) __half g_yh [SEQ * DIM_INNER];

__device__ __forceinline__ float siluf(float v) { return v / (1.0f + expf(-v)); }
__device__ __forceinline__ float softplusf(float v) { return (v > 20.0f) ? v : log1pf(expf(v)); }

// ---------------- fp32 -> fp16 conversion pass ----------------
__global__ void tohalf_kernel(const float* __restrict__ in, __half* __restrict__ out, int n) {
    int i = (blockIdx.x * blockDim.x + threadIdx.x) * 8;
    if (i >= n) return;
    float4 a = *(const float4*)(in + i);
    float4 b = *(const float4*)(in + i + 4);
    __half2 h0 = __floats2half2_rn(a.x, a.y);
    __half2 h1 = __floats2half2_rn(a.z, a.w);
    __half2 h2 = __floats2half2_rn(b.x, b.y);
    __half2 h3 = __floats2half2_rn(b.z, b.w);
    uint4 o;
    o.x = *(uint32_t*)&h0; o.y = *(uint32_t*)&h1;
    o.z = *(uint32_t*)&h2; o.w = *(uint32_t*)&h3;
    *(uint4*)(out + i) = o;
}

#define MMA_F16(acc, a, b) \
    asm volatile( \
        "mma.sync.aligned.m16n8k16.row.col.f32.f16.f16.f32 " \
        "{%0,%1,%2,%3}, {%4,%5,%6,%7}, {%8,%9}, {%0,%1,%2,%3};" \
        : "+f"((acc)[0]), "+f"((acc)[1]), "+f"((acc)[2]), "+f"((acc)[3]) \
        : "r"((a)[0]), "r"((a)[1]), "r"((a)[2]), "r"((a)[3]), \
          "r"((b)[0]), "r"((b)[1]))

#define LDSM_X4(r0, r1, r2, r3, addr) \
    asm volatile("ldmatrix.sync.aligned.m8n8.x4.shared.b16 {%0,%1,%2,%3}, [%4];" \
        : "=r"(r0), "=r"(r1), "=r"(r2), "=r"(r3) : "r"(addr))

// ==== fp16 mma.sync GEMM (R11-proven): 128x128 CTA, 128 thr, 64x64 warp tile,
// ==== TBK=32, cp.async 4-stage + ldmatrix, 2 CTAs/SM ====
#define TBM   128
#define TBN   128
#define TBK   32
#define NSTG  4
#define ROWPH 40
#define STGH  (TBM * ROWPH)              // 5120 halves per operand per stage
#define GEMM_SMEM (2 * NSTG * STGH * 2)  // 81920 bytes

__global__ void __launch_bounds__(128, 2)
h16_gemm(const __half* __restrict__ A, const __half* __restrict__ B,
         float* __restrict__ C, int M, int N, int K) {
    extern __shared__ __half sm[];

    const int tid  = threadIdx.x;
    const int lane = tid & 31;
    const int warp = tid >> 5;
    const int m0   = blockIdx.y * TBM;
    const int n0   = blockIdx.x * TBN;
    const int wm   = (warp >> 1) * 64;
    const int wn   = (warp & 1) * 64;
    const int lr   = lane >> 2;
    const int lc   = lane & 3;
    const int ktiles = K / TBK;

    const int lrow = tid >> 2;              // 0..31
    const int lch  = (tid & 3) * 8;

    const int rowin  = lane & 7;
    const int a_row  = ((lane >> 3) & 1) * 8 + rowin;
    const int a_koff = ((lane >> 4) & 1) * 8;
    const int b_row  = ((lane >> 4) & 1) * 8 + rowin;
    const int b_koff = ((lane >> 3) & 1) * 8;

    uint32_t a_s0, b_s0;
    {
        uint32_t base;
        asm("{ .reg .u64 t; cvta.to.shared.u64 t, %1; cvt.u32.u64 %0, t; }"
            : "=r"(base) : "l"(sm));
        a_s0 = base;
        b_s0 = base + NSTG * STGH * 2;
    }

    auto issue = [&](int kt, int st) {
        const __half* Ag = A + (long)m0 * K + kt * TBK;
        const __half* Bg = B + (long)n0 * K + kt * TBK;
        uint32_t abase = a_s0 + st * STGH * 2;
        uint32_t bbase = b_s0 + st * STGH * 2;
#pragma unroll
        for (int i = 0; i < 4; i++) {
            int r = lrow + i * 32;
            uint32_t doff = r * ROWPH * 2 + lch * 2;
            asm volatile("cp.async.cg.shared.global [%0], [%1], 16;"
                         :: "r"(abase + doff), "l"(Ag + (long)r * K + lch) : "memory");
            int sz = (n0 + r < N) ? 16 : 0;
            asm volatile("cp.async.cg.shared.global [%0], [%1], 16, %2;"
                         :: "r"(bbase + doff), "l"(Bg + (long)r * K + lch), "r"(sz) : "memory");
        }
        asm volatile("cp.async.commit_group;" ::: "memory");
    };

#pragma unroll
    for (int st = 0; st < NSTG - 1; st++) issue(st, st);

    float acc[4][8][4];
#pragma unroll
    for (int i = 0; i < 4; i++)
#pragma unroll
        for (int j = 0; j < 8; j++)
#pragma unroll
            for (int r = 0; r < 4; r++) acc[i][j][r] = 0.0f;

    for (int kt = 0; kt < ktiles; kt++) {
        int s = kt % NSTG;
        asm volatile("cp.async.wait_group %0;" :: "n"(NSTG - 2));
        __syncthreads();
        int nt = kt + NSTG - 1;
        if (nt < ktiles) issue(nt, nt % NSTG);
        else asm volatile("cp.async.commit_group;" ::: "memory");

        uint32_t abase = a_s0 + s * STGH * 2;
        uint32_t bbase = b_s0 + s * STGH * 2;
#pragma unroll
        for (int kk = 0; kk < 2; kk++) {
            int kb = kk * 16;
            uint32_t afr[4][4], bfr[8][2];
#pragma unroll
            for (int mi = 0; mi < 4; mi++) {
                uint32_t addr = abase + (((wm + mi * 16 + a_row) * ROWPH) + kb + a_koff) * 2;
                LDSM_X4(afr[mi][0], afr[mi][1], afr[mi][2], afr[mi][3], addr);
            }
#pragma unroll
            for (int nj = 0; nj < 4; nj++) {
                uint32_t addr = bbase + (((wn + nj * 16 + b_row) * ROWPH) + kb + b_koff) * 2;
                LDSM_X4(bfr[nj * 2][0], bfr[nj * 2][1],
                        bfr[nj * 2 + 1][0], bfr[nj * 2 + 1][1], addr);
            }
#pragma unroll
            for (int mi = 0; mi < 4; mi++)
#pragma unroll
                for (int ni = 0; ni < 8; ni++)
                    MMA_F16(acc[mi][ni], afr[mi], bfr[ni]);
        }
    }

#pragma unroll
    for (int mi = 0; mi < 4; mi++) {
        int r0 = m0 + wm + mi * 16 + lr;
#pragma unroll
        for (int ni = 0; ni < 8; ni++) {
            int ccol = n0 + wn + ni * 8 + lc * 2;
            if (ccol < N) {
                float* p0 = C + (long)r0 * N + ccol;
                float* p1 = C + (long)(r0 + 8) * N + ccol;
                p0[0] = acc[mi][ni][0];
                p0[1] = acc[mi][ni][1];
                p1[0] = acc[mi][ni][2];
                p1[1] = acc[mi][ni][3];
            }
        }
    }
}

// ---------------- dt / dA ----------------
__global__ void dt_kernel(const float* __restrict__ dt_bias,
                          const float* __restrict__ A_log) {
    int idx = blockIdx.x * blockDim.x + threadIdx.x;
    if (idx >= SEQ * NHEADS) return;
    int l = idx / NHEADS, h = idx % NHEADS;
    float v = g_zxbcdt[l * D_IN_PROJ + (D_IN_PROJ - NHEADS) + h] + dt_bias[h];
    float sp = softplusf(v);
    g_dt[idx] = sp;
    g_dA[idx] = -expf(A_log[h]) * sp;
}

// ---------------- causal depthwise conv + SiLU + split (4-wide) ----------------
__global__ void conv_kernel(const float* __restrict__ conv_w,
                            const float* __restrict__ conv_b) {
    int idx = (blockIdx.x * blockDim.x + threadIdx.x) * 4;
    if (idx >= SEQ * CONV_DIM) return;
    int l = idx / CONV_DIM, ch = idx % CONV_DIM;

    float4 wv[4];
#pragma unroll
    for (int j = 0; j < 4; j++)
        wv[j] = *(const float4*)&conv_w[(ch + j) * D_CONV];

    float4 acc = *(const float4*)&conv_b[ch];
#pragma unroll
    for (int k = 0; k < D_CONV; k++) {
        int ls = l - (D_CONV - 1) + k;
        if (ls >= 0) {
            float4 v = *(const float4*)&g_zxbcdt[ls * D_IN_PROJ + DIM_INNER + ch];
            acc.x += v.x * ((const float*)&wv[0])[k];
            acc.y += v.y * ((const float*)&wv[1])[k];
            acc.z += v.z * ((const float*)&wv[2])[k];
            acc.w += v.w * ((const float*)&wv[3])[k];
        }
    }
    acc.x = siluf(acc.x); acc.y = siluf(acc.y);
    acc.z = siluf(acc.z); acc.w = siluf(acc.w);

    if (ch < DIM_INNER) {
        int h = ch >> 7;
        float dtv = g_dt[l * NHEADS + h];
        __half2 h0 = __floats2half2_rn(acc.x, acc.y);
        __half2 h1 = __floats2half2_rn(acc.z, acc.w);
        *(uint32_t*)&g_xsh[l * DIM_INNER + ch]     = *(uint32_t*)&h0;
        *(uint32_t*)&g_xsh[l * DIM_INNER + ch + 2] = *(uint32_t*)&h1;
        float4 xd = make_float4(acc.x * dtv, acc.y * dtv, acc.z * dtv, acc.w * dtv);
        *(float4*)&g_xdt[l * DIM_INNER + ch] = xd;
    } else if (ch < DIM_INNER + D_STATE) {
        *(float4*)&g_B[l * D_STATE + (ch - DIM_INNER)] = acc;
    } else {
        *(float4*)&g_C[l * D_STATE + (ch - DIM_INNER - D_STATE)] = acc;
    }
}

// ---------------- per-(chunk,head) inclusive cumsum of dA ----------------
__global__ void cumsum_kernel() {
    int ch = blockIdx.x;
    int c = ch / NHEADS, h = ch % NHEADS;
    int t = threadIdx.x;
    __shared__ float s[CHUNK];
    s[t] = g_dA[(c * CHUNK + t) * NHEADS + h];
    __syncthreads();
    for (int off = 1; off < CHUNK; off <<= 1) {
        float add = (t >= off) ? s[t - off] : 0.0f;
        __syncthreads();
        s[t] += add;
        __syncthreads();
    }
    g_Acs[ch * CHUNK + t] = s[t];
    if (t == CHUNK - 1) g_Alast[ch] = s[t];
}

// ---------------- chunk states via fp16 mma: S[p,n] = sum_l w(l)*xdt[l,p]*B[l,n]
// M=128 (p), N=64 (n), K=256 (l); K-tiles of 64; A hi/lo split, B fp16.
#define SROW 72
__global__ void __launch_bounds__(256)
states_kernel() {
    __shared__ __half Ah[128 * SROW];    // A hi:  [p][l]
    __shared__ __half Al[128 * SROW];    // A lo
    __shared__ __half Bs[64 * SROW];     // B^T:   [n][l]
    __shared__ float dec[64];

    int chd = blockIdx.x;
    int c = chd / NHEADS, h = chd % NHEADS;
    int tid  = threadIdx.x;
    int lane = tid & 31;
    int warp = tid >> 5;
    int lr = lane >> 2, lc = lane & 3;
    int wm = (warp >> 1) * 32;           // p offset: 0,32,64,96
    int wn = (warp & 1) * 32;            // n offset: 0,32

    float Alast = g_Alast[chd];

    float acc[2][4][4];
#pragma unroll
    for (int i = 0; i < 2; i++)
#pragma unroll
        for (int j = 0; j < 4; j++)
#pragma unroll
            for (int r = 0; r < 4; r++) acc[i][j][r] = 0.0f;

    for (int kt = 0; kt < 4; kt++) {
        int l0 = kt * 64;
        if (tid < 64) dec[tid] = expf(Alast - g_Acs[chd * CHUNK + l0 + tid]);
        __syncthreads();
        // A: [p][l] = xdt[l,p]*dec[l], hi/lo.  8192 elems / 256 thr = 32 each.
        {
            int p = tid & 127, l2 = tid >> 7;
#pragma unroll
            for (int i = 0; i < 32; i++) {
                int l = l2 + i * 2;
                float v = g_xdt[(c * CHUNK + l0 + l) * DIM_INNER + h * HEADDIM + p] * dec[l];
                __half hi = __float2half_rn(v);
                Ah[p * SROW + l] = hi;
                Al[p * SROW + l] = __float2half_rn(v - __half2float(hi));
            }
        }
        // B^T: [n][l].  4096 elems / 256 thr = 16 each.
        {
            int n = tid & 63, l4 = tid >> 6;
#pragma unroll
            for (int i = 0; i < 16; i++) {
                int l = l4 + i * 4;
                Bs[n * SROW + l] = __float2half_rn(g_B[(c * CHUNK + l0 + l) * D_STATE + n]);
            }
        }
        __syncthreads();

#pragma unroll
        for (int kk = 0; kk < 4; kk++) {
            int kb = kk * 16;
            uint32_t ah[2][4], al[2][4], bf[4][2];
#pragma unroll
            for (int mi = 0; mi < 2; mi++) {
                int mb = wm + mi * 16 + lr;
                ah[mi][0] = *(const uint32_t*)&Ah[(mb    ) * SROW + kb + lc * 2];
                ah[mi][1] = *(const uint32_t*)&Ah[(mb + 8) * SROW + kb + lc * 2];
                ah[mi][2] = *(const uint32_t*)&Ah[(mb    ) * SROW + kb + 8 + lc * 2];
                ah[mi][3] = *(const uint32_t*)&Ah[(mb + 8) * SROW + kb + 8 + lc * 2];
                al[mi][0] = *(const uint32_t*)&Al[(mb    ) * SROW + kb + lc * 2];
                al[mi][1] = *(const uint32_t*)&Al[(mb + 8) * SROW + kb + lc * 2];
                al[mi][2] = *(const uint32_t*)&Al[(mb    ) * SROW + kb + 8 + lc * 2];
                al[mi][3] = *(const uint32_t*)&Al[(mb + 8) * SROW + kb + 8 + lc * 2];
            }
#pragma unroll
            for (int ni = 0; ni < 4; ni++) {
                int nb = wn + ni * 8 + lr;
                bf[ni][0] = *(const uint32_t*)&Bs[nb * SROW + kb + lc * 2];
                bf[ni][1] = *(const uint32_t*)&Bs[nb * SROW + kb + 8 + lc * 2];
            }
#pragma unroll
            for (int mi = 0; mi < 2; mi++)
#pragma unroll
                for (int ni = 0; ni < 4; ni++) {
                    MMA_F16(acc[mi][ni], ah[mi], bf[ni]);
                    MMA_F16(acc[mi][ni], al[mi], bf[ni]);
                }
        }
        __syncthreads();
    }

#pragma unroll
    for (int mi = 0; mi < 2; mi++) {
        int p0 = wm + mi * 16 + lr;
#pragma unroll
        for (int ni = 0; ni < 4; ni++) {
            int n = wn + ni * 8 + lc * 2;
            float* s0 = &g_states[chd * (HEADDIM * D_STATE) + p0 * D_STATE + n];
            float* s1 = s0 + 8 * D_STATE;
            s0[0] = acc[mi][ni][0]; s0[1] = acc[mi][ni][1];
            s1[0] = acc[mi][ni][2]; s1[1] = acc[mi][ni][3];
        }
    }
}

// ---------------- inter-chunk recurrence ----------------
__global__ void sprev_kernel() {
    int idx = blockIdx.x * blockDim.x + threadIdx.x;
    if (idx >= NHEADS * HEADDIM * D_STATE) return;
    int h = idx / (HEADDIM * D_STATE);
    int r = idx % (HEADDIM * D_STATE);
    float S = 0.0f;
    for (int c = 0; c < NCHUNK; c++) {
        int ch = c * NHEADS + h;
        g_sprev[ch * (HEADDIM * D_STATE) + r] = S;
        S = expf(g_Alast[ch]) * S + g_states[ch * (HEADDIM * D_STATE) + r];
    }
}

// ================ fused SSD Y kernel (fp16 mma) ================
#define YROW 72
#define O_CH   0
#define O_BS   (O_CH + 128 * YROW)
#define O_GS   (O_BS + 64 * YROW)
#define O_XH   (O_GS + 128 * YROW)
#define O_XL   (O_XH + 128 * YROW)
#define O_SS   (O_XL + 128 * YROW)
#define O_END  (O_SS + 128 * YROW)
#define Y_SMEM_BYTES (O_END * 2 + (128 + 128 + 64) * 4)

__global__ void __launch_bounds__(256, 1)
y_mma_kernel(const float* __restrict__ Dparam) {
    extern __shared__ __half ysm[];
    __half* Ch  = ysm + O_CH;
    __half* Bsm = ysm + O_BS;
    __half* Gsm = ysm + O_GS;
    __half* Xh  = ysm + O_XH;
    __half* Xl  = ysm + O_XL;
    __half* Ssm = ysm + O_SS;
    float* acsl  = (float*)(ysm + O_END);
    float* expAl = acsl + 128;
    float* acss  = expAl + 128;

    const int hh = blockIdx.y, c = blockIdx.z;
    const int lh = blockIdx.x;
    const int l0 = lh * 128;
    const int ch = c * NHEADS + hh;
    const int tid  = threadIdx.x;
    const int lane = tid & 31;
    const int warp = tid >> 5;
    const int lr   = lane >> 2;
    const int lc   = lane & 3;
    const int wmY = (warp >> 1) * 32;
    const int wnY = (warp & 1) * 64;
    const int wmG = (warp >> 1) * 32;
    const int wnG = (warp & 1) * 32;

    {
        int n = tid & 63, r4 = tid >> 6;
#pragma unroll
        for (int i = 0; i < 32; i++) {
            int l = r4 + i * 4;
            Ch[l * YROW + n]  = __float2half_rn(g_C[(c * CHUNK + l0 + l) * D_STATE + n]);
            Ssm[l * YROW + n] = __float2half_rn(g_sprev[ch * (HEADDIM * D_STATE) + l * D_STATE + n]);
        }
        if (tid < 128) {
            float a = g_Acs[ch * CHUNK + l0 + tid];
            acsl[tid] = a;
            expAl[tid] = expf(a);
        }
    }
    __syncthreads();

    float acc[2][8][4];
#pragma unroll
    for (int i = 0; i < 2; i++)
#pragma unroll
        for (int j = 0; j < 8; j++)
#pragma unroll
            for (int r = 0; r < 4; r++) acc[i][j][r] = 0.0f;

    // ---- Y_off: C @ Sprev^T (K = 64) ----
#pragma unroll
    for (int kk = 0; kk < 4; kk++) {
        int kb = kk * 16;
        uint32_t afr[2][4], bfr[8][2];
#pragma unroll
        for (int mi = 0; mi < 2; mi++) {
            int mb = wmY + mi * 16 + lr;
            afr[mi][0] = *(const uint32_t*)&Ch[(mb    ) * YROW + kb + lc * 2];
            afr[mi][1] = *(const uint32_t*)&Ch[(mb + 8) * YROW + kb + lc * 2];
            afr[mi][2] = *(const uint32_t*)&Ch[(mb    ) * YROW + kb + 8 + lc * 2];
            afr[mi][3] = *(const uint32_t*)&Ch[(mb + 8) * YROW + kb + 8 + lc * 2];
        }
#pragma unroll
        for (int ni = 0; ni < 8; ni++) {
            int nb = wnY + ni * 8 + lr;
            bfr[ni][0] = *(const uint32_t*)&Ssm[nb * YROW + kb + lc * 2];
            bfr[ni][1] = *(const uint32_t*)&Ssm[nb * YROW + kb + 8 + lc * 2];
        }
#pragma unroll
        for (int mi = 0; mi < 2; mi++)
#pragma unroll
            for (int ni = 0; ni < 8; ni++)
                MMA_F16(acc[mi][ni], afr[mi], bfr[ni]);
    }
#pragma unroll
    for (int mi = 0; mi < 2; mi++) {
        int r0 = wmY + mi * 16 + lr;
        float e0 = expAl[r0], e1 = expAl[r0 + 8];
#pragma unroll
        for (int ni = 0; ni < 8; ni++) {
            acc[mi][ni][0] *= e0; acc[mi][ni][1] *= e0;
            acc[mi][ni][2] *= e1; acc[mi][ni][3] *= e1;
        }
    }

    // ---- Y_diag: s-tiles of 64 ----
    const int nst = 2 * (lh + 1);
    for (int st = 0; st < nst; st++) {
        {
            int n = tid & 63, s4 = tid >> 6;
#pragma unroll
            for (int i = 0; i < 16; i++) {
                int s = s4 + i * 4;
                Bsm[s * YROW + n] = __float2half_rn(g_B[(c * CHUNK + st * 64 + s) * D_STATE + n]);
            }
            if (tid < 64) acss[tid] = g_Acs[ch * CHUNK + st * 64 + tid];
            int p = tid & 127, s2 = tid >> 7;
#pragma unroll
            for (int i = 0; i < 32; i++) {
                int s = s2 + i * 2;
                float v = g_xdt[(c * CHUNK + st * 64 + s) * DIM_INNER + hh * HEADDIM + p];
                __half hi = __float2half_rn(v);
                Xh[p * YROW + s] = hi;
                Xl[p * YROW + s] = __float2half_rn(v - __half2float(hi));
            }
        }
        __syncthreads();

        float gacc[2][4][4];
#pragma unroll
        for (int i = 0; i < 2; i++)
#pragma unroll
            for (int j = 0; j < 4; j++)
#pragma unroll
                for (int r = 0; r < 4; r++) gacc[i][j][r] = 0.0f;
#pragma unroll
        for (int kk = 0; kk < 4; kk++) {
            int kb = kk * 16;
            uint32_t afr[2][4], bfr[4][2];
#pragma unroll
            for (int mi = 0; mi < 2; mi++) {
                int mb = wmG + mi * 16 + lr;
                afr[mi][0] = *(const uint32_t*)&Ch[(mb    ) * YROW + kb + lc * 2];
                afr[mi][1] = *(const uint32_t*)&Ch[(mb + 8) * YROW + kb + lc * 2];
                afr[mi][2] = *(const uint32_t*)&Ch[(mb    ) * YROW + kb + 8 + lc * 2];
                afr[mi][3] = *(const uint32_t*)&Ch[(mb + 8) * YROW + kb + 8 + lc * 2];
            }
#pragma unroll
            for (int ni = 0; ni < 4; ni++) {
                int nb = wnG + ni * 8 + lr;
                bfr[ni][0] = *(const uint32_t*)&Bsm[nb * YROW + kb + lc * 2];
                bfr[ni][1] = *(const uint32_t*)&Bsm[nb * YROW + kb + 8 + lc * 2];
            }
#pragma unroll
            for (int mi = 0; mi < 2; mi++)
#pragma unroll
                for (int ni = 0; ni < 4; ni++)
                    MMA_F16(gacc[mi][ni], afr[mi], bfr[ni]);
        }

        const int sbase = st * 64;
#pragma unroll
        for (int mi = 0; mi < 2; mi++) {
            int r0 = wmG + mi * 16 + lr;
            float a0 = acsl[r0], a1 = acsl[r0 + 8];
            int lg0 = l0 + r0, lg1 = lg0 + 8;
#pragma unroll
            for (int ni = 0; ni < 4; ni++) {
                int cl = wnG + ni * 8 + lc * 2;
                float as0 = acss[cl], as1 = acss[cl + 1];
                int sg0 = sbase + cl, sg1 = sg0 + 1;
                float g00 = (sg0 <= lg0) ? gacc[mi][ni][0] * expf(a0 - as0) : 0.0f;
                float g01 = (sg1 <= lg0) ? gacc[mi][ni][1] * expf(a0 - as1) : 0.0f;
                float g10 = (sg0 <= lg1) ? gacc[mi][ni][2] * expf(a1 - as0) : 0.0f;
                float g11 = (sg1 <= lg1) ? gacc[mi][ni][3] * expf(a1 - as1) : 0.0f;
                Gsm[(r0    ) * YROW + cl    ] = __float2half_rn(g00);
                Gsm[(r0    ) * YROW + cl + 1] = __float2half_rn(g01);
                Gsm[(r0 + 8) * YROW + cl    ] = __float2half_rn(g10);
                Gsm[(r0 + 8) * YROW + cl + 1] = __float2half_rn(g11);
            }
        }
        __syncthreads();

#pragma unroll
        for (int kk = 0; kk < 4; kk++) {
            int kb = kk * 16;
            uint32_t afr[2][4], bh[8][2], bl[8][2];
#pragma unroll
            for (int mi = 0; mi < 2; mi++) {
                int mb = wmY + mi * 16 + lr;
                afr[mi][0] = *(const uint32_t*)&Gsm[(mb    ) * YROW + kb + lc * 2];
                afr[mi][1] = *(const uint32_t*)&Gsm[(mb + 8) * YROW + kb + lc * 2];
                afr[mi][2] = *(const uint32_t*)&Gsm[(mb    ) * YROW + kb + 8 + lc * 2];
                afr[mi][3] = *(const uint32_t*)&Gsm[(mb + 8) * YROW + kb + 8 + lc * 2];
            }
#pragma unroll
            for (int ni = 0; ni < 8; ni++) {
                int nb = wnY + ni * 8 + lr;
                bh[ni][0] = *(const uint32_t*)&Xh[nb * YROW + kb + lc * 2];
                bh[ni][1] = *(const uint32_t*)&Xh[nb * YROW + kb + 8 + lc * 2];
                bl[ni][0] = *(const uint32_t*)&Xl[nb * YROW + kb + lc * 2];
                bl[ni][1] = *(const uint32_t*)&Xl[nb * YROW + kb + 8 + lc * 2];
            }
#pragma unroll
            for (int mi = 0; mi < 2; mi++)
#pragma unroll
                for (int ni = 0; ni < 8; ni++) {
                    MMA_F16(acc[mi][ni], afr[mi], bh[ni]);
                    MMA_F16(acc[mi][ni], afr[mi], bl[ni]);
                }
        }
        __syncthreads();
    }

    float Dh = Dparam[hh];
#pragma unroll
    for (int mi = 0; mi < 2; mi++) {
        int r0 = wmY + mi * 16 + lr;
#pragma unroll
        for (int ni = 0; ni < 8; ni++) {
            int col = wnY + ni * 8 + lc * 2;
            long o0 = (long)(c * CHUNK + l0 + r0) * DIM_INNER + hh * HEADDIM + col;
            long o1 = o0 + 8L * DIM_INNER;
            g_y[o0]     = acc[mi][ni][0] + __half2float(g_xsh[o0]) * Dh;
            g_y[o0 + 1] = acc[mi][ni][1] + __half2float(g_xsh[o0 + 1]) * Dh;
            g_y[o1]     = acc[mi][ni][2] + __half2float(g_xsh[o1]) * Dh;
            g_y[o1 + 1] = acc[mi][ni][3] + __half2float(g_xsh[o1 + 1]) * Dh;
        }
    }
}

// ---------------- gated RMSNorm (writes fp16 for out_proj) ----------------
__global__ void __launch_bounds__(256)
norm_kernel(const float* __restrict__ norm_w) {
    int l = blockIdx.x;
    int t = threadIdx.x;
    float vals[16];
    float ss = 0.0f;
#pragma unroll
    for (int r = 0; r < 16; r++) {
        int j = t + r * 256;
        float yv = g_y[l * DIM_INNER + j];
        float zv = g_zxbcdt[l * D_IN_PROJ + j];
        float gv = yv * siluf(zv);
        vals[r] = gv;
        ss += gv * gv;
    }
    __shared__ float red[8];
#pragma unroll
    for (int off = 16; off > 0; off >>= 1)
        ss += __shfl_down_sync(0xffffffffu, ss, off);
    if ((t & 31) == 0) red[t >> 5] = ss;
    __syncthreads();
    float total;
    {
        float v = (t < 8) ? red[t] : 0.0f;
#pragma unroll
        for (int off = 4; off > 0; off >>= 1)
            v += __shfl_down_sync(0xffffffffu, v, off);
        if (t == 0) red[0] = v;
    }
    __syncthreads();
    total = red[0];
    float scale = rsqrtf(total / (float)DIM_INNER + 1e-5f);
#pragma unroll
    for (int r = 0; r < 16; r++) {
        int j = t + r * 256;
        g_yh[l * DIM_INNER + j] = __float2half_rn(vals[r] * scale * norm_w[j]);
    }
}

// ---------------- host launcher ----------------
extern "C" void kernel_launch(void* const* d_in, const int* in_sizes, int n_in,
                              void* d_out, int out_size) {
    const float* x        = (const float*)d_in[0];
    const float* in_w     = (const float*)d_in[1];
    const float* conv_w   = (const float*)d_in[2];
    const float* conv_b   = (const float*)d_in[3];
    const float* dt_bias  = (const float*)d_in[4];
    const float* A_log    = (const float*)d_in[5];
    const float* Dparam   = (const float*)d_in[6];
    const float* norm_w   = (const float*)d_in[7];
    const float* out_w    = (const float*)d_in[8];
    float* out            = (float*)d_out;

    float*  zx;  cudaGetSymbolAddress((void**)&zx,  g_zxbcdt);
    __half* wA;  cudaGetSymbolAddress((void**)&wA,  g_wA);
    __half* wB;  cudaGetSymbolAddress((void**)&wB,  g_wB);
    __half* xh;  cudaGetSymbolAddress((void**)&xh,  g_xh);
    __half* yh;  cudaGetSymbolAddress((void**)&yh,  g_yh);

    cudaFuncSetAttribute(h16_gemm, cudaFuncAttributeMaxDynamicSharedMemorySize, GEMM_SMEM);
    cudaFuncSetAttribute(y_mma_kernel, cudaFuncAttributeMaxDynamicSharedMemorySize, Y_SMEM_BYTES);

    // 0. convert GEMM operands to fp16
    tohalf_kernel<<<(D_IN_PROJ * DIM / 8 + 255) / 256, 256>>>(in_w, wA, D_IN_PROJ * DIM);
    tohalf_kernel<<<(SEQ * DIM / 8 + 255) / 256, 256>>>(x, xh, SEQ * DIM);
    tohalf_kernel<<<(DIM * DIM_INNER / 8 + 255) / 256, 256>>>(out_w, wB, DIM * DIM_INNER);

    // 1. in_proj (fp16 mma, R11 config)
    {
        dim3 grid((D_IN_PROJ + TBN - 1) / TBN, SEQ / TBM);
        h16_gemm<<<grid, 128, GEMM_SMEM>>>(xh, wA, zx, SEQ, D_IN_PROJ, DIM);
    }
    // 2. dt / dA
    dt_kernel<<<(SEQ * NHEADS + 255) / 256, 256>>>(dt_bias, A_log);
    // 3. conv + silu + split (4 channels/thread)
    conv_kernel<<<(SEQ * CONV_DIM / 4 + 255) / 256, 256>>>(conv_w, conv_b);
    // 4. cumsum per (chunk, head)
    cumsum_kernel<<<NCHUNK * NHEADS, CHUNK>>>();
    // 5. chunk states (fp16 mma)
    states_kernel<<<NCHUNK * NHEADS, 256>>>();
    // 6. inter-chunk recurrence
    sprev_kernel<<<(NHEADS * HEADDIM * D_STATE + 255) / 256, 256>>>();
    // 7. Y via fp16 mma
    {
        dim3 grid(2, NHEADS, NCHUNK);
        y_mma_kernel<<<grid, 256, Y_SMEM_BYTES>>>(Dparam);
    }
    // 8. gated RMSNorm
    norm_kernel<<<SEQ, 256>>>(norm_w);
    // 9. out_proj
    {
        dim3 grid(DIM / TBN, SEQ / TBM);
        h16_gemm<<<grid, 128, GEMM_SMEM>>>(yh, wB, out, SEQ, DIM, DIM_INNER);
    }
}

// round 14
// speedup vs baseline: 1.4354x; 1.0759x over previous
#include <cuda_runtime.h>
#include <cuda_fp16.h>
#include <math.h>
#include <stdint.h>

// ---------------- problem constants ----------------
#define SEQ        2048
#define DIM        2048
#define DIM_INNER  4096
#define D_STATE    64
#define D_CONV     4
#define HEADDIM    128
#define NHEADS     32
#define CHUNK      256
#define NCHUNK     (SEQ / CHUNK)          // 8
#define CONV_DIM   (DIM_INNER + 2 * D_STATE)      // 4224
#define D_IN_PROJ  (2 * DIM_INNER + 2 * D_STATE + NHEADS)  // 8352

// ---------------- scratch (device globals; no allocation allowed) -------------
__device__ __align__(128) float g_zxbcdt[SEQ * D_IN_PROJ];
__device__ float g_dt   [SEQ * NHEADS];
__device__ __align__(128) __half g_xsh [SEQ * DIM_INNER];
__device__ __align__(128) float g_xdt  [SEQ * DIM_INNER];
__device__ float g_B    [SEQ * D_STATE];
__device__ float g_C    [SEQ * D_STATE];
__device__ float g_Acs  [NCHUNK * NHEADS * CHUNK];
__device__ float g_Alast[NCHUNK * NHEADS];
__device__ float g_states[NCHUNK * NHEADS * HEADDIM * D_STATE];
__device__ float g_sprev [NCHUNK * NHEADS * HEADDIM * D_STATE];
__device__ __align__(128) float g_y    [SEQ * DIM_INNER];
// fp16 GEMM operands
__device__ __align__(128) __half g_wA [D_IN_PROJ * DIM];
__device__ __align__(128) __half g_wB [DIM * DIM_INNER];
__device__ __align__(128) __half g_xh [SEQ * DIM];
__device__ __align__(128) __half g_yh [SEQ * DIM_INNER];

__device__ __forceinline__ float siluf(float v) { return v / (1.0f + expf(-v)); }
__device__ __forceinline__ float softplusf(float v) { return (v > 20.0f) ? v : log1pf(expf(v)); }

// ---------------- fp32 -> fp16 conversion pass ----------------
__global__ void tohalf_kernel(const float* __restrict__ in, __half* __restrict__ out, int n) {
    int i = (blockIdx.x * blockDim.x + threadIdx.x) * 8;
    if (i >= n) return;
    float4 a = *(const float4*)(in + i);
    float4 b = *(const float4*)(in + i + 4);
    __half2 h0 = __floats2half2_rn(a.x, a.y);
    __half2 h1 = __floats2half2_rn(a.z, a.w);
    __half2 h2 = __floats2half2_rn(b.x, b.y);
    __half2 h3 = __floats2half2_rn(b.z, b.w);
    uint4 o;
    o.x = *(uint32_t*)&h0; o.y = *(uint32_t*)&h1;
    o.z = *(uint32_t*)&h2; o.w = *(uint32_t*)&h3;
    *(uint4*)(out + i) = o;
}

#define MMA_F16(acc, a, b) \
    asm volatile( \
        "mma.sync.aligned.m16n8k16.row.col.f32.f16.f16.f32 " \
        "{%0,%1,%2,%3}, {%4,%5,%6,%7}, {%8,%9}, {%0,%1,%2,%3};" \
        : "+f"((acc)[0]), "+f"((acc)[1]), "+f"((acc)[2]), "+f"((acc)[3]) \
        : "r"((a)[0]), "r"((a)[1]), "r"((a)[2]), "r"((a)[3]), \
          "r"((b)[0]), "r"((b)[1]))

#define LDSM_X4(r0, r1, r2, r3, addr) \
    asm volatile("ldmatrix.sync.aligned.m8n8.x4.shared.b16 {%0,%1,%2,%3}, [%4];" \
        : "=r"(r0), "=r"(r1), "=r"(r2), "=r"(r3) : "r"(addr))

// ==== fp16 mma.sync GEMM (R11-proven config, FROZEN) ====
#define TBM   128
#define TBN   128
#define TBK   32
#define NSTG  4
#define ROWPH 40
#define STGH  (TBM * ROWPH)
#define GEMM_SMEM (2 * NSTG * STGH * 2)  // 81920 bytes

__global__ void __launch_bounds__(128, 2)
h16_gemm(const __half* __restrict__ A, const __half* __restrict__ B,
         float* __restrict__ C, int M, int N, int K) {
    extern __shared__ __half sm[];

    const int tid  = threadIdx.x;
    const int lane = tid & 31;
    const int warp = tid >> 5;
    const int m0   = blockIdx.y * TBM;
    const int n0   = blockIdx.x * TBN;
    const int wm   = (warp >> 1) * 64;
    const int wn   = (warp & 1) * 64;
    const int lr   = lane >> 2;
    const int lc   = lane & 3;
    const int ktiles = K / TBK;

    const int lrow = tid >> 2;
    const int lch  = (tid & 3) * 8;

    const int rowin  = lane & 7;
    const int a_row  = ((lane >> 3) & 1) * 8 + rowin;
    const int a_koff = ((lane >> 4) & 1) * 8;
    const int b_row  = ((lane >> 4) & 1) * 8 + rowin;
    const int b_koff = ((lane >> 3) & 1) * 8;

    uint32_t a_s0, b_s0;
    {
        uint32_t base;
        asm("{ .reg .u64 t; cvta.to.shared.u64 t, %1; cvt.u32.u64 %0, t; }"
            : "=r"(base) : "l"(sm));
        a_s0 = base;
        b_s0 = base + NSTG * STGH * 2;
    }

    auto issue = [&](int kt, int st) {
        const __half* Ag = A + (long)m0 * K + kt * TBK;
        const __half* Bg = B + (long)n0 * K + kt * TBK;
        uint32_t abase = a_s0 + st * STGH * 2;
        uint32_t bbase = b_s0 + st * STGH * 2;
#pragma unroll
        for (int i = 0; i < 4; i++) {
            int r = lrow + i * 32;
            uint32_t doff = r * ROWPH * 2 + lch * 2;
            asm volatile("cp.async.cg.shared.global [%0], [%1], 16;"
                         :: "r"(abase + doff), "l"(Ag + (long)r * K + lch) : "memory");
            int sz = (n0 + r < N) ? 16 : 0;
            asm volatile("cp.async.cg.shared.global [%0], [%1], 16, %2;"
                         :: "r"(bbase + doff), "l"(Bg + (long)r * K + lch), "r"(sz) : "memory");
        }
        asm volatile("cp.async.commit_group;" ::: "memory");
    };

#pragma unroll
    for (int st = 0; st < NSTG - 1; st++) issue(st, st);

    float acc[4][8][4];
#pragma unroll
    for (int i = 0; i < 4; i++)
#pragma unroll
        for (int j = 0; j < 8; j++)
#pragma unroll
            for (int r = 0; r < 4; r++) acc[i][j][r] = 0.0f;

    for (int kt = 0; kt < ktiles; kt++) {
        int s = kt % NSTG;
        asm volatile("cp.async.wait_group %0;" :: "n"(NSTG - 2));
        __syncthreads();
        int nt = kt + NSTG - 1;
        if (nt < ktiles) issue(nt, nt % NSTG);
        else asm volatile("cp.async.commit_group;" ::: "memory");

        uint32_t abase = a_s0 + s * STGH * 2;
        uint32_t bbase = b_s0 + s * STGH * 2;
#pragma unroll
        for (int kk = 0; kk < 2; kk++) {
            int kb = kk * 16;
            uint32_t afr[4][4], bfr[8][2];
#pragma unroll
            for (int mi = 0; mi < 4; mi++) {
                uint32_t addr = abase + (((wm + mi * 16 + a_row) * ROWPH) + kb + a_koff) * 2;
                LDSM_X4(afr[mi][0], afr[mi][1], afr[mi][2], afr[mi][3], addr);
            }
#pragma unroll
            for (int nj = 0; nj < 4; nj++) {
                uint32_t addr = bbase + (((wn + nj * 16 + b_row) * ROWPH) + kb + b_koff) * 2;
                LDSM_X4(bfr[nj * 2][0], bfr[nj * 2][1],
                        bfr[nj * 2 + 1][0], bfr[nj * 2 + 1][1], addr);
            }
#pragma unroll
            for (int mi = 0; mi < 4; mi++)
#pragma unroll
                for (int ni = 0; ni < 8; ni++)
                    MMA_F16(acc[mi][ni], afr[mi], bfr[ni]);
        }
    }

#pragma unroll
    for (int mi = 0; mi < 4; mi++) {
        int r0 = m0 + wm + mi * 16 + lr;
#pragma unroll
        for (int ni = 0; ni < 8; ni++) {
            int ccol = n0 + wn + ni * 8 + lc * 2;
            if (ccol < N) {
                float* p0 = C + (long)r0 * N + ccol;
                float* p1 = C + (long)(r0 + 8) * N + ccol;
                p0[0] = acc[mi][ni][0];
                p0[1] = acc[mi][ni][1];
                p1[0] = acc[mi][ni][2];
                p1[1] = acc[mi][ni][3];
            }
        }
    }
}

// ---------------- causal depthwise conv + SiLU + split (4-wide) ----------------
__global__ void conv_kernel(const float* __restrict__ conv_w,
                            const float* __restrict__ conv_b) {
    int idx = (blockIdx.x * blockDim.x + threadIdx.x) * 4;
    if (idx >= SEQ * CONV_DIM) return;
    int l = idx / CONV_DIM, ch = idx % CONV_DIM;

    float4 wv[4];
#pragma unroll
    for (int j = 0; j < 4; j++)
        wv[j] = *(const float4*)&conv_w[(ch + j) * D_CONV];

    float4 acc = *(const float4*)&conv_b[ch];
#pragma unroll
    for (int k = 0; k < D_CONV; k++) {
        int ls = l - (D_CONV - 1) + k;
        if (ls >= 0) {
            float4 v = *(const float4*)&g_zxbcdt[ls * D_IN_PROJ + DIM_INNER + ch];
            acc.x += v.x * ((const float*)&wv[0])[k];
            acc.y += v.y * ((const float*)&wv[1])[k];
            acc.z += v.z * ((const float*)&wv[2])[k];
            acc.w += v.w * ((const float*)&wv[3])[k];
        }
    }
    acc.x = siluf(acc.x); acc.y = siluf(acc.y);
    acc.z = siluf(acc.z); acc.w = siluf(acc.w);

    if (ch < DIM_INNER) {
        int h = ch >> 7;
        float dtv = g_dt[l * NHEADS + h];
        __half2 h0 = __floats2half2_rn(acc.x, acc.y);
        __half2 h1 = __floats2half2_rn(acc.z, acc.w);
        *(uint32_t*)&g_xsh[l * DIM_INNER + ch]     = *(uint32_t*)&h0;
        *(uint32_t*)&g_xsh[l * DIM_INNER + ch + 2] = *(uint32_t*)&h1;
        float4 xd = make_float4(acc.x * dtv, acc.y * dtv, acc.z * dtv, acc.w * dtv);
        *(float4*)&g_xdt[l * DIM_INNER + ch] = xd;
    } else if (ch < DIM_INNER + D_STATE) {
        *(float4*)&g_B[l * D_STATE + (ch - DIM_INNER)] = acc;
    } else {
        *(float4*)&g_C[l * D_STATE + (ch - DIM_INNER - D_STATE)] = acc;
    }
}

// ------- fused dt + per-(chunk,head) inclusive cumsum of dA -------
__global__ void cumsum_dt_kernel(const float* __restrict__ dt_bias,
                                 const float* __restrict__ A_log) {
    int ch = blockIdx.x;
    int c = ch / NHEADS, h = ch % NHEADS;
    int t = threadIdx.x;
    int l = c * CHUNK + t;
    __shared__ float s[CHUNK];
    float v = g_zxbcdt[l * D_IN_PROJ + (D_IN_PROJ - NHEADS) + h] + dt_bias[h];
    float sp = softplusf(v);
    g_dt[l * NHEADS + h] = sp;
    s[t] = -expf(A_log[h]) * sp;
    __syncthreads();
    for (int off = 1; off < CHUNK; off <<= 1) {
        float add = (t >= off) ? s[t - off] : 0.0f;
        __syncthreads();
        s[t] += add;
        __syncthreads();
    }
    g_Acs[ch * CHUNK + t] = s[t];
    if (t == CHUNK - 1) g_Alast[ch] = s[t];
}

// ---------------- chunk states via fp16 mma (hi/lo, R13-proven) ----------------
#define SROW 72
__global__ void __launch_bounds__(256)
states_kernel() {
    __shared__ __half Ah[128 * SROW];
    __shared__ __half Al[128 * SROW];
    __shared__ __half Bs[64 * SROW];
    __shared__ float dec[64];

    int chd = blockIdx.x;
    int c = chd / NHEADS, h = chd % NHEADS;
    int tid  = threadIdx.x;
    int lane = tid & 31;
    int warp = tid >> 5;
    int lr = lane >> 2, lc = lane & 3;
    int wm = (warp >> 1) * 32;
    int wn = (warp & 1) * 32;

    float Alast = g_Alast[chd];

    float acc[2][4][4];
#pragma unroll
    for (int i = 0; i < 2; i++)
#pragma unroll
        for (int j = 0; j < 4; j++)
#pragma unroll
            for (int r = 0; r < 4; r++) acc[i][j][r] = 0.0f;

    for (int kt = 0; kt < 4; kt++) {
        int l0 = kt * 64;
        if (tid < 64) dec[tid] = expf(Alast - g_Acs[chd * CHUNK + l0 + tid]);
        __syncthreads();
        {
            int p = tid & 127, l2 = tid >> 7;
#pragma unroll
            for (int i = 0; i < 32; i++) {
                int l = l2 + i * 2;
                float v = g_xdt[(c * CHUNK + l0 + l) * DIM_INNER + h * HEADDIM + p] * dec[l];
                __half hi = __float2half_rn(v);
                Ah[p * SROW + l] = hi;
                Al[p * SROW + l] = __float2half_rn(v - __half2float(hi));
            }
        }
        {
            int n = tid & 63, l4 = tid >> 6;
#pragma unroll
            for (int i = 0; i < 16; i++) {
                int l = l4 + i * 4;
                Bs[n * SROW + l] = __float2half_rn(g_B[(c * CHUNK + l0 + l) * D_STATE + n]);
            }
        }
        __syncthreads();

#pragma unroll
        for (int kk = 0; kk < 4; kk++) {
            int kb = kk * 16;
            uint32_t ah[2][4], al[2][4], bf[4][2];
#pragma unroll
            for (int mi = 0; mi < 2; mi++) {
                int mb = wm + mi * 16 + lr;
                ah[mi][0] = *(const uint32_t*)&Ah[(mb    ) * SROW + kb + lc * 2];
                ah[mi][1] = *(const uint32_t*)&Ah[(mb + 8) * SROW + kb + lc * 2];
                ah[mi][2] = *(const uint32_t*)&Ah[(mb    ) * SROW + kb + 8 + lc * 2];
                ah[mi][3] = *(const uint32_t*)&Ah[(mb + 8) * SROW + kb + 8 + lc * 2];
                al[mi][0] = *(const uint32_t*)&Al[(mb    ) * SROW + kb + lc * 2];
                al[mi][1] = *(const uint32_t*)&Al[(mb + 8) * SROW + kb + lc * 2];
                al[mi][2] = *(const uint32_t*)&Al[(mb    ) * SROW + kb + 8 + lc * 2];
                al[mi][3] = *(const uint32_t*)&Al[(mb + 8) * SROW + kb + 8 + lc * 2];
            }
#pragma unroll
            for (int ni = 0; ni < 4; ni++) {
                int nb = wn + ni * 8 + lr;
                bf[ni][0] = *(const uint32_t*)&Bs[nb * SROW + kb + lc * 2];
                bf[ni][1] = *(const uint32_t*)&Bs[nb * SROW + kb + 8 + lc * 2];
            }
#pragma unroll
            for (int mi = 0; mi < 2; mi++)
#pragma unroll
                for (int ni = 0; ni < 4; ni++) {
                    MMA_F16(acc[mi][ni], ah[mi], bf[ni]);
                    MMA_F16(acc[mi][ni], al[mi], bf[ni]);
                }
        }
        __syncthreads();
    }

#pragma unroll
    for (int mi = 0; mi < 2; mi++) {
        int p0 = wm + mi * 16 + lr;
#pragma unroll
        for (int ni = 0; ni < 4; ni++) {
            int n = wn + ni * 8 + lc * 2;
            float* s0 = &g_states[chd * (HEADDIM * D_STATE) + p0 * D_STATE + n];
            float* s1 = s0 + 8 * D_STATE;
            s0[0] = acc[mi][ni][0]; s0[1] = acc[mi][ni][1];
            s1[0] = acc[mi][ni][2]; s1[1] = acc[mi][ni][3];
        }
    }
}

// ---------------- inter-chunk recurrence ----------------
__global__ void sprev_kernel() {
    int idx = blockIdx.x * blockDim.x + threadIdx.x;
    if (idx >= NHEADS * HEADDIM * D_STATE) return;
    int h = idx / (HEADDIM * D_STATE);
    int r = idx % (HEADDIM * D_STATE);
    float S = 0.0f;
    for (int c = 0; c < NCHUNK; c++) {
        int ch = c * NHEADS + h;
        g_sprev[ch * (HEADDIM * D_STATE) + r] = S;
        S = expf(g_Alast[ch]) * S + g_states[ch * (HEADDIM * D_STATE) + r];
    }
}

// ================ fused SSD Y kernel (fp16 mma; single-precision X) ============
#define YROW 72
#define O_CH   0
#define O_BS   (O_CH + 128 * YROW)
#define O_GS   (O_BS + 64 * YROW)
#define O_XH   (O_GS + 128 * YROW)
#define O_SS   (O_XH + 128 * YROW)
#define O_END  (O_SS + 128 * YROW)
#define Y_SMEM_BYTES (O_END * 2 + (128 + 128 + 64) * 4)   // ~83.5 KB

__global__ void __launch_bounds__(256, 2)
y_mma_kernel(const float* __restrict__ Dparam) {
    extern __shared__ __half ysm[];
    __half* Ch  = ysm + O_CH;
    __half* Bsm = ysm + O_BS;
    __half* Gsm = ysm + O_GS;
    __half* Xh  = ysm + O_XH;
    __half* Ssm = ysm + O_SS;
    float* acsl  = (float*)(ysm + O_END);
    float* expAl = acsl + 128;
    float* acss  = expAl + 128;

    const int hh = blockIdx.y, c = blockIdx.z;
    const int lh = blockIdx.x;
    const int l0 = lh * 128;
    const int ch = c * NHEADS + hh;
    const int tid  = threadIdx.x;
    const int lane = tid & 31;
    const int warp = tid >> 5;
    const int lr   = lane >> 2;
    const int lc   = lane & 3;
    const int wmY = (warp >> 1) * 32;
    const int wnY = (warp & 1) * 64;
    const int wmG = (warp >> 1) * 32;
    const int wnG = (warp & 1) * 32;

    {
        int n = tid & 63, r4 = tid >> 6;
#pragma unroll
        for (int i = 0; i < 32; i++) {
            int l = r4 + i * 4;
            Ch[l * YROW + n]  = __float2half_rn(g_C[(c * CHUNK + l0 + l) * D_STATE + n]);
            Ssm[l * YROW + n] = __float2half_rn(g_sprev[ch * (HEADDIM * D_STATE) + l * D_STATE + n]);
        }
        if (tid < 128) {
            float a = g_Acs[ch * CHUNK + l0 + tid];
            acsl[tid] = a;
            expAl[tid] = expf(a);
        }
    }
    __syncthreads();

    float acc[2][8][4];
#pragma unroll
    for (int i = 0; i < 2; i++)
#pragma unroll
        for (int j = 0; j < 8; j++)
#pragma unroll
            for (int r = 0; r < 4; r++) acc[i][j][r] = 0.0f;

    // ---- Y_off: C @ Sprev^T (K = 64) ----
#pragma unroll
    for (int kk = 0; kk < 4; kk++) {
        int kb = kk * 16;
        uint32_t afr[2][4], bfr[8][2];
#pragma unroll
        for (int mi = 0; mi < 2; mi++) {
            int mb = wmY + mi * 16 + lr;
            afr[mi][0] = *(const uint32_t*)&Ch[(mb    ) * YROW + kb + lc * 2];
            afr[mi][1] = *(const uint32_t*)&Ch[(mb + 8) * YROW + kb + lc * 2];
            afr[mi][2] = *(const uint32_t*)&Ch[(mb    ) * YROW + kb + 8 + lc * 2];
            afr[mi][3] = *(const uint32_t*)&Ch[(mb + 8) * YROW + kb + 8 + lc * 2];
        }
#pragma unroll
        for (int ni = 0; ni < 8; ni++) {
            int nb = wnY + ni * 8 + lr;
            bfr[ni][0] = *(const uint32_t*)&Ssm[nb * YROW + kb + lc * 2];
            bfr[ni][1] = *(const uint32_t*)&Ssm[nb * YROW + kb + 8 + lc * 2];
        }
#pragma unroll
        for (int mi = 0; mi < 2; mi++)
#pragma unroll
            for (int ni = 0; ni < 8; ni++)
                MMA_F16(acc[mi][ni], afr[mi], bfr[ni]);
    }
#pragma unroll
    for (int mi = 0; mi < 2; mi++) {
        int r0 = wmY + mi * 16 + lr;
        float e0 = expAl[r0], e1 = expAl[r0 + 8];
#pragma unroll
        for (int ni = 0; ni < 8; ni++) {
            acc[mi][ni][0] *= e0; acc[mi][ni][1] *= e0;
            acc[mi][ni][2] *= e1; acc[mi][ni][3] *= e1;
        }
    }

    // ---- Y_diag: s-tiles of 64 ----
    const int nst = 2 * (lh + 1);
    for (int st = 0; st < nst; st++) {
        {
            int n = tid & 63, s4 = tid >> 6;
#pragma unroll
            for (int i = 0; i < 16; i++) {
                int s = s4 + i * 4;
                Bsm[s * YROW + n] = __float2half_rn(g_B[(c * CHUNK + st * 64 + s) * D_STATE + n]);
            }
            if (tid < 64) acss[tid] = g_Acs[ch * CHUNK + st * 64 + tid];
            int p = tid & 127, s2 = tid >> 7;
#pragma unroll
            for (int i = 0; i < 32; i++) {
                int s = s2 + i * 2;
                float v = g_xdt[(c * CHUNK + st * 64 + s) * DIM_INNER + hh * HEADDIM + p];
                Xh[p * YROW + s] = __float2half_rn(v);
            }
        }
        __syncthreads();

        float gacc[2][4][4];
#pragma unroll
        for (int i = 0; i < 2; i++)
#pragma unroll
            for (int j = 0; j < 4; j++)
#pragma unroll
                for (int r = 0; r < 4; r++) gacc[i][j][r] = 0.0f;
#pragma unroll
        for (int kk = 0; kk < 4; kk++) {
            int kb = kk * 16;
            uint32_t afr[2][4], bfr[4][2];
#pragma unroll
            for (int mi = 0; mi < 2; mi++) {
                int mb = wmG + mi * 16 + lr;
                afr[mi][0] = *(const uint32_t*)&Ch[(mb    ) * YROW + kb + lc * 2];
                afr[mi][1] = *(const uint32_t*)&Ch[(mb + 8) * YROW + kb + lc * 2];
                afr[mi][2] = *(const uint32_t*)&Ch[(mb    ) * YROW + kb + 8 + lc * 2];
                afr[mi][3] = *(const uint32_t*)&Ch[(mb + 8) * YROW + kb + 8 + lc * 2];
            }
#pragma unroll
            for (int ni = 0; ni < 4; ni++) {
                int nb = wnG + ni * 8 + lr;
                bfr[ni][0] = *(const uint32_t*)&Bsm[nb * YROW + kb + lc * 2];
                bfr[ni][1] = *(const uint32_t*)&Bsm[nb * YROW + kb + 8 + lc * 2];
            }
#pragma unroll
            for (int mi = 0; mi < 2; mi++)
#pragma unroll
                for (int ni = 0; ni < 4; ni++)
                    MMA_F16(gacc[mi][ni], afr[mi], bfr[ni]);
        }

        const int sbase = st * 64;
#pragma unroll
        for (int mi = 0; mi < 2; mi++) {
            int r0 = wmG + mi * 16 + lr;
            float a0 = acsl[r0], a1 = acsl[r0 + 8];
            int lg0 = l0 + r0, lg1 = lg0 + 8;
#pragma unroll
            for (int ni = 0; ni < 4; ni++) {
                int cl = wnG + ni * 8 + lc * 2;
                float as0 = acss[cl], as1 = acss[cl + 1];
                int sg0 = sbase + cl, sg1 = sg0 + 1;
                float g00 = (sg0 <= lg0) ? gacc[mi][ni][0] * expf(a0 - as0) : 0.0f;
                float g01 = (sg1 <= lg0) ? gacc[mi][ni][1] * expf(a0 - as1) : 0.0f;
                float g10 = (sg0 <= lg1) ? gacc[mi][ni][2] * expf(a1 - as0) : 0.0f;
                float g11 = (sg1 <= lg1) ? gacc[mi][ni][3] * expf(a1 - as1) : 0.0f;
                Gsm[(r0    ) * YROW + cl    ] = __float2half_rn(g00);
                Gsm[(r0    ) * YROW + cl + 1] = __float2half_rn(g01);
                Gsm[(r0 + 8) * YROW + cl    ] = __float2half_rn(g10);
                Gsm[(r0 + 8) * YROW + cl + 1] = __float2half_rn(g11);
            }
        }
        __syncthreads();

#pragma unroll
        for (int kk = 0; kk < 4; kk++) {
            int kb = kk * 16;
            uint32_t afr[2][4], bh[8][2];
#pragma unroll
            for (int mi = 0; mi < 2; mi++) {
                int mb = wmY + mi * 16 + lr;
                afr[mi][0] = *(const uint32_t*)&Gsm[(mb    ) * YROW + kb + lc * 2];
                afr[mi][1] = *(const uint32_t*)&Gsm[(mb + 8) * YROW + kb + lc * 2];
                afr[mi][2] = *(const uint32_t*)&Gsm[(mb    ) * YROW + kb + 8 + lc * 2];
                afr[mi][3] = *(const uint32_t*)&Gsm[(mb + 8) * YROW + kb + 8 + lc * 2];
            }
#pragma unroll
            for (int ni = 0; ni < 8; ni++) {
                int nb = wnY + ni * 8 + lr;
                bh[ni][0] = *(const uint32_t*)&Xh[nb * YROW + kb + lc * 2];
                bh[ni][1] = *(const uint32_t*)&Xh[nb * YROW + kb + 8 + lc * 2];
            }
#pragma unroll
            for (int mi = 0; mi < 2; mi++)
#pragma unroll
                for (int ni = 0; ni < 8; ni++)
                    MMA_F16(acc[mi][ni], afr[mi], bh[ni]);
        }
        __syncthreads();
    }

    float Dh = Dparam[hh];
#pragma unroll
    for (int mi = 0; mi < 2; mi++) {
        int r0 = wmY + mi * 16 + lr;
#pragma unroll
        for (int ni = 0; ni < 8; ni++) {
            int col = wnY + ni * 8 + lc * 2;
            long o0 = (long)(c * CHUNK + l0 + r0) * DIM_INNER + hh * HEADDIM + col;
            long o1 = o0 + 8L * DIM_INNER;
            g_y[o0]     = acc[mi][ni][0] + __half2float(g_xsh[o0]) * Dh;
            g_y[o0 + 1] = acc[mi][ni][1] + __half2float(g_xsh[o0 + 1]) * Dh;
            g_y[o1]     = acc[mi][ni][2] + __half2float(g_xsh[o1]) * Dh;
            g_y[o1 + 1] = acc[mi][ni][3] + __half2float(g_xsh[o1 + 1]) * Dh;
        }
    }
}

// ---------------- gated RMSNorm (writes fp16 for out_proj) ----------------
__global__ void __launch_bounds__(256)
norm_kernel(const float* __restrict__ norm_w) {
    int l = blockIdx.x;
    int t = threadIdx.x;
    float vals[16];
    float ss = 0.0f;
#pragma unroll
    for (int r = 0; r < 16; r++) {
        int j = t + r * 256;
        float yv = g_y[l * DIM_INNER + j];
        float zv = g_zxbcdt[l * D_IN_PROJ + j];
        float gv = yv * siluf(zv);
        vals[r] = gv;
        ss += gv * gv;
    }
    __shared__ float red[8];
#pragma unroll
    for (int off = 16; off > 0; off >>= 1)
        ss += __shfl_down_sync(0xffffffffu, ss, off);
    if ((t & 31) == 0) red[t >> 5] = ss;
    __syncthreads();
    float total;
    {
        float v = (t < 8) ? red[t] : 0.0f;
#pragma unroll
        for (int off = 4; off > 0; off >>= 1)
            v += __shfl_down_sync(0xffffffffu, v, off);
        if (t == 0) red[0] = v;
    }
    __syncthreads();
    total = red[0];
    float scale = rsqrtf(total / (float)DIM_INNER + 1e-5f);
#pragma unroll
    for (int r = 0; r < 16; r++) {
        int j = t + r * 256;
        g_yh[l * DIM_INNER + j] = __float2half_rn(vals[r] * scale * norm_w[j]);
    }
}

// ---------------- host launcher ----------------
extern "C" void kernel_launch(void* const* d_in, const int* in_sizes, int n_in,
                              void* d_out, int out_size) {
    const float* x        = (const float*)d_in[0];
    const float* in_w     = (const float*)d_in[1];
    const float* conv_w   = (const float*)d_in[2];
    const float* conv_b   = (const float*)d_in[3];
    const float* dt_bias  = (const float*)d_in[4];
    const float* A_log    = (const float*)d_in[5];
    const float* Dparam   = (const float*)d_in[6];
    const float* norm_w   = (const float*)d_in[7];
    const float* out_w    = (const float*)d_in[8];
    float* out            = (float*)d_out;

    float*  zx;  cudaGetSymbolAddress((void**)&zx,  g_zxbcdt);
    __half* wA;  cudaGetSymbolAddress((void**)&wA,  g_wA);
    __half* wB;  cudaGetSymbolAddress((void**)&wB,  g_wB);
    __half* xh;  cudaGetSymbolAddress((void**)&xh,  g_xh);
    __half* yh;  cudaGetSymbolAddress((void**)&yh,  g_yh);

    cudaFuncSetAttribute(h16_gemm, cudaFuncAttributeMaxDynamicSharedMemorySize, GEMM_SMEM);
    cudaFuncSetAttribute(y_mma_kernel, cudaFuncAttributeMaxDynamicSharedMemorySize, Y_SMEM_BYTES);

    // 0. convert GEMM operands to fp16
    tohalf_kernel<<<(D_IN_PROJ * DIM / 8 + 255) / 256, 256>>>(in_w, wA, D_IN_PROJ * DIM);
    tohalf_kernel<<<(SEQ * DIM / 8 + 255) / 256, 256>>>(x, xh, SEQ * DIM);
    tohalf_kernel<<<(DIM * DIM_INNER / 8 + 255) / 256, 256>>>(out_w, wB, DIM * DIM_INNER);

    // 1. in_proj (fp16 mma, R11 config)
    {
        dim3 grid((D_IN_PROJ + TBN - 1) / TBN, SEQ / TBM);
        h16_gemm<<<grid, 128, GEMM_SMEM>>>(xh, wA, zx, SEQ, D_IN_PROJ, DIM);
    }
    // 2. fused dt + cumsum per (chunk, head)
    cumsum_dt_kernel<<<NCHUNK * NHEADS, CHUNK>>>(dt_bias, A_log);
    // 3. conv + silu + split (4 channels/thread)
    conv_kernel<<<(SEQ * CONV_DIM / 4 + 255) / 256, 256>>>(conv_w, conv_b);
    // 4. chunk states (fp16 mma)
    states_kernel<<<NCHUNK * NHEADS, 256>>>();
    // 5. inter-chunk recurrence
    sprev_kernel<<<(NHEADS * HEADDIM * D_STATE + 255) / 256, 256>>>();
    // 6. Y via fp16 mma (2 CTAs/SM)
    {
        dim3 grid(2, NHEADS, NCHUNK);
        y_mma_kernel<<<grid, 256, Y_SMEM_BYTES>>>(Dparam);
    }
    // 7. gated RMSNorm
    norm_kernel<<<SEQ, 256>>>(norm_w);
    // 8. out_proj
    {
        dim3 grid(DIM / TBN, SEQ / TBM);
        h16_gemm<<<grid, 128, GEMM_SMEM>>>(yh, wB, out, SEQ, DIM, DIM_INNER);
    }
}

// round 15
// speedup vs baseline: 1.4860x; 1.0352x over previous
#include <cuda_runtime.h>
#include <cuda_fp16.h>
#include <math.h>
#include <stdint.h>

// ---------------- problem constants ----------------
#define SEQ        2048
#define DIM        2048
#define DIM_INNER  4096
#define D_STATE    64
#define D_CONV     4
#define HEADDIM    128
#define NHEADS     32
#define CHUNK      256
#define NCHUNK     (SEQ / CHUNK)          // 8
#define CONV_DIM   (DIM_INNER + 2 * D_STATE)      // 4224
#define D_IN_PROJ  (2 * DIM_INNER + 2 * D_STATE + NHEADS)  // 8352

// ---------------- scratch (device globals; no allocation allowed) -------------
__device__ __align__(128) __half g_zxh [SEQ * D_IN_PROJ];   // in_proj out (fp16)
__device__ float g_dt   [SEQ * NHEADS];
__device__ __align__(128) __half g_xsh [SEQ * DIM_INNER];
__device__ __align__(128) float g_xdt  [SEQ * DIM_INNER];
__device__ float g_B    [SEQ * D_STATE];
__device__ float g_C    [SEQ * D_STATE];
__device__ float g_Acs  [NCHUNK * NHEADS * CHUNK];
__device__ float g_Alast[NCHUNK * NHEADS];
__device__ float g_states[NCHUNK * NHEADS * HEADDIM * D_STATE];
__device__ float g_sprev [NCHUNK * NHEADS * HEADDIM * D_STATE];
__device__ __align__(128) float g_y    [SEQ * DIM_INNER];
// fp16 GEMM operands
__device__ __align__(128) __half g_wA [D_IN_PROJ * DIM];
__device__ __align__(128) __half g_wB [DIM * DIM_INNER];
__device__ __align__(128) __half g_xh [SEQ * DIM];
__device__ __align__(128) __half g_yh [SEQ * DIM_INNER];

__device__ __forceinline__ float siluf(float v) { return v / (1.0f + expf(-v)); }
__device__ __forceinline__ float softplusf(float v) { return (v > 20.0f) ? v : log1pf(expf(v)); }

// ---------------- fp32 -> fp16 conversion pass ----------------
__global__ void tohalf_kernel(const float* __restrict__ in, __half* __restrict__ out, int n) {
    int i = (blockIdx.x * blockDim.x + threadIdx.x) * 8;
    if (i >= n) return;
    float4 a = *(const float4*)(in + i);
    float4 b = *(const float4*)(in + i + 4);
    __half2 h0 = __floats2half2_rn(a.x, a.y);
    __half2 h1 = __floats2half2_rn(a.z, a.w);
    __half2 h2 = __floats2half2_rn(b.x, b.y);
    __half2 h3 = __floats2half2_rn(b.z, b.w);
    uint4 o;
    o.x = *(uint32_t*)&h0; o.y = *(uint32_t*)&h1;
    o.z = *(uint32_t*)&h2; o.w = *(uint32_t*)&h3;
    *(uint4*)(out + i) = o;
}

#define MMA_F16(acc, a, b) \
    asm volatile( \
        "mma.sync.aligned.m16n8k16.row.col.f32.f16.f16.f32 " \
        "{%0,%1,%2,%3}, {%4,%5,%6,%7}, {%8,%9}, {%0,%1,%2,%3};" \
        : "+f"((acc)[0]), "+f"((acc)[1]), "+f"((acc)[2]), "+f"((acc)[3]) \
        : "r"((a)[0]), "r"((a)[1]), "r"((a)[2]), "r"((a)[3]), \
          "r"((b)[0]), "r"((b)[1]))

#define LDSM_X4(r0, r1, r2, r3, addr) \
    asm volatile("ldmatrix.sync.aligned.m8n8.x4.shared.b16 {%0,%1,%2,%3}, [%4];" \
        : "=r"(r0), "=r"(r1), "=r"(r2), "=r"(r3) : "r"(addr))

// ==== fp16 mma.sync GEMM (R11-proven config, FROZEN); OUT_HALF selects epilogue
#define TBM   128
#define TBN   128
#define TBK   32
#define NSTG  4
#define ROWPH 40
#define STGH  (TBM * ROWPH)
#define GEMM_SMEM (2 * NSTG * STGH * 2)  // 81920 bytes

template <int OUT_HALF>
__global__ void __launch_bounds__(128, 2)
h16_gemm(const __half* __restrict__ A, const __half* __restrict__ B,
         void* __restrict__ Cout, int M, int N, int K) {
    extern __shared__ __half sm[];

    const int tid  = threadIdx.x;
    const int lane = tid & 31;
    const int warp = tid >> 5;
    const int m0   = blockIdx.y * TBM;
    const int n0   = blockIdx.x * TBN;
    const int wm   = (warp >> 1) * 64;
    const int wn   = (warp & 1) * 64;
    const int lr   = lane >> 2;
    const int lc   = lane & 3;
    const int ktiles = K / TBK;

    const int lrow = tid >> 2;
    const int lch  = (tid & 3) * 8;

    const int rowin  = lane & 7;
    const int a_row  = ((lane >> 3) & 1) * 8 + rowin;
    const int a_koff = ((lane >> 4) & 1) * 8;
    const int b_row  = ((lane >> 4) & 1) * 8 + rowin;
    const int b_koff = ((lane >> 3) & 1) * 8;

    uint32_t a_s0, b_s0;
    {
        uint32_t base;
        asm("{ .reg .u64 t; cvta.to.shared.u64 t, %1; cvt.u32.u64 %0, t; }"
            : "=r"(base) : "l"(sm));
        a_s0 = base;
        b_s0 = base + NSTG * STGH * 2;
    }

    auto issue = [&](int kt, int st) {
        const __half* Ag = A + (long)m0 * K + kt * TBK;
        const __half* Bg = B + (long)n0 * K + kt * TBK;
        uint32_t abase = a_s0 + st * STGH * 2;
        uint32_t bbase = b_s0 + st * STGH * 2;
#pragma unroll
        for (int i = 0; i < 4; i++) {
            int r = lrow + i * 32;
            uint32_t doff = r * ROWPH * 2 + lch * 2;
            asm volatile("cp.async.cg.shared.global [%0], [%1], 16;"
                         :: "r"(abase + doff), "l"(Ag + (long)r * K + lch) : "memory");
            int sz = (n0 + r < N) ? 16 : 0;
            asm volatile("cp.async.cg.shared.global [%0], [%1], 16, %2;"
                         :: "r"(bbase + doff), "l"(Bg + (long)r * K + lch), "r"(sz) : "memory");
        }
        asm volatile("cp.async.commit_group;" ::: "memory");
    };

#pragma unroll
    for (int st = 0; st < NSTG - 1; st++) issue(st, st);

    float acc[4][8][4];
#pragma unroll
    for (int i = 0; i < 4; i++)
#pragma unroll
        for (int j = 0; j < 8; j++)
#pragma unroll
            for (int r = 0; r < 4; r++) acc[i][j][r] = 0.0f;

    for (int kt = 0; kt < ktiles; kt++) {
        int s = kt % NSTG;
        asm volatile("cp.async.wait_group %0;" :: "n"(NSTG - 2));
        __syncthreads();
        int nt = kt + NSTG - 1;
        if (nt < ktiles) issue(nt, nt % NSTG);
        else asm volatile("cp.async.commit_group;" ::: "memory");

        uint32_t abase = a_s0 + s * STGH * 2;
        uint32_t bbase = b_s0 + s * STGH * 2;
#pragma unroll
        for (int kk = 0; kk < 2; kk++) {
            int kb = kk * 16;
            uint32_t afr[4][4], bfr[8][2];
#pragma unroll
            for (int mi = 0; mi < 4; mi++) {
                uint32_t addr = abase + (((wm + mi * 16 + a_row) * ROWPH) + kb + a_koff) * 2;
                LDSM_X4(afr[mi][0], afr[mi][1], afr[mi][2], afr[mi][3], addr);
            }
#pragma unroll
            for (int nj = 0; nj < 4; nj++) {
                uint32_t addr = bbase + (((wn + nj * 16 + b_row) * ROWPH) + kb + b_koff) * 2;
                LDSM_X4(bfr[nj * 2][0], bfr[nj * 2][1],
                        bfr[nj * 2 + 1][0], bfr[nj * 2 + 1][1], addr);
            }
#pragma unroll
            for (int mi = 0; mi < 4; mi++)
#pragma unroll
                for (int ni = 0; ni < 8; ni++)
                    MMA_F16(acc[mi][ni], afr[mi], bfr[ni]);
        }
    }

#pragma unroll
    for (int mi = 0; mi < 4; mi++) {
        int r0 = m0 + wm + mi * 16 + lr;
#pragma unroll
        for (int ni = 0; ni < 8; ni++) {
            int ccol = n0 + wn + ni * 8 + lc * 2;
            if (ccol < N) {
                if (OUT_HALF) {
                    __half* C = (__half*)Cout;
                    __half2 v0 = __floats2half2_rn(acc[mi][ni][0], acc[mi][ni][1]);
                    __half2 v1 = __floats2half2_rn(acc[mi][ni][2], acc[mi][ni][3]);
                    *(__half2*)(C + (long)r0 * N + ccol) = v0;
                    *(__half2*)(C + (long)(r0 + 8) * N + ccol) = v1;
                } else {
                    float* C = (float*)Cout;
                    float* p0 = C + (long)r0 * N + ccol;
                    float* p1 = C + (long)(r0 + 8) * N + ccol;
                    p0[0] = acc[mi][ni][0];
                    p0[1] = acc[mi][ni][1];
                    p1[0] = acc[mi][ni][2];
                    p1[1] = acc[mi][ni][3];
                }
            }
        }
    }
}

// ---------------- causal depthwise conv + SiLU + split (4-wide, fp16 src) ------
__global__ void conv_kernel(const float* __restrict__ conv_w,
                            const float* __restrict__ conv_b) {
    int idx = (blockIdx.x * blockDim.x + threadIdx.x) * 4;
    if (idx >= SEQ * CONV_DIM) return;
    int l = idx / CONV_DIM, ch = idx % CONV_DIM;

    float4 wv[4];
#pragma unroll
    for (int j = 0; j < 4; j++)
        wv[j] = *(const float4*)&conv_w[(ch + j) * D_CONV];

    float4 acc = *(const float4*)&conv_b[ch];
#pragma unroll
    for (int k = 0; k < D_CONV; k++) {
        int ls = l - (D_CONV - 1) + k;
        if (ls >= 0) {
            const __half2* src = (const __half2*)&g_zxh[ls * D_IN_PROJ + DIM_INNER + ch];
            float2 v01 = __half22float2(src[0]);
            float2 v23 = __half22float2(src[1]);
            acc.x += v01.x * ((const float*)&wv[0])[k];
            acc.y += v01.y * ((const float*)&wv[1])[k];
            acc.z += v23.x * ((const float*)&wv[2])[k];
            acc.w += v23.y * ((const float*)&wv[3])[k];
        }
    }
    acc.x = siluf(acc.x); acc.y = siluf(acc.y);
    acc.z = siluf(acc.z); acc.w = siluf(acc.w);

    if (ch < DIM_INNER) {
        int h = ch >> 7;
        float dtv = g_dt[l * NHEADS + h];
        __half2 h0 = __floats2half2_rn(acc.x, acc.y);
        __half2 h1 = __floats2half2_rn(acc.z, acc.w);
        *(uint32_t*)&g_xsh[l * DIM_INNER + ch]     = *(uint32_t*)&h0;
        *(uint32_t*)&g_xsh[l * DIM_INNER + ch + 2] = *(uint32_t*)&h1;
        float4 xd = make_float4(acc.x * dtv, acc.y * dtv, acc.z * dtv, acc.w * dtv);
        *(float4*)&g_xdt[l * DIM_INNER + ch] = xd;
    } else if (ch < DIM_INNER + D_STATE) {
        *(float4*)&g_B[l * D_STATE + (ch - DIM_INNER)] = acc;
    } else {
        *(float4*)&g_C[l * D_STATE + (ch - DIM_INNER - D_STATE)] = acc;
    }
}

// ------- fused dt + per-(chunk,head) inclusive cumsum of dA -------
__global__ void cumsum_dt_kernel(const float* __restrict__ dt_bias,
                                 const float* __restrict__ A_log) {
    int ch = blockIdx.x;
    int c = ch / NHEADS, h = ch % NHEADS;
    int t = threadIdx.x;
    int l = c * CHUNK + t;
    __shared__ float s[CHUNK];
    float v = __half2float(g_zxh[l * D_IN_PROJ + (D_IN_PROJ - NHEADS) + h]) + dt_bias[h];
    float sp = softplusf(v);
    g_dt[l * NHEADS + h] = sp;
    s[t] = -expf(A_log[h]) * sp;
    __syncthreads();
    for (int off = 1; off < CHUNK; off <<= 1) {
        float add = (t >= off) ? s[t - off] : 0.0f;
        __syncthreads();
        s[t] += add;
        __syncthreads();
    }
    g_Acs[ch * CHUNK + t] = s[t];
    if (t == CHUNK - 1) g_Alast[ch] = s[t];
}

// ---------------- chunk states via fp16 mma (hi/lo, R13-proven) ----------------
#define SROW 72
__global__ void __launch_bounds__(256)
states_kernel() {
    __shared__ __half Ah[128 * SROW];
    __shared__ __half Al[128 * SROW];
    __shared__ __half Bs[64 * SROW];
    __shared__ float dec[64];

    int chd = blockIdx.x;
    int c = chd / NHEADS, h = chd % NHEADS;
    int tid  = threadIdx.x;
    int lane = tid & 31;
    int warp = tid >> 5;
    int lr = lane >> 2, lc = lane & 3;
    int wm = (warp >> 1) * 32;
    int wn = (warp & 1) * 32;

    float Alast = g_Alast[chd];

    float acc[2][4][4];
#pragma unroll
    for (int i = 0; i < 2; i++)
#pragma unroll
        for (int j = 0; j < 4; j++)
#pragma unroll
            for (int r = 0; r < 4; r++) acc[i][j][r] = 0.0f;

    for (int kt = 0; kt < 4; kt++) {
        int l0 = kt * 64;
        if (tid < 64) dec[tid] = expf(Alast - g_Acs[chd * CHUNK + l0 + tid]);
        __syncthreads();
        {
            int p = tid & 127, l2 = tid >> 7;
#pragma unroll
            for (int i = 0; i < 32; i++) {
                int l = l2 + i * 2;
                float v = g_xdt[(c * CHUNK + l0 + l) * DIM_INNER + h * HEADDIM + p] * dec[l];
                __half hi = __float2half_rn(v);
                Ah[p * SROW + l] = hi;
                Al[p * SROW + l] = __float2half_rn(v - __half2float(hi));
            }
        }
        {
            int n = tid & 63, l4 = tid >> 6;
#pragma unroll
            for (int i = 0; i < 16; i++) {
                int l = l4 + i * 4;
                Bs[n * SROW + l] = __float2half_rn(g_B[(c * CHUNK + l0 + l) * D_STATE + n]);
            }
        }
        __syncthreads();

#pragma unroll
        for (int kk = 0; kk < 4; kk++) {
            int kb = kk * 16;
            uint32_t ah[2][4], al[2][4], bf[4][2];
#pragma unroll
            for (int mi = 0; mi < 2; mi++) {
                int mb = wm + mi * 16 + lr;
                ah[mi][0] = *(const uint32_t*)&Ah[(mb    ) * SROW + kb + lc * 2];
                ah[mi][1] = *(const uint32_t*)&Ah[(mb + 8) * SROW + kb + lc * 2];
                ah[mi][2] = *(const uint32_t*)&Ah[(mb    ) * SROW + kb + 8 + lc * 2];
                ah[mi][3] = *(const uint32_t*)&Ah[(mb + 8) * SROW + kb + 8 + lc * 2];
                al[mi][0] = *(const uint32_t*)&Al[(mb    ) * SROW + kb + lc * 2];
                al[mi][1] = *(const uint32_t*)&Al[(mb + 8) * SROW + kb + lc * 2];
                al[mi][2] = *(const uint32_t*)&Al[(mb    ) * SROW + kb + 8 + lc * 2];
                al[mi][3] = *(const uint32_t*)&Al[(mb + 8) * SROW + kb + 8 + lc * 2];
            }
#pragma unroll
            for (int ni = 0; ni < 4; ni++) {
                int nb = wn + ni * 8 + lr;
                bf[ni][0] = *(const uint32_t*)&Bs[nb * SROW + kb + lc * 2];
                bf[ni][1] = *(const uint32_t*)&Bs[nb * SROW + kb + 8 + lc * 2];
            }
#pragma unroll
            for (int mi = 0; mi < 2; mi++)
#pragma unroll
                for (int ni = 0; ni < 4; ni++) {
                    MMA_F16(acc[mi][ni], ah[mi], bf[ni]);
                    MMA_F16(acc[mi][ni], al[mi], bf[ni]);
                }
        }
        __syncthreads();
    }

#pragma unroll
    for (int mi = 0; mi < 2; mi++) {
        int p0 = wm + mi * 16 + lr;
#pragma unroll
        for (int ni = 0; ni < 4; ni++) {
            int n = wn + ni * 8 + lc * 2;
            float* s0 = &g_states[chd * (HEADDIM * D_STATE) + p0 * D_STATE + n];
            float* s1 = s0 + 8 * D_STATE;
            s0[0] = acc[mi][ni][0]; s0[1] = acc[mi][ni][1];
            s1[0] = acc[mi][ni][2]; s1[1] = acc[mi][ni][3];
        }
    }
}

// ---------------- inter-chunk recurrence ----------------
__global__ void sprev_kernel() {
    int idx = blockIdx.x * blockDim.x + threadIdx.x;
    if (idx >= NHEADS * HEADDIM * D_STATE) return;
    int h = idx / (HEADDIM * D_STATE);
    int r = idx % (HEADDIM * D_STATE);
    float S = 0.0f;
    for (int c = 0; c < NCHUNK; c++) {
        int ch = c * NHEADS + h;
        g_sprev[ch * (HEADDIM * D_STATE) + r] = S;
        S = expf(g_Alast[ch]) * S + g_states[ch * (HEADDIM * D_STATE) + r];
    }
}

// ================ fused SSD Y kernel (fp16 mma; single-precision X) ============
#define YROW 72
#define O_CH   0
#define O_BS   (O_CH + 128 * YROW)
#define O_GS   (O_BS + 64 * YROW)
#define O_XH   (O_GS + 128 * YROW)
#define O_SS   (O_XH + 128 * YROW)
#define O_END  (O_SS + 128 * YROW)
#define Y_SMEM_BYTES (O_END * 2 + (128 + 128 + 64) * 4)   // ~83.5 KB

__global__ void __launch_bounds__(256, 2)
y_mma_kernel(const float* __restrict__ Dparam) {
    extern __shared__ __half ysm[];
    __half* Ch  = ysm + O_CH;
    __half* Bsm = ysm + O_BS;
    __half* Gsm = ysm + O_GS;
    __half* Xh  = ysm + O_XH;
    __half* Ssm = ysm + O_SS;
    float* acsl  = (float*)(ysm + O_END);
    float* expAl = acsl + 128;
    float* acss  = expAl + 128;

    const int hh = blockIdx.y, c = blockIdx.z;
    const int lh = blockIdx.x;
    const int l0 = lh * 128;
    const int ch = c * NHEADS + hh;
    const int tid  = threadIdx.x;
    const int lane = tid & 31;
    const int warp = tid >> 5;
    const int lr   = lane >> 2;
    const int lc   = lane & 3;
    const int wmY = (warp >> 1) * 32;
    const int wnY = (warp & 1) * 64;
    const int wmG = (warp >> 1) * 32;
    const int wnG = (warp & 1) * 32;

    {
        int n = tid & 63, r4 = tid >> 6;
#pragma unroll
        for (int i = 0; i < 32; i++) {
            int l = r4 + i * 4;
            Ch[l * YROW + n]  = __float2half_rn(g_C[(c * CHUNK + l0 + l) * D_STATE + n]);
            Ssm[l * YROW + n] = __float2half_rn(g_sprev[ch * (HEADDIM * D_STATE) + l * D_STATE + n]);
        }
        if (tid < 128) {
            float a = g_Acs[ch * CHUNK + l0 + tid];
            acsl[tid] = a;
            expAl[tid] = expf(a);
        }
    }
    __syncthreads();

    float acc[2][8][4];
#pragma unroll
    for (int i = 0; i < 2; i++)
#pragma unroll
        for (int j = 0; j < 8; j++)
#pragma unroll
            for (int r = 0; r < 4; r++) acc[i][j][r] = 0.0f;

    // ---- Y_off: C @ Sprev^T (K = 64) ----
#pragma unroll
    for (int kk = 0; kk < 4; kk++) {
        int kb = kk * 16;
        uint32_t afr[2][4], bfr[8][2];
#pragma unroll
        for (int mi = 0; mi < 2; mi++) {
            int mb = wmY + mi * 16 + lr;
            afr[mi][0] = *(const uint32_t*)&Ch[(mb    ) * YROW + kb + lc * 2];
            afr[mi][1] = *(const uint32_t*)&Ch[(mb + 8) * YROW + kb + lc * 2];
            afr[mi][2] = *(const uint32_t*)&Ch[(mb    ) * YROW + kb + 8 + lc * 2];
            afr[mi][3] = *(const uint32_t*)&Ch[(mb + 8) * YROW + kb + 8 + lc * 2];
        }
#pragma unroll
        for (int ni = 0; ni < 8; ni++) {
            int nb = wnY + ni * 8 + lr;
            bfr[ni][0] = *(const uint32_t*)&Ssm[nb * YROW + kb + lc * 2];
            bfr[ni][1] = *(const uint32_t*)&Ssm[nb * YROW + kb + 8 + lc * 2];
        }
#pragma unroll
        for (int mi = 0; mi < 2; mi++)
#pragma unroll
            for (int ni = 0; ni < 8; ni++)
                MMA_F16(acc[mi][ni], afr[mi], bfr[ni]);
    }
#pragma unroll
    for (int mi = 0; mi < 2; mi++) {
        int r0 = wmY + mi * 16 + lr;
        float e0 = expAl[r0], e1 = expAl[r0 + 8];
#pragma unroll
        for (int ni = 0; ni < 8; ni++) {
            acc[mi][ni][0] *= e0; acc[mi][ni][1] *= e0;
            acc[mi][ni][2] *= e1; acc[mi][ni][3] *= e1;
        }
    }

    // ---- Y_diag: s-tiles of 64 ----
    const int nst = 2 * (lh + 1);
    for (int st = 0; st < nst; st++) {
        {
            int n = tid & 63, s4 = tid >> 6;
#pragma unroll
            for (int i = 0; i < 16; i++) {
                int s = s4 + i * 4;
                Bsm[s * YROW + n] = __float2half_rn(g_B[(c * CHUNK + st * 64 + s) * D_STATE + n]);
            }
            if (tid < 64) acss[tid] = g_Acs[ch * CHUNK + st * 64 + tid];
            int p = tid & 127, s2 = tid >> 7;
#pragma unroll
            for (int i = 0; i < 32; i++) {
                int s = s2 + i * 2;
                float v = g_xdt[(c * CHUNK + st * 64 + s) * DIM_INNER + hh * HEADDIM + p];
                Xh[p * YROW + s] = __float2half_rn(v);
            }
        }
        __syncthreads();

        float gacc[2][4][4];
#pragma unroll
        for (int i = 0; i < 2; i++)
#pragma unroll
            for (int j = 0; j < 4; j++)
#pragma unroll
                for (int r = 0; r < 4; r++) gacc[i][j][r] = 0.0f;
#pragma unroll
        for (int kk = 0; kk < 4; kk++) {
            int kb = kk * 16;
            uint32_t afr[2][4], bfr[4][2];
#pragma unroll
            for (int mi = 0; mi < 2; mi++) {
                int mb = wmG + mi * 16 + lr;
                afr[mi][0] = *(const uint32_t*)&Ch[(mb    ) * YROW + kb + lc * 2];
                afr[mi][1] = *(const uint32_t*)&Ch[(mb + 8) * YROW + kb + lc * 2];
                afr[mi][2] = *(const uint32_t*)&Ch[(mb    ) * YROW + kb + 8 + lc * 2];
                afr[mi][3] = *(const uint32_t*)&Ch[(mb + 8) * YROW + kb + 8 + lc * 2];
            }
#pragma unroll
            for (int ni = 0; ni < 4; ni++) {
                int nb = wnG + ni * 8 + lr;
                bfr[ni][0] = *(const uint32_t*)&Bsm[nb * YROW + kb + lc * 2];
                bfr[ni][1] = *(const uint32_t*)&Bsm[nb * YROW + kb + 8 + lc * 2];
            }
#pragma unroll
            for (int mi = 0; mi < 2; mi++)
#pragma unroll
                for (int ni = 0; ni < 4; ni++)
                    MMA_F16(gacc[mi][ni], afr[mi], bfr[ni]);
        }

        const int sbase = st * 64;
#pragma unroll
        for (int mi = 0; mi < 2; mi++) {
            int r0 = wmG + mi * 16 + lr;
            float a0 = acsl[r0], a1 = acsl[r0 + 8];
            int lg0 = l0 + r0, lg1 = lg0 + 8;
#pragma unroll
            for (int ni = 0; ni < 4; ni++) {
                int cl = wnG + ni * 8 + lc * 2;
                float as0 = acss[cl], as1 = acss[cl + 1];
                int sg0 = sbase + cl, sg1 = sg0 + 1;
                float g00 = (sg0 <= lg0) ? gacc[mi][ni][0] * expf(a0 - as0) : 0.0f;
                float g01 = (sg1 <= lg0) ? gacc[mi][ni][1] * expf(a0 - as1) : 0.0f;
                float g10 = (sg0 <= lg1) ? gacc[mi][ni][2] * expf(a1 - as0) : 0.0f;
                float g11 = (sg1 <= lg1) ? gacc[mi][ni][3] * expf(a1 - as1) : 0.0f;
                Gsm[(r0    ) * YROW + cl    ] = __float2half_rn(g00);
                Gsm[(r0    ) * YROW + cl + 1] = __float2half_rn(g01);
                Gsm[(r0 + 8) * YROW + cl    ] = __float2half_rn(g10);
                Gsm[(r0 + 8) * YROW + cl + 1] = __float2half_rn(g11);
            }
        }
        __syncthreads();

#pragma unroll
        for (int kk = 0; kk < 4; kk++) {
            int kb = kk * 16;
            uint32_t afr[2][4], bh[8][2];
#pragma unroll
            for (int mi = 0; mi < 2; mi++) {
                int mb = wmY + mi * 16 + lr;
                afr[mi][0] = *(const uint32_t*)&Gsm[(mb    ) * YROW + kb + lc * 2];
                afr[mi][1] = *(const uint32_t*)&Gsm[(mb + 8) * YROW + kb + lc * 2];
                afr[mi][2] = *(const uint32_t*)&Gsm[(mb    ) * YROW + kb + 8 + lc * 2];
                afr[mi][3] = *(const uint32_t*)&Gsm[(mb + 8) * YROW + kb + 8 + lc * 2];
            }
#pragma unroll
            for (int ni = 0; ni < 8; ni++) {
                int nb = wnY + ni * 8 + lr;
                bh[ni][0] = *(const uint32_t*)&Xh[nb * YROW + kb + lc * 2];
                bh[ni][1] = *(const uint32_t*)&Xh[nb * YROW + kb + 8 + lc * 2];
            }
#pragma unroll
            for (int mi = 0; mi < 2; mi++)
#pragma unroll
                for (int ni = 0; ni < 8; ni++)
                    MMA_F16(acc[mi][ni], afr[mi], bh[ni]);
        }
        __syncthreads();
    }

    float Dh = Dparam[hh];
#pragma unroll
    for (int mi = 0; mi < 2; mi++) {
        int r0 = wmY + mi * 16 + lr;
#pragma unroll
        for (int ni = 0; ni < 8; ni++) {
            int col = wnY + ni * 8 + lc * 2;
            long o0 = (long)(c * CHUNK + l0 + r0) * DIM_INNER + hh * HEADDIM + col;
            long o1 = o0 + 8L * DIM_INNER;
            g_y[o0]     = acc[mi][ni][0] + __half2float(g_xsh[o0]) * Dh;
            g_y[o0 + 1] = acc[mi][ni][1] + __half2float(g_xsh[o0 + 1]) * Dh;
            g_y[o1]     = acc[mi][ni][2] + __half2float(g_xsh[o1]) * Dh;
            g_y[o1 + 1] = acc[mi][ni][3] + __half2float(g_xsh[o1 + 1]) * Dh;
        }
    }
}

// ---------------- gated RMSNorm (fp16 z; writes fp16 for out_proj) -------------
__global__ void __launch_bounds__(256)
norm_kernel(const float* __restrict__ norm_w) {
    int l = blockIdx.x;
    int t = threadIdx.x;
    float vals[16];
    float ss = 0.0f;
#pragma unroll
    for (int r = 0; r < 16; r++) {
        int j = t + r * 256;
        float yv = g_y[l * DIM_INNER + j];
        float zv = __half2float(g_zxh[l * D_IN_PROJ + j]);
        float gv = yv * siluf(zv);
        vals[r] = gv;
        ss += gv * gv;
    }
    __shared__ float red[8];
#pragma unroll
    for (int off = 16; off > 0; off >>= 1)
        ss += __shfl_down_sync(0xffffffffu, ss, off);
    if ((t & 31) == 0) red[t >> 5] = ss;
    __syncthreads();
    float total;
    {
        float v = (t < 8) ? red[t] : 0.0f;
#pragma unroll
        for (int off = 4; off > 0; off >>= 1)
            v += __shfl_down_sync(0xffffffffu, v, off);
        if (t == 0) red[0] = v;
    }
    __syncthreads();
    total = red[0];
    float scale = rsqrtf(total / (float)DIM_INNER + 1e-5f);
#pragma unroll
    for (int r = 0; r < 16; r++) {
        int j = t + r * 256;
        g_yh[l * DIM_INNER + j] = __float2half_rn(vals[r] * scale * norm_w[j]);
    }
}

// ---------------- host launcher ----------------
extern "C" void kernel_launch(void* const* d_in, const int* in_sizes, int n_in,
                              void* d_out, int out_size) {
    const float* x        = (const float*)d_in[0];
    const float* in_w     = (const float*)d_in[1];
    const float* conv_w   = (const float*)d_in[2];
    const float* conv_b   = (const float*)d_in[3];
    const float* dt_bias  = (const float*)d_in[4];
    const float* A_log    = (const float*)d_in[5];
    const float* Dparam   = (const float*)d_in[6];
    const float* norm_w   = (const float*)d_in[7];
    const float* out_w    = (const float*)d_in[8];
    float* out            = (float*)d_out;

    __half* zxh; cudaGetSymbolAddress((void**)&zxh, g_zxh);
    __half* wA;  cudaGetSymbolAddress((void**)&wA,  g_wA);
    __half* wB;  cudaGetSymbolAddress((void**)&wB,  g_wB);
    __half* xh;  cudaGetSymbolAddress((void**)&xh,  g_xh);
    __half* yh;  cudaGetSymbolAddress((void**)&yh,  g_yh);

    cudaFuncSetAttribute(h16_gemm<0>, cudaFuncAttributeMaxDynamicSharedMemorySize, GEMM_SMEM);
    cudaFuncSetAttribute(h16_gemm<1>, cudaFuncAttributeMaxDynamicSharedMemorySize, GEMM_SMEM);
    cudaFuncSetAttribute(y_mma_kernel, cudaFuncAttributeMaxDynamicSharedMemorySize, Y_SMEM_BYTES);

    // 0. convert GEMM operands to fp16
    tohalf_kernel<<<(D_IN_PROJ * DIM / 8 + 255) / 256, 256>>>(in_w, wA, D_IN_PROJ * DIM);
    tohalf_kernel<<<(SEQ * DIM / 8 + 255) / 256, 256>>>(x, xh, SEQ * DIM);
    tohalf_kernel<<<(DIM * DIM_INNER / 8 + 255) / 256, 256>>>(out_w, wB, DIM * DIM_INNER);

    // 1. in_proj (fp16 mma, fp16 output)
    {
        dim3 grid((D_IN_PROJ + TBN - 1) / TBN, SEQ / TBM);
        h16_gemm<1><<<grid, 128, GEMM_SMEM>>>(xh, wA, zxh, SEQ, D_IN_PROJ, DIM);
    }
    // 2. fused dt + cumsum per (chunk, head)
    cumsum_dt_kernel<<<NCHUNK * NHEADS, CHUNK>>>(dt_bias, A_log);
    // 3. conv + silu + split (4 channels/thread, fp16 src)
    conv_kernel<<<(SEQ * CONV_DIM / 4 + 255) / 256, 256>>>(conv_w, conv_b);
    // 4. chunk states (fp16 mma)
    states_kernel<<<NCHUNK * NHEADS, 256>>>();
    // 5. inter-chunk recurrence
    sprev_kernel<<<(NHEADS * HEADDIM * D_STATE + 255) / 256, 256>>>();
    // 6. Y via fp16 mma (2 CTAs/SM)
    {
        dim3 grid(2, NHEADS, NCHUNK);
        y_mma_kernel<<<grid, 256, Y_SMEM_BYTES>>>(Dparam);
    }
    // 7. gated RMSNorm (fp16 z)
    norm_kernel<<<SEQ, 256>>>(norm_w);
    // 8. out_proj (fp32 output)
    {
        dim3 grid(DIM / TBN, SEQ / TBM);
        h16_gemm<0><<<grid, 128, GEMM_SMEM>>>(yh, wB, out, SEQ, DIM, DIM_INNER);
    }
}

// round 16
// speedup vs baseline: 1.5313x; 1.0304x over previous
#include <cuda_runtime.h>
#include <cuda_fp16.h>
#include <math.h>
#include <stdint.h>

// ---------------- problem constants ----------------
#define SEQ        2048
#define DIM        2048
#define DIM_INNER  4096
#define D_STATE    64
#define D_CONV     4
#define HEADDIM    128
#define NHEADS     32
#define CHUNK      256
#define NCHUNK     (SEQ / CHUNK)          // 8
#define CONV_DIM   (DIM_INNER + 2 * D_STATE)      // 4224
#define D_IN_PROJ  (2 * DIM_INNER + 2 * D_STATE + NHEADS)  // 8352

// ---------------- scratch (device globals; no allocation allowed) -------------
__device__ __align__(128) __half g_zxh [SEQ * D_IN_PROJ];   // in_proj out (fp16)
__device__ float g_dt   [SEQ * NHEADS];
__device__ __align__(128) __half g_xsh [SEQ * DIM_INNER];
__device__ __align__(128) __half g_xdth[SEQ * DIM_INNER];   // x*dt (fp16)
__device__ float g_B    [SEQ * D_STATE];
__device__ float g_C    [SEQ * D_STATE];
__device__ float g_Acs  [NCHUNK * NHEADS * CHUNK];
__device__ float g_Alast[NCHUNK * NHEADS];
__device__ float g_states[NCHUNK * NHEADS * HEADDIM * D_STATE];
__device__ float g_sprev [NCHUNK * NHEADS * HEADDIM * D_STATE];
__device__ __align__(128) __half g_yhalf[SEQ * DIM_INNER];  // y (fp16)
// fp16 GEMM operands
__device__ __align__(128) __half g_wA [D_IN_PROJ * DIM];
__device__ __align__(128) __half g_wB [DIM * DIM_INNER];
__device__ __align__(128) __half g_xh [SEQ * DIM];
__device__ __align__(128) __half g_yh [SEQ * DIM_INNER];

__device__ __forceinline__ float siluf(float v) { return v / (1.0f + expf(-v)); }
__device__ __forceinline__ float softplusf(float v) { return (v > 20.0f) ? v : log1pf(expf(v)); }

// ---------------- fp32 -> fp16 conversion pass ----------------
__global__ void tohalf_kernel(const float* __restrict__ in, __half* __restrict__ out, int n) {
    int i = (blockIdx.x * blockDim.x + threadIdx.x) * 8;
    if (i >= n) return;
    float4 a = *(const float4*)(in + i);
    float4 b = *(const float4*)(in + i + 4);
    __half2 h0 = __floats2half2_rn(a.x, a.y);
    __half2 h1 = __floats2half2_rn(a.z, a.w);
    __half2 h2 = __floats2half2_rn(b.x, b.y);
    __half2 h3 = __floats2half2_rn(b.z, b.w);
    uint4 o;
    o.x = *(uint32_t*)&h0; o.y = *(uint32_t*)&h1;
    o.z = *(uint32_t*)&h2; o.w = *(uint32_t*)&h3;
    *(uint4*)(out + i) = o;
}

#define MMA_F16(acc, a, b) \
    asm volatile( \
        "mma.sync.aligned.m16n8k16.row.col.f32.f16.f16.f32 " \
        "{%0,%1,%2,%3}, {%4,%5,%6,%7}, {%8,%9}, {%0,%1,%2,%3};" \
        : "+f"((acc)[0]), "+f"((acc)[1]), "+f"((acc)[2]), "+f"((acc)[3]) \
        : "r"((a)[0]), "r"((a)[1]), "r"((a)[2]), "r"((a)[3]), \
          "r"((b)[0]), "r"((b)[1]))

#define LDSM_X4(r0, r1, r2, r3, addr) \
    asm volatile("ldmatrix.sync.aligned.m8n8.x4.shared.b16 {%0,%1,%2,%3}, [%4];" \
        : "=r"(r0), "=r"(r1), "=r"(r2), "=r"(r3) : "r"(addr))

// ==== fp16 mma.sync GEMM (R11-proven config, FROZEN); OUT_HALF selects epilogue
#define TBM   128
#define TBN   128
#define TBK   32
#define NSTG  4
#define ROWPH 40
#define STGH  (TBM * ROWPH)
#define GEMM_SMEM (2 * NSTG * STGH * 2)  // 81920 bytes

template <int OUT_HALF>
__global__ void __launch_bounds__(128, 2)
h16_gemm(const __half* __restrict__ A, const __half* __restrict__ B,
         void* __restrict__ Cout, int M, int N, int K) {
    extern __shared__ __half sm[];

    const int tid  = threadIdx.x;
    const int lane = tid & 31;
    const int warp = tid >> 5;
    const int m0   = blockIdx.y * TBM;
    const int n0   = blockIdx.x * TBN;
    const int wm   = (warp >> 1) * 64;
    const int wn   = (warp & 1) * 64;
    const int lr   = lane >> 2;
    const int lc   = lane & 3;
    const int ktiles = K / TBK;

    const int lrow = tid >> 2;
    const int lch  = (tid & 3) * 8;

    const int rowin  = lane & 7;
    const int a_row  = ((lane >> 3) & 1) * 8 + rowin;
    const int a_koff = ((lane >> 4) & 1) * 8;
    const int b_row  = ((lane >> 4) & 1) * 8 + rowin;
    const int b_koff = ((lane >> 3) & 1) * 8;

    uint32_t a_s0, b_s0;
    {
        uint32_t base;
        asm("{ .reg .u64 t; cvta.to.shared.u64 t, %1; cvt.u32.u64 %0, t; }"
            : "=r"(base) : "l"(sm));
        a_s0 = base;
        b_s0 = base + NSTG * STGH * 2;
    }

    auto issue = [&](int kt, int st) {
        const __half* Ag = A + (long)m0 * K + kt * TBK;
        const __half* Bg = B + (long)n0 * K + kt * TBK;
        uint32_t abase = a_s0 + st * STGH * 2;
        uint32_t bbase = b_s0 + st * STGH * 2;
#pragma unroll
        for (int i = 0; i < 4; i++) {
            int r = lrow + i * 32;
            uint32_t doff = r * ROWPH * 2 + lch * 2;
            asm volatile("cp.async.cg.shared.global [%0], [%1], 16;"
                         :: "r"(abase + doff), "l"(Ag + (long)r * K + lch) : "memory");
            int sz = (n0 + r < N) ? 16 : 0;
            asm volatile("cp.async.cg.shared.global [%0], [%1], 16, %2;"
                         :: "r"(bbase + doff), "l"(Bg + (long)r * K + lch), "r"(sz) : "memory");
        }
        asm volatile("cp.async.commit_group;" ::: "memory");
    };

#pragma unroll
    for (int st = 0; st < NSTG - 1; st++) issue(st, st);

    float acc[4][8][4];
#pragma unroll
    for (int i = 0; i < 4; i++)
#pragma unroll
        for (int j = 0; j < 8; j++)
#pragma unroll
            for (int r = 0; r < 4; r++) acc[i][j][r] = 0.0f;

    for (int kt = 0; kt < ktiles; kt++) {
        int s = kt % NSTG;
        asm volatile("cp.async.wait_group %0;" :: "n"(NSTG - 2));
        __syncthreads();
        int nt = kt + NSTG - 1;
        if (nt < ktiles) issue(nt, nt % NSTG);
        else asm volatile("cp.async.commit_group;" ::: "memory");

        uint32_t abase = a_s0 + s * STGH * 2;
        uint32_t bbase = b_s0 + s * STGH * 2;
#pragma unroll
        for (int kk = 0; kk < 2; kk++) {
            int kb = kk * 16;
            uint32_t afr[4][4], bfr[8][2];
#pragma unroll
            for (int mi = 0; mi < 4; mi++) {
                uint32_t addr = abase + (((wm + mi * 16 + a_row) * ROWPH) + kb + a_koff) * 2;
                LDSM_X4(afr[mi][0], afr[mi][1], afr[mi][2], afr[mi][3], addr);
            }
#pragma unroll
            for (int nj = 0; nj < 4; nj++) {
                uint32_t addr = bbase + (((wn + nj * 16 + b_row) * ROWPH) + kb + b_koff) * 2;
                LDSM_X4(bfr[nj * 2][0], bfr[nj * 2][1],
                        bfr[nj * 2 + 1][0], bfr[nj * 2 + 1][1], addr);
            }
#pragma unroll
            for (int mi = 0; mi < 4; mi++)
#pragma unroll
                for (int ni = 0; ni < 8; ni++)
                    MMA_F16(acc[mi][ni], afr[mi], bfr[ni]);
        }
    }

#pragma unroll
    for (int mi = 0; mi < 4; mi++) {
        int r0 = m0 + wm + mi * 16 + lr;
#pragma unroll
        for (int ni = 0; ni < 8; ni++) {
            int ccol = n0 + wn + ni * 8 + lc * 2;
            if (ccol < N) {
                if (OUT_HALF) {
                    __half* C = (__half*)Cout;
                    __half2 v0 = __floats2half2_rn(acc[mi][ni][0], acc[mi][ni][1]);
                    __half2 v1 = __floats2half2_rn(acc[mi][ni][2], acc[mi][ni][3]);
                    *(__half2*)(C + (long)r0 * N + ccol) = v0;
                    *(__half2*)(C + (long)(r0 + 8) * N + ccol) = v1;
                } else {
                    float* C = (float*)Cout;
                    float* p0 = C + (long)r0 * N + ccol;
                    float* p1 = C + (long)(r0 + 8) * N + ccol;
                    p0[0] = acc[mi][ni][0];
                    p0[1] = acc[mi][ni][1];
                    p1[0] = acc[mi][ni][2];
                    p1[1] = acc[mi][ni][3];
                }
            }
        }
    }
}

// ---------------- causal depthwise conv + SiLU + split (4-wide, fp16) ----------
__global__ void conv_kernel(const float* __restrict__ conv_w,
                            const float* __restrict__ conv_b) {
    int idx = (blockIdx.x * blockDim.x + threadIdx.x) * 4;
    if (idx >= SEQ * CONV_DIM) return;
    int l = idx / CONV_DIM, ch = idx % CONV_DIM;

    float4 wv[4];
#pragma unroll
    for (int j = 0; j < 4; j++)
        wv[j] = *(const float4*)&conv_w[(ch + j) * D_CONV];

    float4 acc = *(const float4*)&conv_b[ch];
#pragma unroll
    for (int k = 0; k < D_CONV; k++) {
        int ls = l - (D_CONV - 1) + k;
        if (ls >= 0) {
            const __half2* src = (const __half2*)&g_zxh[ls * D_IN_PROJ + DIM_INNER + ch];
            float2 v01 = __half22float2(src[0]);
            float2 v23 = __half22float2(src[1]);
            acc.x += v01.x * ((const float*)&wv[0])[k];
            acc.y += v01.y * ((const float*)&wv[1])[k];
            acc.z += v23.x * ((const float*)&wv[2])[k];
            acc.w += v23.y * ((const float*)&wv[3])[k];
        }
    }
    acc.x = siluf(acc.x); acc.y = siluf(acc.y);
    acc.z = siluf(acc.z); acc.w = siluf(acc.w);

    if (ch < DIM_INNER) {
        int h = ch >> 7;
        float dtv = g_dt[l * NHEADS + h];
        __half2 h0 = __floats2half2_rn(acc.x, acc.y);
        __half2 h1 = __floats2half2_rn(acc.z, acc.w);
        *(uint32_t*)&g_xsh[l * DIM_INNER + ch]     = *(uint32_t*)&h0;
        *(uint32_t*)&g_xsh[l * DIM_INNER + ch + 2] = *(uint32_t*)&h1;
        __half2 d0 = __floats2half2_rn(acc.x * dtv, acc.y * dtv);
        __half2 d1 = __floats2half2_rn(acc.z * dtv, acc.w * dtv);
        *(uint32_t*)&g_xdth[l * DIM_INNER + ch]     = *(uint32_t*)&d0;
        *(uint32_t*)&g_xdth[l * DIM_INNER + ch + 2] = *(uint32_t*)&d1;
    } else if (ch < DIM_INNER + D_STATE) {
        *(float4*)&g_B[l * D_STATE + (ch - DIM_INNER)] = acc;
    } else {
        *(float4*)&g_C[l * D_STATE + (ch - DIM_INNER - D_STATE)] = acc;
    }
}

// ------- fused dt + per-(chunk,head) inclusive cumsum of dA -------
__global__ void cumsum_dt_kernel(const float* __restrict__ dt_bias,
                                 const float* __restrict__ A_log) {
    int ch = blockIdx.x;
    int c = ch / NHEADS, h = ch % NHEADS;
    int t = threadIdx.x;
    int l = c * CHUNK + t;
    __shared__ float s[CHUNK];
    float v = __half2float(g_zxh[l * D_IN_PROJ + (D_IN_PROJ - NHEADS) + h]) + dt_bias[h];
    float sp = softplusf(v);
    g_dt[l * NHEADS + h] = sp;
    s[t] = -expf(A_log[h]) * sp;
    __syncthreads();
    for (int off = 1; off < CHUNK; off <<= 1) {
        float add = (t >= off) ? s[t - off] : 0.0f;
        __syncthreads();
        s[t] += add;
        __syncthreads();
    }
    g_Acs[ch * CHUNK + t] = s[t];
    if (t == CHUNK - 1) g_Alast[ch] = s[t];
}

// ---------------- chunk states via fp16 mma (hi/lo on weighted product) --------
#define SROW 72
__global__ void __launch_bounds__(256)
states_kernel() {
    __shared__ __half Ah[128 * SROW];
    __shared__ __half Al[128 * SROW];
    __shared__ __half Bs[64 * SROW];
    __shared__ float dec[64];

    int chd = blockIdx.x;
    int c = chd / NHEADS, h = chd % NHEADS;
    int tid  = threadIdx.x;
    int lane = tid & 31;
    int warp = tid >> 5;
    int lr = lane >> 2, lc = lane & 3;
    int wm = (warp >> 1) * 32;
    int wn = (warp & 1) * 32;

    float Alast = g_Alast[chd];

    float acc[2][4][4];
#pragma unroll
    for (int i = 0; i < 2; i++)
#pragma unroll
        for (int j = 0; j < 4; j++)
#pragma unroll
            for (int r = 0; r < 4; r++) acc[i][j][r] = 0.0f;

    for (int kt = 0; kt < 4; kt++) {
        int l0 = kt * 64;
        if (tid < 64) dec[tid] = expf(Alast - g_Acs[chd * CHUNK + l0 + tid]);
        __syncthreads();
        {
            int p = tid & 127, l2 = tid >> 7;
#pragma unroll
            for (int i = 0; i < 32; i++) {
                int l = l2 + i * 2;
                float v = __half2float(g_xdth[(c * CHUNK + l0 + l) * DIM_INNER + h * HEADDIM + p]) * dec[l];
                __half hi = __float2half_rn(v);
                Ah[p * SROW + l] = hi;
                Al[p * SROW + l] = __float2half_rn(v - __half2float(hi));
            }
        }
        {
            int n = tid & 63, l4 = tid >> 6;
#pragma unroll
            for (int i = 0; i < 16; i++) {
                int l = l4 + i * 4;
                Bs[n * SROW + l] = __float2half_rn(g_B[(c * CHUNK + l0 + l) * D_STATE + n]);
            }
        }
        __syncthreads();

#pragma unroll
        for (int kk = 0; kk < 4; kk++) {
            int kb = kk * 16;
            uint32_t ah[2][4], al[2][4], bf[4][2];
#pragma unroll
            for (int mi = 0; mi < 2; mi++) {
                int mb = wm + mi * 16 + lr;
                ah[mi][0] = *(const uint32_t*)&Ah[(mb    ) * SROW + kb + lc * 2];
                ah[mi][1] = *(const uint32_t*)&Ah[(mb + 8) * SROW + kb + lc * 2];
                ah[mi][2] = *(const uint32_t*)&Ah[(mb    ) * SROW + kb + 8 + lc * 2];
                ah[mi][3] = *(const uint32_t*)&Ah[(mb + 8) * SROW + kb + 8 + lc * 2];
                al[mi][0] = *(const uint32_t*)&Al[(mb    ) * SROW + kb + lc * 2];
                al[mi][1] = *(const uint32_t*)&Al[(mb + 8) * SROW + kb + lc * 2];
                al[mi][2] = *(const uint32_t*)&Al[(mb    ) * SROW + kb + 8 + lc * 2];
                al[mi][3] = *(const uint32_t*)&Al[(mb + 8) * SROW + kb + 8 + lc * 2];
            }
#pragma unroll
            for (int ni = 0; ni < 4; ni++) {
                int nb = wn + ni * 8 + lr;
                bf[ni][0] = *(const uint32_t*)&Bs[nb * SROW + kb + lc * 2];
                bf[ni][1] = *(const uint32_t*)&Bs[nb * SROW + kb + 8 + lc * 2];
            }
#pragma unroll
            for (int mi = 0; mi < 2; mi++)
#pragma unroll
                for (int ni = 0; ni < 4; ni++) {
                    MMA_F16(acc[mi][ni], ah[mi], bf[ni]);
                    MMA_F16(acc[mi][ni], al[mi], bf[ni]);
                }
        }
        __syncthreads();
    }

#pragma unroll
    for (int mi = 0; mi < 2; mi++) {
        int p0 = wm + mi * 16 + lr;
#pragma unroll
        for (int ni = 0; ni < 4; ni++) {
            int n = wn + ni * 8 + lc * 2;
            float* s0 = &g_states[chd * (HEADDIM * D_STATE) + p0 * D_STATE + n];
            float* s1 = s0 + 8 * D_STATE;
            s0[0] = acc[mi][ni][0]; s0[1] = acc[mi][ni][1];
            s1[0] = acc[mi][ni][2]; s1[1] = acc[mi][ni][3];
        }
    }
}

// ---------------- inter-chunk recurrence ----------------
__global__ void sprev_kernel() {
    int idx = blockIdx.x * blockDim.x + threadIdx.x;
    if (idx >= NHEADS * HEADDIM * D_STATE) return;
    int h = idx / (HEADDIM * D_STATE);
    int r = idx % (HEADDIM * D_STATE);
    float S = 0.0f;
    for (int c = 0; c < NCHUNK; c++) {
        int ch = c * NHEADS + h;
        g_sprev[ch * (HEADDIM * D_STATE) + r] = S;
        S = expf(g_Alast[ch]) * S + g_states[ch * (HEADDIM * D_STATE) + r];
    }
}

// ================ fused SSD Y kernel (fp16 mma) ================
#define YROW 72
#define O_CH   0
#define O_BS   (O_CH + 128 * YROW)
#define O_GS   (O_BS + 64 * YROW)
#define O_XH   (O_GS + 128 * YROW)
#define O_SS   (O_XH + 128 * YROW)
#define O_END  (O_SS + 128 * YROW)
#define Y_SMEM_BYTES (O_END * 2 + (128 + 128 + 64) * 4)   // ~83.5 KB

__global__ void __launch_bounds__(256, 2)
y_mma_kernel(const float* __restrict__ Dparam) {
    extern __shared__ __half ysm[];
    __half* Ch  = ysm + O_CH;
    __half* Bsm = ysm + O_BS;
    __half* Gsm = ysm + O_GS;
    __half* Xh  = ysm + O_XH;
    __half* Ssm = ysm + O_SS;
    float* acsl  = (float*)(ysm + O_END);
    float* expAl = acsl + 128;
    float* acss  = expAl + 128;

    const int hh = blockIdx.y, c = blockIdx.z;
    const int lh = blockIdx.x;
    const int l0 = lh * 128;
    const int ch = c * NHEADS + hh;
    const int tid  = threadIdx.x;
    const int lane = tid & 31;
    const int warp = tid >> 5;
    const int lr   = lane >> 2;
    const int lc   = lane & 3;
    const int wmY = (warp >> 1) * 32;
    const int wnY = (warp & 1) * 64;
    const int wmG = (warp >> 1) * 32;
    const int wnG = (warp & 1) * 32;

    {
        int n = tid & 63, r4 = tid >> 6;
#pragma unroll
        for (int i = 0; i < 32; i++) {
            int l = r4 + i * 4;
            Ch[l * YROW + n]  = __float2half_rn(g_C[(c * CHUNK + l0 + l) * D_STATE + n]);
            Ssm[l * YROW + n] = __float2half_rn(g_sprev[ch * (HEADDIM * D_STATE) + l * D_STATE + n]);
        }
        if (tid < 128) {
            float a = g_Acs[ch * CHUNK + l0 + tid];
            acsl[tid] = a;
            expAl[tid] = expf(a);
        }
    }
    __syncthreads();

    float acc[2][8][4];
#pragma unroll
    for (int i = 0; i < 2; i++)
#pragma unroll
        for (int j = 0; j < 8; j++)
#pragma unroll
            for (int r = 0; r < 4; r++) acc[i][j][r] = 0.0f;

    // ---- Y_off: C @ Sprev^T (K = 64) ----
#pragma unroll
    for (int kk = 0; kk < 4; kk++) {
        int kb = kk * 16;
        uint32_t afr[2][4], bfr[8][2];
#pragma unroll
        for (int mi = 0; mi < 2; mi++) {
            int mb = wmY + mi * 16 + lr;
            afr[mi][0] = *(const uint32_t*)&Ch[(mb    ) * YROW + kb + lc * 2];
            afr[mi][1] = *(const uint32_t*)&Ch[(mb + 8) * YROW + kb + lc * 2];
            afr[mi][2] = *(const uint32_t*)&Ch[(mb    ) * YROW + kb + 8 + lc * 2];
            afr[mi][3] = *(const uint32_t*)&Ch[(mb + 8) * YROW + kb + 8 + lc * 2];
        }
#pragma unroll
        for (int ni = 0; ni < 8; ni++) {
            int nb = wnY + ni * 8 + lr;
            bfr[ni][0] = *(const uint32_t*)&Ssm[nb * YROW + kb + lc * 2];
            bfr[ni][1] = *(const uint32_t*)&Ssm[nb * YROW + kb + 8 + lc * 2];
        }
#pragma unroll
        for (int mi = 0; mi < 2; mi++)
#pragma unroll
            for (int ni = 0; ni < 8; ni++)
                MMA_F16(acc[mi][ni], afr[mi], bfr[ni]);
    }
#pragma unroll
    for (int mi = 0; mi < 2; mi++) {
        int r0 = wmY + mi * 16 + lr;
        float e0 = expAl[r0], e1 = expAl[r0 + 8];
#pragma unroll
        for (int ni = 0; ni < 8; ni++) {
            acc[mi][ni][0] *= e0; acc[mi][ni][1] *= e0;
            acc[mi][ni][2] *= e1; acc[mi][ni][3] *= e1;
        }
    }

    // ---- Y_diag: s-tiles of 64 ----
    const int nst = 2 * (lh + 1);
    for (int st = 0; st < nst; st++) {
        {
            int n = tid & 63, s4 = tid >> 6;
#pragma unroll
            for (int i = 0; i < 16; i++) {
                int s = s4 + i * 4;
                Bsm[s * YROW + n] = __float2half_rn(g_B[(c * CHUNK + st * 64 + s) * D_STATE + n]);
            }
            if (tid < 64) acss[tid] = g_Acs[ch * CHUNK + st * 64 + tid];
            int p = tid & 127, s2 = tid >> 7;
#pragma unroll
            for (int i = 0; i < 32; i++) {
                int s = s2 + i * 2;
                Xh[p * YROW + s] = g_xdth[(c * CHUNK + st * 64 + s) * DIM_INNER + hh * HEADDIM + p];
            }
        }
        __syncthreads();

        float gacc[2][4][4];
#pragma unroll
        for (int i = 0; i < 2; i++)
#pragma unroll
            for (int j = 0; j < 4; j++)
#pragma unroll
                for (int r = 0; r < 4; r++) gacc[i][j][r] = 0.0f;
#pragma unroll
        for (int kk = 0; kk < 4; kk++) {
            int kb = kk * 16;
            uint32_t afr[2][4], bfr[4][2];
#pragma unroll
            for (int mi = 0; mi < 2; mi++) {
                int mb = wmG + mi * 16 + lr;
                afr[mi][0] = *(const uint32_t*)&Ch[(mb    ) * YROW + kb + lc * 2];
                afr[mi][1] = *(const uint32_t*)&Ch[(mb + 8) * YROW + kb + lc * 2];
                afr[mi][2] = *(const uint32_t*)&Ch[(mb    ) * YROW + kb + 8 + lc * 2];
                afr[mi][3] = *(const uint32_t*)&Ch[(mb + 8) * YROW + kb + 8 + lc * 2];
            }
#pragma unroll
            for (int ni = 0; ni < 4; ni++) {
                int nb = wnG + ni * 8 + lr;
                bfr[ni][0] = *(const uint32_t*)&Bsm[nb * YROW + kb + lc * 2];
                bfr[ni][1] = *(const uint32_t*)&Bsm[nb * YROW + kb + 8 + lc * 2];
            }
#pragma unroll
            for (int mi = 0; mi < 2; mi++)
#pragma unroll
                for (int ni = 0; ni < 4; ni++)
                    MMA_F16(gacc[mi][ni], afr[mi], bfr[ni]);
        }

        const int sbase = st * 64;
#pragma unroll
        for (int mi = 0; mi < 2; mi++) {
            int r0 = wmG + mi * 16 + lr;
            float a0 = acsl[r0], a1 = acsl[r0 + 8];
            int lg0 = l0 + r0, lg1 = lg0 + 8;
#pragma unroll
            for (int ni = 0; ni < 4; ni++) {
                int cl = wnG + ni * 8 + lc * 2;
                float as0 = acss[cl], as1 = acss[cl + 1];
                int sg0 = sbase + cl, sg1 = sg0 + 1;
                float g00 = (sg0 <= lg0) ? gacc[mi][ni][0] * expf(a0 - as0) : 0.0f;
                float g01 = (sg1 <= lg0) ? gacc[mi][ni][1] * expf(a0 - as1) : 0.0f;
                float g10 = (sg0 <= lg1) ? gacc[mi][ni][2] * expf(a1 - as0) : 0.0f;
                float g11 = (sg1 <= lg1) ? gacc[mi][ni][3] * expf(a1 - as1) : 0.0f;
                Gsm[(r0    ) * YROW + cl    ] = __float2half_rn(g00);
                Gsm[(r0    ) * YROW + cl + 1] = __float2half_rn(g01);
                Gsm[(r0 + 8) * YROW + cl    ] = __float2half_rn(g10);
                Gsm[(r0 + 8) * YROW + cl + 1] = __float2half_rn(g11);
            }
        }
        __syncthreads();

#pragma unroll
        for (int kk = 0; kk < 4; kk++) {
            int kb = kk * 16;
            uint32_t afr[2][4], bh[8][2];
#pragma unroll
            for (int mi = 0; mi < 2; mi++) {
                int mb = wmY + mi * 16 + lr;
                afr[mi][0] = *(const uint32_t*)&Gsm[(mb    ) * YROW + kb + lc * 2];
                afr[mi][1] = *(const uint32_t*)&Gsm[(mb + 8) * YROW + kb + lc * 2];
                afr[mi][2] = *(const uint32_t*)&Gsm[(mb    ) * YROW + kb + 8 + lc * 2];
                afr[mi][3] = *(const uint32_t*)&Gsm[(mb + 8) * YROW + kb + 8 + lc * 2];
            }
#pragma unroll
            for (int ni = 0; ni < 8; ni++) {
                int nb = wnY + ni * 8 + lr;
                bh[ni][0] = *(const uint32_t*)&Xh[nb * YROW + kb + lc * 2];
                bh[ni][1] = *(const uint32_t*)&Xh[nb * YROW + kb + 8 + lc * 2];
            }
#pragma unroll
            for (int mi = 0; mi < 2; mi++)
#pragma unroll
                for (int ni = 0; ni < 8; ni++)
                    MMA_F16(acc[mi][ni], afr[mi], bh[ni]);
        }
        __syncthreads();
    }

    float Dh = Dparam[hh];
#pragma unroll
    for (int mi = 0; mi < 2; mi++) {
        int r0 = wmY + mi * 16 + lr;
#pragma unroll
        for (int ni = 0; ni < 8; ni++) {
            int col = wnY + ni * 8 + lc * 2;
            long o0 = (long)(c * CHUNK + l0 + r0) * DIM_INNER + hh * HEADDIM + col;
            long o1 = o0 + 8L * DIM_INNER;
            __half2 v0 = __floats2half2_rn(
                acc[mi][ni][0] + __half2float(g_xsh[o0]) * Dh,
                acc[mi][ni][1] + __half2float(g_xsh[o0 + 1]) * Dh);
            __half2 v1 = __floats2half2_rn(
                acc[mi][ni][2] + __half2float(g_xsh[o1]) * Dh,
                acc[mi][ni][3] + __half2float(g_xsh[o1 + 1]) * Dh);
            *(__half2*)&g_yhalf[o0] = v0;
            *(__half2*)&g_yhalf[o1] = v1;
        }
    }
}

// ---------------- gated RMSNorm (fp16 y/z; writes fp16 for out_proj) -----------
__global__ void __launch_bounds__(256)
norm_kernel(const float* __restrict__ norm_w) {
    int l = blockIdx.x;
    int t = threadIdx.x;
    float vals[16];
    float ss = 0.0f;
#pragma unroll
    for (int r = 0; r < 16; r++) {
        int j = t + r * 256;
        float yv = __half2float(g_yhalf[l * DIM_INNER + j]);
        float zv = __half2float(g_zxh[l * D_IN_PROJ + j]);
        float gv = yv * siluf(zv);
        vals[r] = gv;
        ss += gv * gv;
    }
    __shared__ float red[8];
#pragma unroll
    for (int off = 16; off > 0; off >>= 1)
        ss += __shfl_down_sync(0xffffffffu, ss, off);
    if ((t & 31) == 0) red[t >> 5] = ss;
    __syncthreads();
    float total;
    {
        float v = (t < 8) ? red[t] : 0.0f;
#pragma unroll
        for (int off = 4; off > 0; off >>= 1)
            v += __shfl_down_sync(0xffffffffu, v, off);
        if (t == 0) red[0] = v;
    }
    __syncthreads();
    total = red[0];
    float scale = rsqrtf(total / (float)DIM_INNER + 1e-5f);
#pragma unroll
    for (int r = 0; r < 16; r++) {
        int j = t + r * 256;
        g_yh[l * DIM_INNER + j] = __float2half_rn(vals[r] * scale * norm_w[j]);
    }
}

// ---------------- host launcher ----------------
extern "C" void kernel_launch(void* const* d_in, const int* in_sizes, int n_in,
                              void* d_out, int out_size) {
    const float* x        = (const float*)d_in[0];
    const float* in_w     = (const float*)d_in[1];
    const float* conv_w   = (const float*)d_in[2];
    const float* conv_b   = (const float*)d_in[3];
    const float* dt_bias  = (const float*)d_in[4];
    const float* A_log    = (const float*)d_in[5];
    const float* Dparam   = (const float*)d_in[6];
    const float* norm_w   = (const float*)d_in[7];
    const float* out_w    = (const float*)d_in[8];
    float* out            = (float*)d_out;

    __half* zxh; cudaGetSymbolAddress((void**)&zxh, g_zxh);
    __half* wA;  cudaGetSymbolAddress((void**)&wA,  g_wA);
    __half* wB;  cudaGetSymbolAddress((void**)&wB,  g_wB);
    __half* xh;  cudaGetSymbolAddress((void**)&xh,  g_xh);
    __half* yh;  cudaGetSymbolAddress((void**)&yh,  g_yh);

    cudaFuncSetAttribute(h16_gemm<0>, cudaFuncAttributeMaxDynamicSharedMemorySize, GEMM_SMEM);
    cudaFuncSetAttribute(h16_gemm<1>, cudaFuncAttributeMaxDynamicSharedMemorySize, GEMM_SMEM);
    cudaFuncSetAttribute(y_mma_kernel, cudaFuncAttributeMaxDynamicSharedMemorySize, Y_SMEM_BYTES);

    // 0. convert GEMM operands to fp16
    tohalf_kernel<<<(D_IN_PROJ * DIM / 8 + 255) / 256, 256>>>(in_w, wA, D_IN_PROJ * DIM);
    tohalf_kernel<<<(SEQ * DIM / 8 + 255) / 256, 256>>>(x, xh, SEQ * DIM);
    tohalf_kernel<<<(DIM * DIM_INNER / 8 + 255) / 256, 256>>>(out_w, wB, DIM * DIM_INNER);

    // 1. in_proj (fp16 mma, fp16 output)
    {
        dim3 grid((D_IN_PROJ + TBN - 1) / TBN, SEQ / TBM);
        h16_gemm<1><<<grid, 128, GEMM_SMEM>>>(xh, wA, zxh, SEQ, D_IN_PROJ, DIM);
    }
    // 2. fused dt + cumsum per (chunk, head)
    cumsum_dt_kernel<<<NCHUNK * NHEADS, CHUNK>>>(dt_bias, A_log);
    // 3. conv + silu + split (4 channels/thread)
    conv_kernel<<<(SEQ * CONV_DIM / 4 + 255) / 256, 256>>>(conv_w, conv_b);
    // 4. chunk states (fp16 mma)
    states_kernel<<<NCHUNK * NHEADS, 256>>>();
    // 5. inter-chunk recurrence
    sprev_kernel<<<(NHEADS * HEADDIM * D_STATE + 255) / 256, 256>>>();
    // 6. Y via fp16 mma (2 CTAs/SM)
    {
        dim3 grid(2, NHEADS, NCHUNK);
        y_mma_kernel<<<grid, 256, Y_SMEM_BYTES>>>(Dparam);
    }
    // 7. gated RMSNorm
    norm_kernel<<<SEQ, 256>>>(norm_w);
    // 8. out_proj (fp32 output)
    {
        dim3 grid(DIM / TBN, SEQ / TBM);
        h16_gemm<0><<<grid, 128, GEMM_SMEM>>>(yh, wB, out, SEQ, DIM, DIM_INNER);
    }
}

// round 17
// speedup vs baseline: 1.5389x; 1.0050x over previous
#include <cuda_runtime.h>
#include <cuda_fp16.h>
#include <math.h>
#include <stdint.h>

// ---------------- problem constants ----------------
#define SEQ        2048
#define DIM        2048
#define DIM_INNER  4096
#define D_STATE    64
#define D_CONV     4
#define HEADDIM    128
#define NHEADS     32
#define CHUNK      256
#define NCHUNK     (SEQ / CHUNK)          // 8
#define CONV_DIM   (DIM_INNER + 2 * D_STATE)      // 4224
#define D_IN_PROJ  (2 * DIM_INNER + 2 * D_STATE + NHEADS)  // 8352

// ---------------- scratch (device globals; no allocation allowed) -------------
__device__ __align__(128) __half g_zxh [SEQ * D_IN_PROJ];
__device__ float g_dt   [SEQ * NHEADS];
__device__ __align__(128) __half g_xsh [SEQ * DIM_INNER];
__device__ __align__(128) __half g_xdth[SEQ * DIM_INNER];
__device__ float g_B    [SEQ * D_STATE];
__device__ float g_C    [SEQ * D_STATE];
__device__ float g_Acs  [NCHUNK * NHEADS * CHUNK];
__device__ float g_Alast[NCHUNK * NHEADS];
__device__ float g_states[NCHUNK * NHEADS * HEADDIM * D_STATE];
__device__ float g_sprev [NCHUNK * NHEADS * HEADDIM * D_STATE];
__device__ __align__(128) __half g_yhalf[SEQ * DIM_INNER];
// fp16 GEMM operands
__device__ __align__(128) __half g_wA [D_IN_PROJ * DIM];
__device__ __align__(128) __half g_wB [DIM * DIM_INNER];
__device__ __align__(128) __half g_xh [SEQ * DIM];
__device__ __align__(128) __half g_yh [SEQ * DIM_INNER];

__device__ __forceinline__ float siluf(float v) { return v / (1.0f + expf(-v)); }
__device__ __forceinline__ float softplusf(float v) { return (v > 20.0f) ? v : log1pf(expf(v)); }

// ---------------- fp32 -> fp16 conversion pass ----------------
__global__ void tohalf_kernel(const float* __restrict__ in, __half* __restrict__ out, int n) {
    int i = (blockIdx.x * blockDim.x + threadIdx.x) * 8;
    if (i >= n) return;
    float4 a = *(const float4*)(in + i);
    float4 b = *(const float4*)(in + i + 4);
    __half2 h0 = __floats2half2_rn(a.x, a.y);
    __half2 h1 = __floats2half2_rn(a.z, a.w);
    __half2 h2 = __floats2half2_rn(b.x, b.y);
    __half2 h3 = __floats2half2_rn(b.z, b.w);
    uint4 o;
    o.x = *(uint32_t*)&h0; o.y = *(uint32_t*)&h1;
    o.z = *(uint32_t*)&h2; o.w = *(uint32_t*)&h3;
    *(uint4*)(out + i) = o;
}

#define MMA_F16(acc, a, b) \
    asm volatile( \
        "mma.sync.aligned.m16n8k16.row.col.f32.f16.f16.f32 " \
        "{%0,%1,%2,%3}, {%4,%5,%6,%7}, {%8,%9}, {%0,%1,%2,%3};" \
        : "+f"((acc)[0]), "+f"((acc)[1]), "+f"((acc)[2]), "+f"((acc)[3]) \
        : "r"((a)[0]), "r"((a)[1]), "r"((a)[2]), "r"((a)[3]), \
          "r"((b)[0]), "r"((b)[1]))

#define LDSM_X4(r0, r1, r2, r3, addr) \
    asm volatile("ldmatrix.sync.aligned.m8n8.x4.shared.b16 {%0,%1,%2,%3}, [%4];" \
        : "=r"(r0), "=r"(r1), "=r"(r2), "=r"(r3) : "r"(addr))

// ==== fp16 mma.sync GEMM (R11-proven config, FROZEN); OUT_HALF selects epilogue
#define TBM   128
#define TBN   128
#define TBK   32
#define NSTG  4
#define ROWPH 40
#define STGH  (TBM * ROWPH)
#define GEMM_SMEM (2 * NSTG * STGH * 2)  // 81920 bytes

template <int OUT_HALF>
__global__ void __launch_bounds__(128, 2)
h16_gemm(const __half* __restrict__ A, const __half* __restrict__ B,
         void* __restrict__ Cout, int M, int N, int K) {
    extern __shared__ __half sm[];

    const int tid  = threadIdx.x;
    const int lane = tid & 31;
    const int warp = tid >> 5;
    const int m0   = blockIdx.y * TBM;
    const int n0   = blockIdx.x * TBN;
    const int wm   = (warp >> 1) * 64;
    const int wn   = (warp & 1) * 64;
    const int lr   = lane >> 2;
    const int lc   = lane & 3;
    const int ktiles = K / TBK;

    const int lrow = tid >> 2;
    const int lch  = (tid & 3) * 8;

    const int rowin  = lane & 7;
    const int a_row  = ((lane >> 3) & 1) * 8 + rowin;
    const int a_koff = ((lane >> 4) & 1) * 8;
    const int b_row  = ((lane >> 4) & 1) * 8 + rowin;
    const int b_koff = ((lane >> 3) & 1) * 8;

    uint32_t a_s0, b_s0;
    {
        uint32_t base;
        asm("{ .reg .u64 t; cvta.to.shared.u64 t, %1; cvt.u32.u64 %0, t; }"
            : "=r"(base) : "l"(sm));
        a_s0 = base;
        b_s0 = base + NSTG * STGH * 2;
    }

    auto issue = [&](int kt, int st) {
        const __half* Ag = A + (long)m0 * K + kt * TBK;
        const __half* Bg = B + (long)n0 * K + kt * TBK;
        uint32_t abase = a_s0 + st * STGH * 2;
        uint32_t bbase = b_s0 + st * STGH * 2;
#pragma unroll
        for (int i = 0; i < 4; i++) {
            int r = lrow + i * 32;
            uint32_t doff = r * ROWPH * 2 + lch * 2;
            asm volatile("cp.async.cg.shared.global [%0], [%1], 16;"
                         :: "r"(abase + doff), "l"(Ag + (long)r * K + lch) : "memory");
            int sz = (n0 + r < N) ? 16 : 0;
            asm volatile("cp.async.cg.shared.global [%0], [%1], 16, %2;"
                         :: "r"(bbase + doff), "l"(Bg + (long)r * K + lch), "r"(sz) : "memory");
        }
        asm volatile("cp.async.commit_group;" ::: "memory");
    };

#pragma unroll
    for (int st = 0; st < NSTG - 1; st++) issue(st, st);

    float acc[4][8][4];
#pragma unroll
    for (int i = 0; i < 4; i++)
#pragma unroll
        for (int j = 0; j < 8; j++)
#pragma unroll
            for (int r = 0; r < 4; r++) acc[i][j][r] = 0.0f;

    for (int kt = 0; kt < ktiles; kt++) {
        int s = kt % NSTG;
        asm volatile("cp.async.wait_group %0;" :: "n"(NSTG - 2));
        __syncthreads();
        int nt = kt + NSTG - 1;
        if (nt < ktiles) issue(nt, nt % NSTG);
        else asm volatile("cp.async.commit_group;" ::: "memory");

        uint32_t abase = a_s0 + s * STGH * 2;
        uint32_t bbase = b_s0 + s * STGH * 2;
#pragma unroll
        for (int kk = 0; kk < 2; kk++) {
            int kb = kk * 16;
            uint32_t afr[4][4], bfr[8][2];
#pragma unroll
            for (int mi = 0; mi < 4; mi++) {
                uint32_t addr = abase + (((wm + mi * 16 + a_row) * ROWPH) + kb + a_koff) * 2;
                LDSM_X4(afr[mi][0], afr[mi][1], afr[mi][2], afr[mi][3], addr);
            }
#pragma unroll
            for (int nj = 0; nj < 4; nj++) {
                uint32_t addr = bbase + (((wn + nj * 16 + b_row) * ROWPH) + kb + b_koff) * 2;
                LDSM_X4(bfr[nj * 2][0], bfr[nj * 2][1],
                        bfr[nj * 2 + 1][0], bfr[nj * 2 + 1][1], addr);
            }
#pragma unroll
            for (int mi = 0; mi < 4; mi++)
#pragma unroll
                for (int ni = 0; ni < 8; ni++)
                    MMA_F16(acc[mi][ni], afr[mi], bfr[ni]);
        }
    }

#pragma unroll
    for (int mi = 0; mi < 4; mi++) {
        int r0 = m0 + wm + mi * 16 + lr;
#pragma unroll
        for (int ni = 0; ni < 8; ni++) {
            int ccol = n0 + wn + ni * 8 + lc * 2;
            if (ccol < N) {
                if (OUT_HALF) {
                    __half* C = (__half*)Cout;
                    __half2 v0 = __floats2half2_rn(acc[mi][ni][0], acc[mi][ni][1]);
                    __half2 v1 = __floats2half2_rn(acc[mi][ni][2], acc[mi][ni][3]);
                    *(__half2*)(C + (long)r0 * N + ccol) = v0;
                    *(__half2*)(C + (long)(r0 + 8) * N + ccol) = v1;
                } else {
                    float* C = (float*)Cout;
                    float* p0 = C + (long)r0 * N + ccol;
                    float* p1 = C + (long)(r0 + 8) * N + ccol;
                    p0[0] = acc[mi][ni][0];
                    p0[1] = acc[mi][ni][1];
                    p1[0] = acc[mi][ni][2];
                    p1[1] = acc[mi][ni][3];
                }
            }
        }
    }
}

// ---------------- causal depthwise conv + SiLU + split (4-wide, fp16) ----------
__global__ void conv_kernel(const float* __restrict__ conv_w,
                            const float* __restrict__ conv_b) {
    int idx = (blockIdx.x * blockDim.x + threadIdx.x) * 4;
    if (idx >= SEQ * CONV_DIM) return;
    int l = idx / CONV_DIM, ch = idx % CONV_DIM;

    float4 wv[4];
#pragma unroll
    for (int j = 0; j < 4; j++)
        wv[j] = *(const float4*)&conv_w[(ch + j) * D_CONV];

    float4 acc = *(const float4*)&conv_b[ch];
#pragma unroll
    for (int k = 0; k < D_CONV; k++) {
        int ls = l - (D_CONV - 1) + k;
        if (ls >= 0) {
            const __half2* src = (const __half2*)&g_zxh[ls * D_IN_PROJ + DIM_INNER + ch];
            float2 v01 = __half22float2(src[0]);
            float2 v23 = __half22float2(src[1]);
            acc.x += v01.x * ((const float*)&wv[0])[k];
            acc.y += v01.y * ((const float*)&wv[1])[k];
            acc.z += v23.x * ((const float*)&wv[2])[k];
            acc.w += v23.y * ((const float*)&wv[3])[k];
        }
    }
    acc.x = siluf(acc.x); acc.y = siluf(acc.y);
    acc.z = siluf(acc.z); acc.w = siluf(acc.w);

    if (ch < DIM_INNER) {
        int h = ch >> 7;
        float dtv = g_dt[l * NHEADS + h];
        __half2 h0 = __floats2half2_rn(acc.x, acc.y);
        __half2 h1 = __floats2half2_rn(acc.z, acc.w);
        *(uint32_t*)&g_xsh[l * DIM_INNER + ch]     = *(uint32_t*)&h0;
        *(uint32_t*)&g_xsh[l * DIM_INNER + ch + 2] = *(uint32_t*)&h1;
        __half2 d0 = __floats2half2_rn(acc.x * dtv, acc.y * dtv);
        __half2 d1 = __floats2half2_rn(acc.z * dtv, acc.w * dtv);
        *(uint32_t*)&g_xdth[l * DIM_INNER + ch]     = *(uint32_t*)&d0;
        *(uint32_t*)&g_xdth[l * DIM_INNER + ch + 2] = *(uint32_t*)&d1;
    } else if (ch < DIM_INNER + D_STATE) {
        *(float4*)&g_B[l * D_STATE + (ch - DIM_INNER)] = acc;
    } else {
        *(float4*)&g_C[l * D_STATE + (ch - DIM_INNER - D_STATE)] = acc;
    }
}

// ------- fused dt + per-(chunk,head) inclusive cumsum of dA -------
__global__ void cumsum_dt_kernel(const float* __restrict__ dt_bias,
                                 const float* __restrict__ A_log) {
    int ch = blockIdx.x;
    int c = ch / NHEADS, h = ch % NHEADS;
    int t = threadIdx.x;
    int l = c * CHUNK + t;
    __shared__ float s[CHUNK];
    float v = __half2float(g_zxh[l * D_IN_PROJ + (D_IN_PROJ - NHEADS) + h]) + dt_bias[h];
    float sp = softplusf(v);
    g_dt[l * NHEADS + h] = sp;
    s[t] = -expf(A_log[h]) * sp;
    __syncthreads();
    for (int off = 1; off < CHUNK; off <<= 1) {
        float add = (t >= off) ? s[t - off] : 0.0f;
        __syncthreads();
        s[t] += add;
        __syncthreads();
    }
    g_Acs[ch * CHUNK + t] = s[t];
    if (t == CHUNK - 1) g_Alast[ch] = s[t];
}

// ---------------- chunk states via fp16 mma (hi/lo on weighted product) --------
#define SROW 72
__global__ void __launch_bounds__(256)
states_kernel() {
    __shared__ __half Ah[128 * SROW];
    __shared__ __half Al[128 * SROW];
    __shared__ __half Bs[64 * SROW];
    __shared__ float dec[64];

    int chd = blockIdx.x;
    int c = chd / NHEADS, h = chd % NHEADS;
    int tid  = threadIdx.x;
    int lane = tid & 31;
    int warp = tid >> 5;
    int lr = lane >> 2, lc = lane & 3;
    int wm = (warp >> 1) * 32;
    int wn = (warp & 1) * 32;

    float Alast = g_Alast[chd];

    float acc[2][4][4];
#pragma unroll
    for (int i = 0; i < 2; i++)
#pragma unroll
        for (int j = 0; j < 4; j++)
#pragma unroll
            for (int r = 0; r < 4; r++) acc[i][j][r] = 0.0f;

    for (int kt = 0; kt < 4; kt++) {
        int l0 = kt * 64;
        if (tid < 64) dec[tid] = expf(Alast - g_Acs[chd * CHUNK + l0 + tid]);
        __syncthreads();
        {
            int p = tid & 127, l2 = tid >> 7;
#pragma unroll
            for (int i = 0; i < 32; i++) {
                int l = l2 + i * 2;
                float v = __half2float(g_xdth[(c * CHUNK + l0 + l) * DIM_INNER + h * HEADDIM + p]) * dec[l];
                __half hi = __float2half_rn(v);
                Ah[p * SROW + l] = hi;
                Al[p * SROW + l] = __float2half_rn(v - __half2float(hi));
            }
        }
        {
            int n = tid & 63, l4 = tid >> 6;
#pragma unroll
            for (int i = 0; i < 16; i++) {
                int l = l4 + i * 4;
                Bs[n * SROW + l] = __float2half_rn(g_B[(c * CHUNK + l0 + l) * D_STATE + n]);
            }
        }
        __syncthreads();

#pragma unroll
        for (int kk = 0; kk < 4; kk++) {
            int kb = kk * 16;
            uint32_t ah[2][4], al[2][4], bf[4][2];
#pragma unroll
            for (int mi = 0; mi < 2; mi++) {
                int mb = wm + mi * 16 + lr;
                ah[mi][0] = *(const uint32_t*)&Ah[(mb    ) * SROW + kb + lc * 2];
                ah[mi][1] = *(const uint32_t*)&Ah[(mb + 8) * SROW + kb + lc * 2];
                ah[mi][2] = *(const uint32_t*)&Ah[(mb    ) * SROW + kb + 8 + lc * 2];
                ah[mi][3] = *(const uint32_t*)&Ah[(mb + 8) * SROW + kb + 8 + lc * 2];
                al[mi][0] = *(const uint32_t*)&Al[(mb    ) * SROW + kb + lc * 2];
                al[mi][1] = *(const uint32_t*)&Al[(mb + 8) * SROW + kb + lc * 2];
                al[mi][2] = *(const uint32_t*)&Al[(mb    ) * SROW + kb + 8 + lc * 2];
                al[mi][3] = *(const uint32_t*)&Al[(mb + 8) * SROW + kb + 8 + lc * 2];
            }
#pragma unroll
            for (int ni = 0; ni < 4; ni++) {
                int nb = wn + ni * 8 + lr;
                bf[ni][0] = *(const uint32_t*)&Bs[nb * SROW + kb + lc * 2];
                bf[ni][1] = *(const uint32_t*)&Bs[nb * SROW + kb + 8 + lc * 2];
            }
#pragma unroll
            for (int mi = 0; mi < 2; mi++)
#pragma unroll
                for (int ni = 0; ni < 4; ni++) {
                    MMA_F16(acc[mi][ni], ah[mi], bf[ni]);
                    MMA_F16(acc[mi][ni], al[mi], bf[ni]);
                }
        }
        __syncthreads();
    }

#pragma unroll
    for (int mi = 0; mi < 2; mi++) {
        int p0 = wm + mi * 16 + lr;
#pragma unroll
        for (int ni = 0; ni < 4; ni++) {
            int n = wn + ni * 8 + lc * 2;
            float* s0 = &g_states[chd * (HEADDIM * D_STATE) + p0 * D_STATE + n];
            float* s1 = s0 + 8 * D_STATE;
            s0[0] = acc[mi][ni][0]; s0[1] = acc[mi][ni][1];
            s1[0] = acc[mi][ni][2]; s1[1] = acc[mi][ni][3];
        }
    }
}

// ---------------- inter-chunk recurrence ----------------
__global__ void sprev_kernel() {
    int idx = blockIdx.x * blockDim.x + threadIdx.x;
    if (idx >= NHEADS * HEADDIM * D_STATE) return;
    int h = idx / (HEADDIM * D_STATE);
    int r = idx % (HEADDIM * D_STATE);
    float S = 0.0f;
    for (int c = 0; c < NCHUNK; c++) {
        int ch = c * NHEADS + h;
        g_sprev[ch * (HEADDIM * D_STATE) + r] = S;
        S = expf(g_Alast[ch]) * S + g_states[ch * (HEADDIM * D_STATE) + r];
    }
}

// ================ fused SSD Y kernel (fp16 mma, ldmatrix fragments) ============
#define YROW 72
#define O_CH   0
#define O_BS   (O_CH + 128 * YROW)
#define O_GS   (O_BS + 64 * YROW)
#define O_XH   (O_GS + 128 * YROW)
#define O_SS   (O_XH + 128 * YROW)
#define O_END  (O_SS + 128 * YROW)
#define Y_SMEM_BYTES (O_END * 2 + (128 + 128 + 64) * 4)

__global__ void __launch_bounds__(256, 2)
y_mma_kernel(const float* __restrict__ Dparam) {
    extern __shared__ __half ysm[];
    __half* Ch  = ysm + O_CH;
    __half* Bsm = ysm + O_BS;
    __half* Gsm = ysm + O_GS;
    __half* Xh  = ysm + O_XH;
    __half* Ssm = ysm + O_SS;
    float* acsl  = (float*)(ysm + O_END);
    float* expAl = acsl + 128;
    float* acss  = expAl + 128;

    const int hh = blockIdx.y, c = blockIdx.z;
    const int lh = blockIdx.x;
    const int l0 = lh * 128;
    const int ch = c * NHEADS + hh;
    const int tid  = threadIdx.x;
    const int lane = tid & 31;
    const int warp = tid >> 5;
    const int lr   = lane >> 2;
    const int lc   = lane & 3;
    const int wmY = (warp >> 1) * 32;
    const int wnY = (warp & 1) * 64;
    const int wmG = (warp >> 1) * 32;
    const int wnG = (warp & 1) * 32;

    // ldmatrix lane-dependent offsets (proven in h16_gemm)
    const int rowin  = lane & 7;
    const int a_row  = ((lane >> 3) & 1) * 8 + rowin;
    const int a_koff = ((lane >> 4) & 1) * 8;
    const int b_row  = ((lane >> 4) & 1) * 8 + rowin;
    const int b_koff = ((lane >> 3) & 1) * 8;

    uint32_t sbase;
    asm("{ .reg .u64 t; cvta.to.shared.u64 t, %1; cvt.u32.u64 %0, t; }"
        : "=r"(sbase) : "l"(ysm));
    const uint32_t chS = sbase + O_CH * 2;
    const uint32_t bsS = sbase + O_BS * 2;
    const uint32_t gsS = sbase + O_GS * 2;
    const uint32_t xhS = sbase + O_XH * 2;
    const uint32_t ssS = sbase + O_SS * 2;

    {
        int n = tid & 63, r4 = tid >> 6;
#pragma unroll
        for (int i = 0; i < 32; i++) {
            int l = r4 + i * 4;
            Ch[l * YROW + n]  = __float2half_rn(g_C[(c * CHUNK + l0 + l) * D_STATE + n]);
            Ssm[l * YROW + n] = __float2half_rn(g_sprev[ch * (HEADDIM * D_STATE) + l * D_STATE + n]);
        }
        if (tid < 128) {
            float a = g_Acs[ch * CHUNK + l0 + tid];
            acsl[tid] = a;
            expAl[tid] = expf(a);
        }
    }
    __syncthreads();

    float acc[2][8][4];
#pragma unroll
    for (int i = 0; i < 2; i++)
#pragma unroll
        for (int j = 0; j < 8; j++)
#pragma unroll
            for (int r = 0; r < 4; r++) acc[i][j][r] = 0.0f;

    // ---- Y_off: C @ Sprev^T (K = 64) ----
#pragma unroll
    for (int kk = 0; kk < 4; kk++) {
        int kb = kk * 16;
        uint32_t afr[2][4], bfr[8][2];
#pragma unroll
        for (int mi = 0; mi < 2; mi++) {
            uint32_t addr = chS + (((wmY + mi * 16 + a_row) * YROW) + kb + a_koff) * 2;
            LDSM_X4(afr[mi][0], afr[mi][1], afr[mi][2], afr[mi][3], addr);
        }
#pragma unroll
        for (int nj = 0; nj < 4; nj++) {
            uint32_t addr = ssS + (((wnY + nj * 16 + b_row) * YROW) + kb + b_koff) * 2;
            LDSM_X4(bfr[nj * 2][0], bfr[nj * 2][1],
                    bfr[nj * 2 + 1][0], bfr[nj * 2 + 1][1], addr);
        }
#pragma unroll
        for (int mi = 0; mi < 2; mi++)
#pragma unroll
            for (int ni = 0; ni < 8; ni++)
                MMA_F16(acc[mi][ni], afr[mi], bfr[ni]);
    }
#pragma unroll
    for (int mi = 0; mi < 2; mi++) {
        int r0 = wmY + mi * 16 + lr;
        float e0 = expAl[r0], e1 = expAl[r0 + 8];
#pragma unroll
        for (int ni = 0; ni < 8; ni++) {
            acc[mi][ni][0] *= e0; acc[mi][ni][1] *= e0;
            acc[mi][ni][2] *= e1; acc[mi][ni][3] *= e1;
        }
    }

    // ---- Y_diag: s-tiles of 64 ----
    const int nst = 2 * (lh + 1);
    for (int st = 0; st < nst; st++) {
        {
            int n = tid & 63, s4 = tid >> 6;
#pragma unroll
            for (int i = 0; i < 16; i++) {
                int s = s4 + i * 4;
                Bsm[s * YROW + n] = __float2half_rn(g_B[(c * CHUNK + st * 64 + s) * D_STATE + n]);
            }
            if (tid < 64) acss[tid] = g_Acs[ch * CHUNK + st * 64 + tid];
            int p = tid & 127, s2 = tid >> 7;
#pragma unroll
            for (int i = 0; i < 32; i++) {
                int s = s2 + i * 2;
                Xh[p * YROW + s] = g_xdth[(c * CHUNK + st * 64 + s) * DIM_INNER + hh * HEADDIM + p];
            }
        }
        __syncthreads();

        float gacc[2][4][4];
#pragma unroll
        for (int i = 0; i < 2; i++)
#pragma unroll
            for (int j = 0; j < 4; j++)
#pragma unroll
                for (int r = 0; r < 4; r++) gacc[i][j][r] = 0.0f;
#pragma unroll
        for (int kk = 0; kk < 4; kk++) {
            int kb = kk * 16;
            uint32_t afr[2][4], bfr[4][2];
#pragma unroll
            for (int mi = 0; mi < 2; mi++) {
                uint32_t addr = chS + (((wmG + mi * 16 + a_row) * YROW) + kb + a_koff) * 2;
                LDSM_X4(afr[mi][0], afr[mi][1], afr[mi][2], afr[mi][3], addr);
            }
#pragma unroll
            for (int nj = 0; nj < 2; nj++) {
                uint32_t addr = bsS + (((wnG + nj * 16 + b_row) * YROW) + kb + b_koff) * 2;
                LDSM_X4(bfr[nj * 2][0], bfr[nj * 2][1],
                        bfr[nj * 2 + 1][0], bfr[nj * 2 + 1][1], addr);
            }
#pragma unroll
            for (int mi = 0; mi < 2; mi++)
#pragma unroll
                for (int ni = 0; ni < 4; ni++)
                    MMA_F16(gacc[mi][ni], afr[mi], bfr[ni]);
        }

        const int sbase2 = st * 64;
#pragma unroll
        for (int mi = 0; mi < 2; mi++) {
            int r0 = wmG + mi * 16 + lr;
            float a0 = acsl[r0], a1 = acsl[r0 + 8];
            int lg0 = l0 + r0, lg1 = lg0 + 8;
#pragma unroll
            for (int ni = 0; ni < 4; ni++) {
                int cl = wnG + ni * 8 + lc * 2;
                float as0 = acss[cl], as1 = acss[cl + 1];
                int sg0 = sbase2 + cl, sg1 = sg0 + 1;
                float g00 = (sg0 <= lg0) ? gacc[mi][ni][0] * expf(a0 - as0) : 0.0f;
                float g01 = (sg1 <= lg0) ? gacc[mi][ni][1] * expf(a0 - as1) : 0.0f;
                float g10 = (sg0 <= lg1) ? gacc[mi][ni][2] * expf(a1 - as0) : 0.0f;
                float g11 = (sg1 <= lg1) ? gacc[mi][ni][3] * expf(a1 - as1) : 0.0f;
                Gsm[(r0    ) * YROW + cl    ] = __float2half_rn(g00);
                Gsm[(r0    ) * YROW + cl + 1] = __float2half_rn(g01);
                Gsm[(r0 + 8) * YROW + cl    ] = __float2half_rn(g10);
                Gsm[(r0 + 8) * YROW + cl + 1] = __float2half_rn(g11);
            }
        }
        __syncthreads();

#pragma unroll
        for (int kk = 0; kk < 4; kk++) {
            int kb = kk * 16;
            uint32_t afr[2][4], bh[8][2];
#pragma unroll
            for (int mi = 0; mi < 2; mi++) {
                uint32_t addr = gsS + (((wmY + mi * 16 + a_row) * YROW) + kb + a_koff) * 2;
                LDSM_X4(afr[mi][0], afr[mi][1], afr[mi][2], afr[mi][3], addr);
            }
#pragma unroll
            for (int nj = 0; nj < 4; nj++) {
                uint32_t addr = xhS + (((wnY + nj * 16 + b_row) * YROW) + kb + b_koff) * 2;
                LDSM_X4(bh[nj * 2][0], bh[nj * 2][1],
                        bh[nj * 2 + 1][0], bh[nj * 2 + 1][1], addr);
            }
#pragma unroll
            for (int mi = 0; mi < 2; mi++)
#pragma unroll
                for (int ni = 0; ni < 8; ni++)
                    MMA_F16(acc[mi][ni], afr[mi], bh[ni]);
        }
        __syncthreads();
    }

    float Dh = Dparam[hh];
#pragma unroll
    for (int mi = 0; mi < 2; mi++) {
        int r0 = wmY + mi * 16 + lr;
#pragma unroll
        for (int ni = 0; ni < 8; ni++) {
            int col = wnY + ni * 8 + lc * 2;
            long o0 = (long)(c * CHUNK + l0 + r0) * DIM_INNER + hh * HEADDIM + col;
            long o1 = o0 + 8L * DIM_INNER;
            __half2 v0 = __floats2half2_rn(
                acc[mi][ni][0] + __half2float(g_xsh[o0]) * Dh,
                acc[mi][ni][1] + __half2float(g_xsh[o0 + 1]) * Dh);
            __half2 v1 = __floats2half2_rn(
                acc[mi][ni][2] + __half2float(g_xsh[o1]) * Dh,
                acc[mi][ni][3] + __half2float(g_xsh[o1 + 1]) * Dh);
            *(__half2*)&g_yhalf[o0] = v0;
            *(__half2*)&g_yhalf[o1] = v1;
        }
    }
}

// ---------------- gated RMSNorm (fp16 y/z; writes fp16 for out_proj) -----------
__global__ void __launch_bounds__(256)
norm_kernel(const float* __restrict__ norm_w) {
    int l = blockIdx.x;
    int t = threadIdx.x;
    float vals[16];
    float ss = 0.0f;
#pragma unroll
    for (int r = 0; r < 16; r++) {
        int j = t + r * 256;
        float yv = __half2float(g_yhalf[l * DIM_INNER + j]);
        float zv = __half2float(g_zxh[l * D_IN_PROJ + j]);
        float gv = yv * siluf(zv);
        vals[r] = gv;
        ss += gv * gv;
    }
    __shared__ float red[8];
#pragma unroll
    for (int off = 16; off > 0; off >>= 1)
        ss += __shfl_down_sync(0xffffffffu, ss, off);
    if ((t & 31) == 0) red[t >> 5] = ss;
    __syncthreads();
    float total;
    {
        float v = (t < 8) ? red[t] : 0.0f;
#pragma unroll
        for (int off = 4; off > 0; off >>= 1)
            v += __shfl_down_sync(0xffffffffu, v, off);
        if (t == 0) red[0] = v;
    }
    __syncthreads();
    total = red[0];
    float scale = rsqrtf(total / (float)DIM_INNER + 1e-5f);
#pragma unroll
    for (int r = 0; r < 16; r++) {
        int j = t + r * 256;
        g_yh[l * DIM_INNER + j] = __float2half_rn(vals[r] * scale * norm_w[j]);
    }
}

// ---------------- host launcher ----------------
extern "C" void kernel_launch(void* const* d_in, const int* in_sizes, int n_in,
                              void* d_out, int out_size) {
    const float* x        = (const float*)d_in[0];
    const float* in_w     = (const float*)d_in[1];
    const float* conv_w   = (const float*)d_in[2];
    const float* conv_b   = (const float*)d_in[3];
    const float* dt_bias  = (const float*)d_in[4];
    const float* A_log    = (const float*)d_in[5];
    const float* Dparam   = (const float*)d_in[6];
    const float* norm_w   = (const float*)d_in[7];
    const float* out_w    = (const float*)d_in[8];
    float* out            = (float*)d_out;

    __half* zxh; cudaGetSymbolAddress((void**)&zxh, g_zxh);
    __half* wA;  cudaGetSymbolAddress((void**)&wA,  g_wA);
    __half* wB;  cudaGetSymbolAddress((void**)&wB,  g_wB);
    __half* xh;  cudaGetSymbolAddress((void**)&xh,  g_xh);
    __half* yh;  cudaGetSymbolAddress((void**)&yh,  g_yh);

    cudaFuncSetAttribute(h16_gemm<0>, cudaFuncAttributeMaxDynamicSharedMemorySize, GEMM_SMEM);
    cudaFuncSetAttribute(h16_gemm<1>, cudaFuncAttributeMaxDynamicSharedMemorySize, GEMM_SMEM);
    cudaFuncSetAttribute(y_mma_kernel, cudaFuncAttributeMaxDynamicSharedMemorySize, Y_SMEM_BYTES);

    // 0. convert GEMM operands to fp16
    tohalf_kernel<<<(D_IN_PROJ * DIM / 8 + 255) / 256, 256>>>(in_w, wA, D_IN_PROJ * DIM);
    tohalf_kernel<<<(SEQ * DIM / 8 + 255) / 256, 256>>>(x, xh, SEQ * DIM);
    tohalf_kernel<<<(DIM * DIM_INNER / 8 + 255) / 256, 256>>>(out_w, wB, DIM * DIM_INNER);

    // 1. in_proj (fp16 mma, fp16 output)
    {
        dim3 grid((D_IN_PROJ + TBN - 1) / TBN, SEQ / TBM);
        h16_gemm<1><<<grid, 128, GEMM_SMEM>>>(xh, wA, zxh, SEQ, D_IN_PROJ, DIM);
    }
    // 2. fused dt + cumsum per (chunk, head)
    cumsum_dt_kernel<<<NCHUNK * NHEADS, CHUNK>>>(dt_bias, A_log);
    // 3. conv + silu + split (4 channels/thread)
    conv_kernel<<<(SEQ * CONV_DIM / 4 + 255) / 256, 256>>>(conv_w, conv_b);
    // 4. chunk states (fp16 mma)
    states_kernel<<<NCHUNK * NHEADS, 256>>>();
    // 5. inter-chunk recurrence
    sprev_kernel<<<(NHEADS * HEADDIM * D_STATE + 255) / 256, 256>>>();
    // 6. Y via fp16 mma + ldmatrix (2 CTAs/SM)
    {
        dim3 grid(2, NHEADS, NCHUNK);
        y_mma_kernel<<<grid, 256, Y_SMEM_BYTES>>>(Dparam);
    }
    // 7. gated RMSNorm
    norm_kernel<<<SEQ, 256>>>(norm_w);
    // 8. out_proj (fp32 output)
    {
        dim3 grid(DIM / TBN, SEQ / TBM);
        h16_gemm<0><<<grid, 128, GEMM_SMEM>>>(yh, wB, out, SEQ, DIM, DIM_INNER);
    }
}